// round 3
// baseline (speedup 1.0000x reference)
#include <cuda_runtime.h>

#define NMAX 50000
#define EMAX 500000

// ---- static device scratch (allocation-free contract) ----
__device__ float g_hs[(size_t)NMAX * 256];   // per-layer source projections
__device__ float g_f0[(size_t)NMAX * 256];   // feature ping
__device__ float g_f1[(size_t)NMAX * 256];   // feature pong
__device__ float g_als[NMAX * 4];            // per-node per-head source attn logit
__device__ float g_ald[NMAX * 4];            // per-node per-head dest attn logit
__device__ float g_vdst[256 * 4];            // folded W_dst @ a_dst^T  [K,H]
__device__ int   g_cnt[NMAX + 1];
__device__ int   g_cur[NMAX + 1];
__device__ int   g_rowptr[NMAX + 1];
__device__ int   g_ssrc[EMAX];               // src ids sorted by dst

// ============================================================
// Edge sort: counting sort by dst (hist -> scan -> scatter)
// ============================================================
__global__ void hist_kernel(const int* __restrict__ dst, int E) {
    int e = blockIdx.x * blockDim.x + threadIdx.x;
    if (e < E) atomicAdd(&g_cnt[dst[e]], 1);
}

__global__ void scan_kernel(int n) {
    __shared__ int sh[1024];
    __shared__ int carry_s;
    int tid = threadIdx.x;
    if (tid == 0) carry_s = 0;
    __syncthreads();
    for (int base = 0; base < n; base += 1024) {
        int i = base + tid;
        int v = (i < n) ? g_cnt[i] : 0;
        sh[tid] = v;
        __syncthreads();
        for (int off = 1; off < 1024; off <<= 1) {
            int t = (tid >= off) ? sh[tid - off] : 0;
            __syncthreads();
            sh[tid] += t;
            __syncthreads();
        }
        int excl = sh[tid] - v + carry_s;
        if (i < n) { g_rowptr[i] = excl; g_cur[i] = excl; }
        __syncthreads();
        if (tid == 1023) carry_s += sh[1023];
        __syncthreads();
    }
    if (tid == 0) g_rowptr[n] = carry_s;
}

__global__ void scatter_kernel(const int* __restrict__ src, const int* __restrict__ dst, int E) {
    int e = blockIdx.x * blockDim.x + threadIdx.x;
    if (e < E) {
        int d = dst[e];
        int p = atomicAdd(&g_cur[d], 1);
        g_ssrc[p] = src[e];
    }
}

// ============================================================
// Fold W_dst @ a_dst^T  -> g_vdst[k*H + h]
// ============================================================
__global__ void vdst_kernel(const float* __restrict__ Wd, const float* __restrict__ ad,
                            int K, int H) {
    int k = blockIdx.x * blockDim.x + threadIdx.x;
    if (k >= K) return;
    for (int h = 0; h < H; h++) {
        float s = 0.f;
        const float* wr = &Wd[(size_t)k * H * 64 + h * 64];
        const float* ar = &ad[h * 64];
        #pragma unroll 16
        for (int c = 0; c < 64; c++) s += wr[c] * ar[c];
        g_vdst[k * H + h] = s;
    }
}

// ============================================================
// Tiled SGEMM  C[N,M] = A[N,K] * B[K,M], all row-major.
// BM=128 BN=64 BK=16, 256 threads, 8x4 per thread.
// ============================================================
template <int BM, int BN, int BK, int TM, int TN>
__global__ void sgemm_kernel(const float* __restrict__ A, const float* __restrict__ B,
                             float* __restrict__ C, int N, int K, int M) {
    __shared__ float As[BK][BM];
    __shared__ float Bs[BK][BN];
    const int tid = threadIdx.x;
    const int tx = tid % (BN / TN);   // 16
    const int ty = tid / (BN / TN);   // 16
    const int rowBase = blockIdx.x * BM;
    const int colBase = blockIdx.y * BN;

    float acc[TM][TN];
    #pragma unroll
    for (int i = 0; i < TM; i++)
        #pragma unroll
        for (int j = 0; j < TN; j++) acc[i][j] = 0.f;

    for (int k0 = 0; k0 < K; k0 += BK) {
        // A tile: BM*BK = 2048 floats -> 2 float4 per thread
        #pragma unroll
        for (int q = 0; q < 2; q++) {
            int id = tid * 2 + q;            // 0..511
            int r  = id / (BK / 4);          // 0..127
            int kv = (id % (BK / 4)) * 4;    // 0,4,8,12
            float4 v;
            int grow = rowBase + r;
            if (grow < N)
                v = *reinterpret_cast<const float4*>(&A[(size_t)grow * K + k0 + kv]);
            else
                v = make_float4(0.f, 0.f, 0.f, 0.f);
            As[kv + 0][r] = v.x; As[kv + 1][r] = v.y;
            As[kv + 2][r] = v.z; As[kv + 3][r] = v.w;
        }
        // B tile: BK*BN = 1024 floats -> 1 float4 per thread
        {
            int r  = tid / (BN / 4);         // 0..15
            int cv = (tid % (BN / 4)) * 4;   // 0..60
            float4 v = *reinterpret_cast<const float4*>(&B[(size_t)(k0 + r) * M + colBase + cv]);
            Bs[r][cv + 0] = v.x; Bs[r][cv + 1] = v.y;
            Bs[r][cv + 2] = v.z; Bs[r][cv + 3] = v.w;
        }
        __syncthreads();
        #pragma unroll
        for (int kk = 0; kk < BK; kk++) {
            float ra[TM], rb[TN];
            #pragma unroll
            for (int i = 0; i < TM; i++) ra[i] = As[kk][ty * TM + i];
            #pragma unroll
            for (int j = 0; j < TN; j++) rb[j] = Bs[kk][tx * TN + j];
            #pragma unroll
            for (int i = 0; i < TM; i++)
                #pragma unroll
                for (int j = 0; j < TN; j++) acc[i][j] += ra[i] * rb[j];
        }
        __syncthreads();
    }

    #pragma unroll
    for (int i = 0; i < TM; i++) {
        int grow = rowBase + ty * TM + i;
        if (grow < N) {
            float4 v = make_float4(acc[i][0], acc[i][1], acc[i][2], acc[i][3]);
            *reinterpret_cast<float4*>(&C[(size_t)grow * M + colBase + tx * TN]) = v;
        }
    }
}

// ============================================================
// Per-node attention logits: al_s = sum_c hs*a_src ; al_d = feat @ vdst
// One warp per node.
// ============================================================
template <int H>
__global__ void al_kernel(const float* __restrict__ feat, const float* __restrict__ hs,
                          const float* __restrict__ a_src, int n, int K) {
    const int HC = H * 64;
    const int R  = HC / 32;      // channels per lane
    const int G  = 64 / R;       // lanes per head
    int w = (blockIdx.x * blockDim.x + threadIdx.x) >> 5;
    int lane = threadIdx.x & 31;
    if (w >= n) return;

    // al_s
    float ps = 0.f;
    #pragma unroll
    for (int r = 0; r < R; r++)
        ps += hs[(size_t)w * HC + lane * R + r] * a_src[lane * R + r];
    #pragma unroll
    for (int off = G / 2; off > 0; off >>= 1)
        ps += __shfl_xor_sync(0xffffffffu, ps, off);
    if ((lane & (G - 1)) == 0) g_als[w * H + lane / G] = ps;

    // al_d
    float pd[H];
    #pragma unroll
    for (int h = 0; h < H; h++) pd[h] = 0.f;
    for (int k = lane; k < K; k += 32) {
        float f = feat[(size_t)w * K + k];
        #pragma unroll
        for (int h = 0; h < H; h++) pd[h] += f * g_vdst[k * H + h];
    }
    #pragma unroll
    for (int h = 0; h < H; h++) {
        float v = pd[h];
        #pragma unroll
        for (int off = 16; off > 0; off >>= 1)
            v += __shfl_xor_sync(0xffffffffu, v, off);
        if (lane == 0) g_ald[w * H + h] = v;
    }
}

// ============================================================
// Aggregation: warp per dst node, online softmax over sorted edges,
// rescaled accumulator of hs[src]; no global atomics.
// ============================================================
template <int H>
__global__ void agg_kernel(const float* __restrict__ hs, const float* __restrict__ bias,
                           float* __restrict__ out, int n, int doRelu) {
    const int HC = H * 64;
    const int R  = HC / 32;
    int w = (blockIdx.x * blockDim.x + threadIdx.x) >> 5;
    int lane = threadIdx.x & 31;
    if (w >= n) return;
    int h = (lane * R) / 64;
    float ald_h = g_ald[w * H + h];

    float acc[R];
    #pragma unroll
    for (int r = 0; r < R; r++) acc[r] = 0.f;
    float m = -1e30f, den = 0.f;

    int beg = g_rowptr[w], end = g_rowptr[w + 1];
    for (int e = beg; e < end; e++) {
        int s = g_ssrc[e];
        float ev = g_als[s * H + h] + ald_h;
        ev = ev > 0.f ? ev : 0.2f * ev;              // leaky_relu(0.2)
        float mn = fmaxf(m, ev);
        float sc = __expf(m - mn);
        float wg = __expf(ev - mn);
        den = den * sc + wg;
        const float* hp = &hs[(size_t)s * HC + lane * R];
        if (R == 8) {
            float4 v0 = *reinterpret_cast<const float4*>(hp);
            float4 v1 = *reinterpret_cast<const float4*>(hp + 4);
            acc[0] = acc[0] * sc + wg * v0.x; acc[1] = acc[1] * sc + wg * v0.y;
            acc[2] = acc[2] * sc + wg * v0.z; acc[3] = acc[3] * sc + wg * v0.w;
            acc[4] = acc[4] * sc + wg * v1.x; acc[5] = acc[5] * sc + wg * v1.y;
            acc[6] = acc[6] * sc + wg * v1.z; acc[7] = acc[7] * sc + wg * v1.w;
        } else {
            float2 v = *reinterpret_cast<const float2*>(hp);
            acc[0] = acc[0] * sc + wg * v.x;
            acc[1] = acc[1] * sc + wg * v.y;
        }
        m = mn;
    }
    float invd = (end > beg) ? 1.f / den : 0.f;      // deg==0 -> bias only
    #pragma unroll
    for (int r = 0; r < R; r++) {
        float o = acc[r] * invd + bias[lane * R + r];
        if (doRelu) o = fmaxf(o, 0.f);
        out[(size_t)w * HC + lane * R + r] = o;
    }
}

// ============================================================
// Launch
// ============================================================
extern "C" void kernel_launch(void* const* d_in, const int* in_sizes, int n_in,
                              void* d_out, int out_size) {
    const float* x  = (const float*)d_in[0];
    const int*   ei = (const int*)d_in[1];
    int n = in_sizes[0] / 256;
    int E = in_sizes[1] / 2;
    const int* src = ei;
    const int* dst = ei + E;

    const float *Ws[4], *Wd[4], *as_[4], *ad_[4], *bb[4];
    for (int l = 0; l < 4; l++) {
        Ws[l]  = (const float*)d_in[2 + 5 * l + 0];
        Wd[l]  = (const float*)d_in[2 + 5 * l + 1];
        as_[l] = (const float*)d_in[2 + 5 * l + 2];
        ad_[l] = (const float*)d_in[2 + 5 * l + 3];
        bb[l]  = (const float*)d_in[2 + 5 * l + 4];
    }

    void *p_hs, *p_f0, *p_f1, *p_cnt;
    cudaGetSymbolAddress(&p_hs, g_hs);
    cudaGetSymbolAddress(&p_f0, g_f0);
    cudaGetSymbolAddress(&p_f1, g_f1);
    cudaGetSymbolAddress(&p_cnt, g_cnt);
    float* hs = (float*)p_hs;
    float* f0 = (float*)p_f0;
    float* f1 = (float*)p_f1;

    // ---- sort edges by dst (runs every launch; deterministic work) ----
    cudaMemsetAsync(p_cnt, 0, (size_t)(n + 1) * sizeof(int));
    hist_kernel<<<(E + 255) / 256, 256>>>(dst, E);
    scan_kernel<<<1, 1024>>>(n);
    scatter_kernel<<<(E + 255) / 256, 256>>>(src, dst, E);

    int warpBlocks = (n * 32 + 255) / 256;
    dim3 gGrid4((n + 127) / 128, 4);
    dim3 gGrid1((n + 127) / 128, 1);

    const float* fin = x;
    float* fouts[3] = {f0, f1, f0};
    for (int l = 0; l < 3; l++) {
        vdst_kernel<<<1, 256>>>(Wd[l], ad_[l], 256, 4);
        sgemm_kernel<128, 64, 16, 8, 4><<<gGrid4, 256>>>(fin, Ws[l], hs, n, 256, 256);
        al_kernel<4><<<warpBlocks, 256>>>(fin, hs, as_[l], n, 256);
        agg_kernel<4><<<warpBlocks, 256>>>(hs, bb[l], fouts[l], n, 1);
        fin = fouts[l];
    }
    // layer 4: H=1, out dim 64, no relu, straight to d_out
    vdst_kernel<<<1, 256>>>(Wd[3], ad_[3], 256, 1);
    sgemm_kernel<128, 64, 16, 8, 4><<<gGrid1, 256>>>(fin, Ws[3], hs, n, 256, 64);
    al_kernel<1><<<warpBlocks, 256>>>(fin, hs, as_[3], n, 256);
    agg_kernel<1><<<warpBlocks, 256>>>(hs, bb[3], (float*)d_out, n, 0);
}

// round 4
// speedup vs baseline: 1.1208x; 1.1208x over previous
#include <cuda_runtime.h>

#define NMAX 50000
#define EMAX 500000

// ---- static device scratch (allocation-free contract) ----
__device__ float g_hs[(size_t)NMAX * 256];   // per-layer source projections
__device__ float g_f0[(size_t)NMAX * 256];   // feature ping
__device__ float g_f1[(size_t)NMAX * 256];   // feature pong
__device__ float g_als[NMAX * 4];            // per-node per-head source attn logit
__device__ float g_ald[NMAX * 4];            // per-node per-head dest attn logit
__device__ float g_vdstAll[4 * 1024];        // folded W_dst @ a_dst^T, all layers
__device__ int   g_cnt[NMAX + 1];
__device__ int   g_cur[NMAX + 1];
__device__ int   g_rowptr[NMAX + 1];
__device__ int   g_bsum[64];
__device__ int   g_ssrc[EMAX];               // src ids sorted by dst

// ============================================================
// Edge sort: counting sort by dst (hist -> 3-phase scan -> scatter)
// ============================================================
__global__ void hist_kernel(const int* __restrict__ dst, int E) {
    int e = blockIdx.x * blockDim.x + threadIdx.x;
    if (e < E) atomicAdd(&g_cnt[dst[e]], 1);
}

__global__ void scanA_kernel(int n) {
    __shared__ int sh[1024];
    int tid = threadIdx.x;
    int i = blockIdx.x * 1024 + tid;
    int v = (i < n) ? g_cnt[i] : 0;
    sh[tid] = v;
    __syncthreads();
    #pragma unroll
    for (int off = 1; off < 1024; off <<= 1) {
        int t = (tid >= off) ? sh[tid - off] : 0;
        __syncthreads();
        sh[tid] += t;
        __syncthreads();
    }
    if (i < n) g_rowptr[i] = sh[tid] - v;   // exclusive within block
    if (tid == 1023) g_bsum[blockIdx.x] = sh[1023];
}

__global__ void scanB_kernel(int nb) {
    __shared__ int sh[64];
    int tid = threadIdx.x;
    int v = (tid < nb) ? g_bsum[tid] : 0;
    sh[tid] = v;
    __syncthreads();
    #pragma unroll
    for (int off = 1; off < 64; off <<= 1) {
        int t = (tid >= off) ? sh[tid - off] : 0;
        __syncthreads();
        sh[tid] += t;
        __syncthreads();
    }
    if (tid < nb) g_bsum[tid] = sh[tid] - v;  // exclusive block offsets
}

__global__ void scanC_kernel(int n, int E) {
    int i = blockIdx.x * 1024 + threadIdx.x;
    if (i < n) {
        int r = g_rowptr[i] + g_bsum[blockIdx.x];
        g_rowptr[i] = r;
        g_cur[i] = r;
    }
    if (i == n) g_rowptr[n] = E;
}

__global__ void scatter_kernel(const int* __restrict__ src, const int* __restrict__ dst, int E) {
    int e = blockIdx.x * blockDim.x + threadIdx.x;
    if (e < E) {
        int d = dst[e];
        int p = atomicAdd(&g_cur[d], 1);
        g_ssrc[p] = src[e];
    }
}

// ============================================================
// Fold W_dst @ a_dst^T for ALL layers: warp per (layer,k,h).
// Layers 0-2: H=4 (1024 warps each); layer 3: H=1 (256 warps).
// ============================================================
__global__ void vdst_all_kernel(const float* __restrict__ W0, const float* __restrict__ W1,
                                const float* __restrict__ W2, const float* __restrict__ W3,
                                const float* __restrict__ a0, const float* __restrict__ a1,
                                const float* __restrict__ a2, const float* __restrict__ a3) {
    int w = (blockIdx.x * blockDim.x + threadIdx.x) >> 5;
    int lane = threadIdx.x & 31;
    if (w >= 3328) return;
    const float *Wd, *ad;
    int k, h, H, l;
    if (w < 3072) {
        l = w >> 10;
        int rem = w & 1023;
        k = rem >> 2; h = rem & 3; H = 4;
        if (l == 0) { Wd = W0; ad = a0; }
        else if (l == 1) { Wd = W1; ad = a1; }
        else { Wd = W2; ad = a2; }
    } else {
        l = 3; k = w - 3072; h = 0; H = 1;
        Wd = W3; ad = a3;
    }
    int HC = H * 64;
    const float* wr = Wd + (size_t)k * HC + h * 64;
    const float* ar = ad + h * 64;
    float s = wr[lane] * ar[lane] + wr[lane + 32] * ar[lane + 32];
    #pragma unroll
    for (int off = 16; off > 0; off >>= 1)
        s += __shfl_xor_sync(0xffffffffu, s, off);
    if (lane == 0) g_vdstAll[l * 1024 + k * H + h] = s;
}

// ============================================================
// SGEMM  C[N,M] = A[N,K] * B[K,M], row-major.
// BM=128, BK=8, 256 threads, double-buffered, TM=8, TN=BN/16.
// ============================================================
template <int BN>
__global__ void sgemm2_kernel(const float* __restrict__ A, const float* __restrict__ B,
                              float* __restrict__ C, int N, int K, int M) {
    constexpr int BM = 128, BK = 8, TM = 8, TN = BN / 16;
    constexpr int BV = (BK * BN) / 256;   // B floats per thread per stage (4 or 2)
    __shared__ float As[2][BK][BM];
    __shared__ float Bs[2][BK][BN];
    const int tid = threadIdx.x;
    const int tx = tid & 15;
    const int ty = tid >> 4;
    const int rowBase = blockIdx.x * BM;
    const int colBase = blockIdx.y * BN;

    const int aRow = tid >> 1;
    const int aK   = (tid & 1) << 2;
    const bool aOk = (rowBase + aRow) < N;
    const float* Ag = A + (size_t)(rowBase + aRow) * K + aK;

    const int bR = tid >> 5;
    const int bC = (tid & 31) * BV;
    const float* Bg = B + (size_t)bR * M + colBase + bC;

    float acc[TM][TN] = {};

    // preload stage 0
    {
        float4 av = aOk ? *reinterpret_cast<const float4*>(Ag) : make_float4(0.f, 0.f, 0.f, 0.f);
        As[0][aK + 0][aRow] = av.x; As[0][aK + 1][aRow] = av.y;
        As[0][aK + 2][aRow] = av.z; As[0][aK + 3][aRow] = av.w;
        if constexpr (BV == 4) {
            *reinterpret_cast<float4*>(&Bs[0][bR][bC]) = *reinterpret_cast<const float4*>(Bg);
        } else {
            *reinterpret_cast<float2*>(&Bs[0][bR][bC]) = *reinterpret_cast<const float2*>(Bg);
        }
    }
    __syncthreads();

    const int nIter = K / BK;
    int buf = 0;
    for (int it = 0; it < nIter; it++) {
        float4 av;
        float4 bv4;
        float2 bv2;
        const bool notLast = (it + 1 < nIter);
        if (notLast) {
            av = aOk ? *reinterpret_cast<const float4*>(Ag + (it + 1) * BK)
                     : make_float4(0.f, 0.f, 0.f, 0.f);
            if constexpr (BV == 4)
                bv4 = *reinterpret_cast<const float4*>(Bg + (size_t)(it + 1) * BK * M);
            else
                bv2 = *reinterpret_cast<const float2*>(Bg + (size_t)(it + 1) * BK * M);
        }

        #pragma unroll
        for (int kk = 0; kk < BK; kk++) {
            float a[TM], b[TN];
            #pragma unroll
            for (int i = 0; i < TM; i += 4) {
                float4 t = *reinterpret_cast<const float4*>(&As[buf][kk][ty * TM + i]);
                a[i] = t.x; a[i + 1] = t.y; a[i + 2] = t.z; a[i + 3] = t.w;
            }
            #pragma unroll
            for (int j = 0; j < TN; j += 4) {
                float4 t = *reinterpret_cast<const float4*>(&Bs[buf][kk][tx * TN + j]);
                b[j] = t.x; b[j + 1] = t.y; b[j + 2] = t.z; b[j + 3] = t.w;
            }
            #pragma unroll
            for (int i = 0; i < TM; i++)
                #pragma unroll
                for (int j = 0; j < TN; j++)
                    acc[i][j] += a[i] * b[j];
        }

        if (notLast) {
            int nb = buf ^ 1;
            As[nb][aK + 0][aRow] = av.x; As[nb][aK + 1][aRow] = av.y;
            As[nb][aK + 2][aRow] = av.z; As[nb][aK + 3][aRow] = av.w;
            if constexpr (BV == 4)
                *reinterpret_cast<float4*>(&Bs[nb][bR][bC]) = bv4;
            else
                *reinterpret_cast<float2*>(&Bs[nb][bR][bC]) = bv2;
        }
        __syncthreads();
        buf ^= 1;
    }

    #pragma unroll
    for (int i = 0; i < TM; i++) {
        int grow = rowBase + ty * TM + i;
        if (grow < N) {
            #pragma unroll
            for (int j = 0; j < TN; j += 4) {
                float4 v = make_float4(acc[i][j], acc[i][j + 1], acc[i][j + 2], acc[i][j + 3]);
                *reinterpret_cast<float4*>(&C[(size_t)grow * M + colBase + tx * TN + j]) = v;
            }
        }
    }
}

// ============================================================
// Per-node attention logits: al_s = sum_c hs*a_src ; al_d = feat @ vdst
// One warp per node.
// ============================================================
template <int H>
__global__ void al_kernel(const float* __restrict__ feat, const float* __restrict__ hs,
                          const float* __restrict__ a_src, const float* __restrict__ vd,
                          int n, int K) {
    const int HC = H * 64;
    const int R  = HC / 32;      // channels per lane
    const int G  = 64 / R;       // lanes per head
    int w = (blockIdx.x * blockDim.x + threadIdx.x) >> 5;
    int lane = threadIdx.x & 31;
    if (w >= n) return;

    // al_s
    float ps = 0.f;
    #pragma unroll
    for (int r = 0; r < R; r++)
        ps += hs[(size_t)w * HC + lane * R + r] * a_src[lane * R + r];
    #pragma unroll
    for (int off = G / 2; off > 0; off >>= 1)
        ps += __shfl_xor_sync(0xffffffffu, ps, off);
    if ((lane & (G - 1)) == 0) g_als[w * H + lane / G] = ps;

    // al_d
    float pd[H];
    #pragma unroll
    for (int h = 0; h < H; h++) pd[h] = 0.f;
    for (int k = lane; k < K; k += 32) {
        float f = feat[(size_t)w * K + k];
        #pragma unroll
        for (int h = 0; h < H; h++) pd[h] += f * vd[k * H + h];
    }
    #pragma unroll
    for (int h = 0; h < H; h++) {
        float v = pd[h];
        #pragma unroll
        for (int off = 16; off > 0; off >>= 1)
            v += __shfl_xor_sync(0xffffffffu, v, off);
        if (lane == 0) g_ald[w * H + h] = v;
    }
}

// ============================================================
// Aggregation: warp per dst node, online softmax over sorted edges.
// ============================================================
template <int H>
__global__ void agg_kernel(const float* __restrict__ hs, const float* __restrict__ bias,
                           float* __restrict__ out, int n, int doRelu) {
    const int HC = H * 64;
    const int R  = HC / 32;
    int w = (blockIdx.x * blockDim.x + threadIdx.x) >> 5;
    int lane = threadIdx.x & 31;
    if (w >= n) return;
    int h = (lane * R) / 64;
    float ald_h = g_ald[w * H + h];

    float acc[R];
    #pragma unroll
    for (int r = 0; r < R; r++) acc[r] = 0.f;
    float m = -1e30f, den = 0.f;

    int beg = g_rowptr[w], end = g_rowptr[w + 1];
    for (int e = beg; e < end; e++) {
        int s = g_ssrc[e];
        float ev = g_als[s * H + h] + ald_h;
        ev = ev > 0.f ? ev : 0.2f * ev;              // leaky_relu(0.2)
        float mn = fmaxf(m, ev);
        float sc = __expf(m - mn);
        float wg = __expf(ev - mn);
        den = den * sc + wg;
        const float* hp = &hs[(size_t)s * HC + lane * R];
        if (R == 8) {
            float4 v0 = *reinterpret_cast<const float4*>(hp);
            float4 v1 = *reinterpret_cast<const float4*>(hp + 4);
            acc[0] = acc[0] * sc + wg * v0.x; acc[1] = acc[1] * sc + wg * v0.y;
            acc[2] = acc[2] * sc + wg * v0.z; acc[3] = acc[3] * sc + wg * v0.w;
            acc[4] = acc[4] * sc + wg * v1.x; acc[5] = acc[5] * sc + wg * v1.y;
            acc[6] = acc[6] * sc + wg * v1.z; acc[7] = acc[7] * sc + wg * v1.w;
        } else {
            float2 v = *reinterpret_cast<const float2*>(hp);
            acc[0] = acc[0] * sc + wg * v.x;
            acc[1] = acc[1] * sc + wg * v.y;
        }
        m = mn;
    }
    float invd = (end > beg) ? 1.f / den : 0.f;      // deg==0 -> bias only
    #pragma unroll
    for (int r = 0; r < R; r++) {
        float o = acc[r] * invd + bias[lane * R + r];
        if (doRelu) o = fmaxf(o, 0.f);
        out[(size_t)w * HC + lane * R + r] = o;
    }
}

// ============================================================
// Launch
// ============================================================
extern "C" void kernel_launch(void* const* d_in, const int* in_sizes, int n_in,
                              void* d_out, int out_size) {
    const float* x  = (const float*)d_in[0];
    const int*   ei = (const int*)d_in[1];
    int n = in_sizes[0] / 256;
    int E = in_sizes[1] / 2;
    const int* src = ei;
    const int* dst = ei + E;

    const float *Ws[4], *Wd[4], *as_[4], *ad_[4], *bb[4];
    for (int l = 0; l < 4; l++) {
        Ws[l]  = (const float*)d_in[2 + 5 * l + 0];
        Wd[l]  = (const float*)d_in[2 + 5 * l + 1];
        as_[l] = (const float*)d_in[2 + 5 * l + 2];
        ad_[l] = (const float*)d_in[2 + 5 * l + 3];
        bb[l]  = (const float*)d_in[2 + 5 * l + 4];
    }

    void *p_hs, *p_f0, *p_f1, *p_cnt, *p_vd;
    cudaGetSymbolAddress(&p_hs, g_hs);
    cudaGetSymbolAddress(&p_f0, g_f0);
    cudaGetSymbolAddress(&p_f1, g_f1);
    cudaGetSymbolAddress(&p_cnt, g_cnt);
    cudaGetSymbolAddress(&p_vd, g_vdstAll);
    float* hs = (float*)p_hs;
    float* f0 = (float*)p_f0;
    float* f1 = (float*)p_f1;
    const float* vd = (const float*)p_vd;

    // ---- sort edges by dst ----
    int nb = (n + 1023) / 1024;
    cudaMemsetAsync(p_cnt, 0, (size_t)(n + 1) * sizeof(int));
    hist_kernel<<<(E + 255) / 256, 256>>>(dst, E);
    scanA_kernel<<<nb, 1024>>>(n);
    scanB_kernel<<<1, 64>>>(nb);
    scanC_kernel<<<nb, 1024>>>(n, E);
    scatter_kernel<<<(E + 255) / 256, 256>>>(src, dst, E);

    // ---- fold all layers' W_dst @ a_dst^T ----
    vdst_all_kernel<<<416, 256>>>(Wd[0], Wd[1], Wd[2], Wd[3],
                                  ad_[0], ad_[1], ad_[2], ad_[3]);

    int warpBlocks = (n * 32 + 255) / 256;
    dim3 gGrid((n + 127) / 128, 2);
    dim3 gGrid4((n + 127) / 128, 1);

    const float* fin = x;
    float* fouts[3] = {f0, f1, f0};
    for (int l = 0; l < 3; l++) {
        sgemm2_kernel<128><<<gGrid, 256>>>(fin, Ws[l], hs, n, 256, 256);
        al_kernel<4><<<warpBlocks, 256>>>(fin, hs, as_[l], vd + l * 1024, n, 256);
        agg_kernel<4><<<warpBlocks, 256>>>(hs, bb[l], fouts[l], n, 1);
        fin = fouts[l];
    }
    // layer 4: H=1, out dim 64, no relu, straight to d_out
    sgemm2_kernel<64><<<gGrid4, 256>>>(fin, Ws[3], hs, n, 256, 64);
    al_kernel<1><<<warpBlocks, 256>>>(fin, hs, as_[3], vd + 3 * 1024, n, 256);
    agg_kernel<1><<<warpBlocks, 256>>>(hs, bb[3], (float*)d_out, n, 0);
}

// round 5
// speedup vs baseline: 1.1221x; 1.0012x over previous
#include <cuda_runtime.h>

#define NMAX 50000
#define EMAX 500000

// ---- static device scratch (allocation-free contract) ----
__device__ float g_hs[(size_t)NMAX * 256];   // per-layer source projections
__device__ float g_f0[(size_t)NMAX * 256];   // feature ping
__device__ float g_f1[(size_t)NMAX * 256];   // feature pong
__device__ float g_als[NMAX * 4];            // per-node per-head source attn logit
__device__ float g_ald[NMAX * 4];            // per-node per-head dest attn logit
__device__ float g_vdstAll[4 * 1024];        // folded W_dst @ a_dst^T, all layers
__device__ int   g_cnt[NMAX + 1];
__device__ int   g_cur[NMAX + 1];
__device__ int   g_rowptr[NMAX + 1];
__device__ int   g_bsum[64];
__device__ int   g_ssrc[EMAX];               // src ids sorted by dst

// ============================================================
// Edge sort: counting sort by dst (hist -> 3-phase scan -> scatter)
// ============================================================
__global__ void hist_kernel(const int* __restrict__ dst, int E) {
    int e = blockIdx.x * blockDim.x + threadIdx.x;
    if (e < E) atomicAdd(&g_cnt[dst[e]], 1);
}

__global__ void scanA_kernel(int n) {
    __shared__ int sh[1024];
    int tid = threadIdx.x;
    int i = blockIdx.x * 1024 + tid;
    int v = (i < n) ? g_cnt[i] : 0;
    sh[tid] = v;
    __syncthreads();
    #pragma unroll
    for (int off = 1; off < 1024; off <<= 1) {
        int t = (tid >= off) ? sh[tid - off] : 0;
        __syncthreads();
        sh[tid] += t;
        __syncthreads();
    }
    if (i < n) g_rowptr[i] = sh[tid] - v;   // exclusive within block
    if (tid == 1023) g_bsum[blockIdx.x] = sh[1023];
}

__global__ void scanB_kernel(int nb) {
    __shared__ int sh[64];
    int tid = threadIdx.x;
    int v = (tid < nb) ? g_bsum[tid] : 0;
    sh[tid] = v;
    __syncthreads();
    #pragma unroll
    for (int off = 1; off < 64; off <<= 1) {
        int t = (tid >= off) ? sh[tid - off] : 0;
        __syncthreads();
        sh[tid] += t;
        __syncthreads();
    }
    if (tid < nb) g_bsum[tid] = sh[tid] - v;  // exclusive block offsets
}

__global__ void scanC_kernel(int n, int E) {
    int i = blockIdx.x * 1024 + threadIdx.x;
    if (i < n) {
        int r = g_rowptr[i] + g_bsum[blockIdx.x];
        g_rowptr[i] = r;
        g_cur[i] = r;
    }
    if (i == n) g_rowptr[n] = E;
}

__global__ void scatter_kernel(const int* __restrict__ src, const int* __restrict__ dst, int E) {
    int e = blockIdx.x * blockDim.x + threadIdx.x;
    if (e < E) {
        int d = dst[e];
        int p = atomicAdd(&g_cur[d], 1);
        g_ssrc[p] = src[e];
    }
}

// ============================================================
// Fold W_dst @ a_dst^T for ALL layers: warp per (layer,k,h).
// Layers 0-2: H=4 (1024 warps each); layer 3: H=1 (256 warps).
// ============================================================
__global__ void vdst_all_kernel(const float* __restrict__ W0, const float* __restrict__ W1,
                                const float* __restrict__ W2, const float* __restrict__ W3,
                                const float* __restrict__ a0, const float* __restrict__ a1,
                                const float* __restrict__ a2, const float* __restrict__ a3) {
    int w = (blockIdx.x * blockDim.x + threadIdx.x) >> 5;
    int lane = threadIdx.x & 31;
    if (w >= 3328) return;
    const float *Wd, *ad;
    int k, h, H, l;
    if (w < 3072) {
        l = w >> 10;
        int rem = w & 1023;
        k = rem >> 2; h = rem & 3; H = 4;
        if (l == 0) { Wd = W0; ad = a0; }
        else if (l == 1) { Wd = W1; ad = a1; }
        else { Wd = W2; ad = a2; }
    } else {
        l = 3; k = w - 3072; h = 0; H = 1;
        Wd = W3; ad = a3;
    }
    int HC = H * 64;
    const float* wr = Wd + (size_t)k * HC + h * 64;
    const float* ar = ad + h * 64;
    float s = wr[lane] * ar[lane] + wr[lane + 32] * ar[lane + 32];
    #pragma unroll
    for (int off = 16; off > 0; off >>= 1)
        s += __shfl_xor_sync(0xffffffffu, s, off);
    if (lane == 0) g_vdstAll[l * 1024 + k * H + h] = s;
}

// ============================================================
// SGEMM  C[N,M] = A[N,K] * B[K,M], row-major.
// BM=128, BK=8, 256 threads, double-buffered, TM=8, TN=BN/16.
// ============================================================
template <int BN>
__global__ void sgemm2_kernel(const float* __restrict__ A, const float* __restrict__ B,
                              float* __restrict__ C, int N, int K, int M) {
    constexpr int BM = 128, BK = 8, TM = 8, TN = BN / 16;
    constexpr int BV = (BK * BN) / 256;   // B floats per thread per stage (4 or 2)
    __shared__ float As[2][BK][BM];
    __shared__ float Bs[2][BK][BN];
    const int tid = threadIdx.x;
    const int tx = tid & 15;
    const int ty = tid >> 4;
    const int rowBase = blockIdx.x * BM;
    const int colBase = blockIdx.y * BN;

    const int aRow = tid >> 1;
    const int aK   = (tid & 1) << 2;
    const bool aOk = (rowBase + aRow) < N;
    const float* Ag = A + (size_t)(rowBase + aRow) * K + aK;

    const int bR = tid >> 5;
    const int bC = (tid & 31) * BV;
    const float* Bg = B + (size_t)bR * M + colBase + bC;

    float acc[TM][TN] = {};

    // preload stage 0
    {
        float4 av = aOk ? *reinterpret_cast<const float4*>(Ag) : make_float4(0.f, 0.f, 0.f, 0.f);
        As[0][aK + 0][aRow] = av.x; As[0][aK + 1][aRow] = av.y;
        As[0][aK + 2][aRow] = av.z; As[0][aK + 3][aRow] = av.w;
        if constexpr (BV == 4) {
            *reinterpret_cast<float4*>(&Bs[0][bR][bC]) = *reinterpret_cast<const float4*>(Bg);
        } else {
            *reinterpret_cast<float2*>(&Bs[0][bR][bC]) = *reinterpret_cast<const float2*>(Bg);
        }
    }
    __syncthreads();

    const int nIter = K / BK;
    int buf = 0;
    for (int it = 0; it < nIter; it++) {
        float4 av;
        float4 bv4;
        float2 bv2;
        const bool notLast = (it + 1 < nIter);
        if (notLast) {
            av = aOk ? *reinterpret_cast<const float4*>(Ag + (it + 1) * BK)
                     : make_float4(0.f, 0.f, 0.f, 0.f);
            if constexpr (BV == 4)
                bv4 = *reinterpret_cast<const float4*>(Bg + (size_t)(it + 1) * BK * M);
            else
                bv2 = *reinterpret_cast<const float2*>(Bg + (size_t)(it + 1) * BK * M);
        }

        #pragma unroll
        for (int kk = 0; kk < BK; kk++) {
            float a[TM], b[TN];
            #pragma unroll
            for (int i = 0; i < TM; i += 4) {
                float4 t = *reinterpret_cast<const float4*>(&As[buf][kk][ty * TM + i]);
                a[i] = t.x; a[i + 1] = t.y; a[i + 2] = t.z; a[i + 3] = t.w;
            }
            #pragma unroll
            for (int j = 0; j < TN; j += 4) {
                float4 t = *reinterpret_cast<const float4*>(&Bs[buf][kk][tx * TN + j]);
                b[j] = t.x; b[j + 1] = t.y; b[j + 2] = t.z; b[j + 3] = t.w;
            }
            #pragma unroll
            for (int i = 0; i < TM; i++)
                #pragma unroll
                for (int j = 0; j < TN; j++)
                    acc[i][j] += a[i] * b[j];
        }

        if (notLast) {
            int nb = buf ^ 1;
            As[nb][aK + 0][aRow] = av.x; As[nb][aK + 1][aRow] = av.y;
            As[nb][aK + 2][aRow] = av.z; As[nb][aK + 3][aRow] = av.w;
            if constexpr (BV == 4)
                *reinterpret_cast<float4*>(&Bs[nb][bR][bC]) = bv4;
            else
                *reinterpret_cast<float2*>(&Bs[nb][bR][bC]) = bv2;
        }
        __syncthreads();
        buf ^= 1;
    }

    #pragma unroll
    for (int i = 0; i < TM; i++) {
        int grow = rowBase + ty * TM + i;
        if (grow < N) {
            #pragma unroll
            for (int j = 0; j < TN; j += 4) {
                float4 v = make_float4(acc[i][j], acc[i][j + 1], acc[i][j + 2], acc[i][j + 3]);
                *reinterpret_cast<float4*>(&C[(size_t)grow * M + colBase + tx * TN + j]) = v;
            }
        }
    }
}

// ============================================================
// Per-node attention logits: al_s = sum_c hs*a_src ; al_d = feat @ vdst
// One warp per node.
// ============================================================
template <int H>
__global__ void al_kernel(const float* __restrict__ feat, const float* __restrict__ hs,
                          const float* __restrict__ a_src, const float* __restrict__ vd,
                          int n, int K) {
    const int HC = H * 64;
    const int R  = HC / 32;      // channels per lane
    const int G  = 64 / R;       // lanes per head
    int w = (blockIdx.x * blockDim.x + threadIdx.x) >> 5;
    int lane = threadIdx.x & 31;
    if (w >= n) return;

    // al_s
    float ps = 0.f;
    #pragma unroll
    for (int r = 0; r < R; r++)
        ps += hs[(size_t)w * HC + lane * R + r] * a_src[lane * R + r];
    #pragma unroll
    for (int off = G / 2; off > 0; off >>= 1)
        ps += __shfl_xor_sync(0xffffffffu, ps, off);
    if ((lane & (G - 1)) == 0) g_als[w * H + lane / G] = ps;

    // al_d
    float pd[H];
    #pragma unroll
    for (int h = 0; h < H; h++) pd[h] = 0.f;
    for (int k = lane; k < K; k += 32) {
        float f = feat[(size_t)w * K + k];
        #pragma unroll
        for (int h = 0; h < H; h++) pd[h] += f * vd[k * H + h];
    }
    #pragma unroll
    for (int h = 0; h < H; h++) {
        float v = pd[h];
        #pragma unroll
        for (int off = 16; off > 0; off >>= 1)
            v += __shfl_xor_sync(0xffffffffu, v, off);
        if (lane == 0) g_ald[w * H + h] = v;
    }
}

// ============================================================
// Aggregation: warp per dst node, online softmax over sorted edges.
// ============================================================
template <int H>
__global__ void agg_kernel(const float* __restrict__ hs, const float* __restrict__ bias,
                           float* __restrict__ out, int n, int doRelu) {
    const int HC = H * 64;
    const int R  = HC / 32;
    int w = (blockIdx.x * blockDim.x + threadIdx.x) >> 5;
    int lane = threadIdx.x & 31;
    if (w >= n) return;
    int h = (lane * R) / 64;
    float ald_h = g_ald[w * H + h];

    float acc[R];
    #pragma unroll
    for (int r = 0; r < R; r++) acc[r] = 0.f;
    float m = -1e30f, den = 0.f;

    int beg = g_rowptr[w], end = g_rowptr[w + 1];
    for (int e = beg; e < end; e++) {
        int s = g_ssrc[e];
        float ev = g_als[s * H + h] + ald_h;
        ev = ev > 0.f ? ev : 0.2f * ev;              // leaky_relu(0.2)
        float mn = fmaxf(m, ev);
        float sc = __expf(m - mn);
        float wg = __expf(ev - mn);
        den = den * sc + wg;
        const float* hp = &hs[(size_t)s * HC + lane * R];
        if (R == 8) {
            float4 v0 = *reinterpret_cast<const float4*>(hp);
            float4 v1 = *reinterpret_cast<const float4*>(hp + 4);
            acc[0] = acc[0] * sc + wg * v0.x; acc[1] = acc[1] * sc + wg * v0.y;
            acc[2] = acc[2] * sc + wg * v0.z; acc[3] = acc[3] * sc + wg * v0.w;
            acc[4] = acc[4] * sc + wg * v1.x; acc[5] = acc[5] * sc + wg * v1.y;
            acc[6] = acc[6] * sc + wg * v1.z; acc[7] = acc[7] * sc + wg * v1.w;
        } else {
            float2 v = *reinterpret_cast<const float2*>(hp);
            acc[0] = acc[0] * sc + wg * v.x;
            acc[1] = acc[1] * sc + wg * v.y;
        }
        m = mn;
    }
    float invd = (end > beg) ? 1.f / den : 0.f;      // deg==0 -> bias only
    #pragma unroll
    for (int r = 0; r < R; r++) {
        float o = acc[r] * invd + bias[lane * R + r];
        if (doRelu) o = fmaxf(o, 0.f);
        out[(size_t)w * HC + lane * R + r] = o;
    }
}

// ============================================================
// Launch
// ============================================================
extern "C" void kernel_launch(void* const* d_in, const int* in_sizes, int n_in,
                              void* d_out, int out_size) {
    const float* x  = (const float*)d_in[0];
    const int*   ei = (const int*)d_in[1];
    int n = in_sizes[0] / 256;
    int E = in_sizes[1] / 2;
    const int* src = ei;
    const int* dst = ei + E;

    const float *Ws[4], *Wd[4], *as_[4], *ad_[4], *bb[4];
    for (int l = 0; l < 4; l++) {
        Ws[l]  = (const float*)d_in[2 + 5 * l + 0];
        Wd[l]  = (const float*)d_in[2 + 5 * l + 1];
        as_[l] = (const float*)d_in[2 + 5 * l + 2];
        ad_[l] = (const float*)d_in[2 + 5 * l + 3];
        bb[l]  = (const float*)d_in[2 + 5 * l + 4];
    }

    void *p_hs, *p_f0, *p_f1, *p_cnt, *p_vd;
    cudaGetSymbolAddress(&p_hs, g_hs);
    cudaGetSymbolAddress(&p_f0, g_f0);
    cudaGetSymbolAddress(&p_f1, g_f1);
    cudaGetSymbolAddress(&p_cnt, g_cnt);
    cudaGetSymbolAddress(&p_vd, g_vdstAll);
    float* hs = (float*)p_hs;
    float* f0 = (float*)p_f0;
    float* f1 = (float*)p_f1;
    const float* vd = (const float*)p_vd;

    // ---- sort edges by dst ----
    int nb = (n + 1023) / 1024;
    cudaMemsetAsync(p_cnt, 0, (size_t)(n + 1) * sizeof(int));
    hist_kernel<<<(E + 255) / 256, 256>>>(dst, E);
    scanA_kernel<<<nb, 1024>>>(n);
    scanB_kernel<<<1, 64>>>(nb);
    scanC_kernel<<<nb, 1024>>>(n, E);
    scatter_kernel<<<(E + 255) / 256, 256>>>(src, dst, E);

    // ---- fold all layers' W_dst @ a_dst^T ----
    vdst_all_kernel<<<416, 256>>>(Wd[0], Wd[1], Wd[2], Wd[3],
                                  ad_[0], ad_[1], ad_[2], ad_[3]);

    int warpBlocks = (n * 32 + 255) / 256;
    dim3 gGrid((n + 127) / 128, 2);
    dim3 gGrid4((n + 127) / 128, 1);

    const float* fin = x;
    float* fouts[3] = {f0, f1, f0};
    for (int l = 0; l < 3; l++) {
        sgemm2_kernel<128><<<gGrid, 256>>>(fin, Ws[l], hs, n, 256, 256);
        al_kernel<4><<<warpBlocks, 256>>>(fin, hs, as_[l], vd + l * 1024, n, 256);
        agg_kernel<4><<<warpBlocks, 256>>>(hs, bb[l], fouts[l], n, 1);
        fin = fouts[l];
    }
    // layer 4: H=1, out dim 64, no relu, straight to d_out
    sgemm2_kernel<64><<<gGrid4, 256>>>(fin, Ws[3], hs, n, 256, 64);
    al_kernel<1><<<warpBlocks, 256>>>(fin, hs, as_[3], vd + 3 * 1024, n, 256);
    agg_kernel<1><<<warpBlocks, 256>>>(hs, bb[3], (float*)d_out, n, 0);
}

// round 6
// speedup vs baseline: 1.1693x; 1.0420x over previous
#include <cuda_runtime.h>

#define NMAX 50000
#define EMAX 500000

// ---- static device scratch (allocation-free contract) ----
__device__ float g_hs[(size_t)NMAX * 256];   // per-layer source projections
__device__ float g_f0[(size_t)NMAX * 256];   // feature ping
__device__ float g_f1[(size_t)NMAX * 256];   // feature pong
__device__ float g_als[NMAX * 4];            // per-node per-head source attn logit
__device__ float g_ald[NMAX * 4];            // per-node per-head dest attn logit
__device__ float g_vdstAll[4 * 1024];        // folded W_dst @ a_dst^T, all layers
__device__ int   g_cnt[NMAX + 1];
__device__ int   g_cur[NMAX + 1];
__device__ int   g_rowptr[NMAX + 1];
__device__ int   g_bsum[64];
__device__ int   g_ssrc[EMAX];               // src ids sorted by dst

// ============================================================
// Edge sort: counting sort by dst (hist -> 3-phase scan -> scatter)
// ============================================================
__global__ void hist_kernel(const int* __restrict__ dst, int E) {
    int e = blockIdx.x * blockDim.x + threadIdx.x;
    if (e < E) atomicAdd(&g_cnt[dst[e]], 1);
}

__global__ void scanA_kernel(int n) {
    __shared__ int sh[1024];
    int tid = threadIdx.x;
    int i = blockIdx.x * 1024 + tid;
    int v = (i < n) ? g_cnt[i] : 0;
    sh[tid] = v;
    __syncthreads();
    #pragma unroll
    for (int off = 1; off < 1024; off <<= 1) {
        int t = (tid >= off) ? sh[tid - off] : 0;
        __syncthreads();
        sh[tid] += t;
        __syncthreads();
    }
    if (i < n) g_rowptr[i] = sh[tid] - v;   // exclusive within block
    if (tid == 1023) g_bsum[blockIdx.x] = sh[1023];
}

__global__ void scanB_kernel(int nb) {
    __shared__ int sh[64];
    int tid = threadIdx.x;
    int v = (tid < nb) ? g_bsum[tid] : 0;
    sh[tid] = v;
    __syncthreads();
    #pragma unroll
    for (int off = 1; off < 64; off <<= 1) {
        int t = (tid >= off) ? sh[tid - off] : 0;
        __syncthreads();
        sh[tid] += t;
        __syncthreads();
    }
    if (tid < nb) g_bsum[tid] = sh[tid] - v;  // exclusive block offsets
}

__global__ void scanC_kernel(int n, int E) {
    int i = blockIdx.x * 1024 + threadIdx.x;
    if (i < n) {
        int r = g_rowptr[i] + g_bsum[blockIdx.x];
        g_rowptr[i] = r;
        g_cur[i] = r;
    }
    if (i == n) g_rowptr[n] = E;
}

__global__ void scatter_kernel(const int* __restrict__ src, const int* __restrict__ dst, int E) {
    int e = blockIdx.x * blockDim.x + threadIdx.x;
    if (e < E) {
        int d = dst[e];
        int p = atomicAdd(&g_cur[d], 1);
        g_ssrc[p] = src[e];
    }
}

// ============================================================
// Fold W_dst @ a_dst^T for ALL layers: warp per (layer,k,h).
// ============================================================
__global__ void vdst_all_kernel(const float* __restrict__ W0, const float* __restrict__ W1,
                                const float* __restrict__ W2, const float* __restrict__ W3,
                                const float* __restrict__ a0, const float* __restrict__ a1,
                                const float* __restrict__ a2, const float* __restrict__ a3) {
    int w = (blockIdx.x * blockDim.x + threadIdx.x) >> 5;
    int lane = threadIdx.x & 31;
    if (w >= 3328) return;
    const float *Wd, *ad;
    int k, h, H, l;
    if (w < 3072) {
        l = w >> 10;
        int rem = w & 1023;
        k = rem >> 2; h = rem & 3; H = 4;
        if (l == 0) { Wd = W0; ad = a0; }
        else if (l == 1) { Wd = W1; ad = a1; }
        else { Wd = W2; ad = a2; }
    } else {
        l = 3; k = w - 3072; h = 0; H = 1;
        Wd = W3; ad = a3;
    }
    int HC = H * 64;
    const float* wr = Wd + (size_t)k * HC + h * 64;
    const float* ar = ad + h * 64;
    float s = wr[lane] * ar[lane] + wr[lane + 32] * ar[lane + 32];
    #pragma unroll
    for (int off = 16; off > 0; off >>= 1)
        s += __shfl_xor_sync(0xffffffffu, s, off);
    if (lane == 0) g_vdstAll[l * 1024 + k * H + h] = s;
}

// ============================================================
// Tensor-core GEMM via split-TF32 (3xTF32): fp32-grade accuracy on HMMA pipe.
// C[N,M] = A[N,256] * B[256,M].  BM=128, BN=64, BK=16. 256 threads, 8 warps,
// warp tile 32x32 (warps 4xM x 2xN), mma.m16n8k8.tf32.
// ============================================================
__device__ __forceinline__ unsigned f2tf(float x) {
    unsigned r;
    asm("cvt.rna.tf32.f32 %0, %1;" : "=r"(r) : "f"(x));
    return r;
}

__device__ __forceinline__ void mma8(float* c, const unsigned* a, const unsigned* b) {
    asm volatile(
        "mma.sync.aligned.m16n8k8.row.col.f32.tf32.tf32.f32 "
        "{%0,%1,%2,%3}, {%4,%5,%6,%7}, {%8,%9}, {%0,%1,%2,%3};\n"
        : "+f"(c[0]), "+f"(c[1]), "+f"(c[2]), "+f"(c[3])
        : "r"(a[0]), "r"(a[1]), "r"(a[2]), "r"(a[3]), "r"(b[0]), "r"(b[1]));
}

#define AS 20   // A smem row stride (banks: 8 rowgroups x 4 cols -> 32 distinct)
#define BS 72   // B smem row stride (banks: 8k x 8n -> 32 distinct)

__global__ void gemm_tc_kernel(const float* __restrict__ A, const float* __restrict__ B,
                               float* __restrict__ C, int N, int M) {
    __shared__ float Ah[128][AS];
    __shared__ float Alo[128][AS];
    __shared__ float Bh[16][BS];
    __shared__ float Blo[16][BS];
    const int tid = threadIdx.x;
    const int lane = tid & 31;
    const int wid = tid >> 5;
    const int warpM = wid & 3;
    const int warpN = wid >> 2;
    const int g  = lane >> 2;
    const int tg = lane & 3;
    const int rowBase = blockIdx.x * 128;
    const int colBase = blockIdx.y * 64;

    float c[2][4][4] = {};

    // B global: 16x64 tile, one float4 per thread
    const int bkr = tid >> 4;            // 0..15
    const int bnc = (tid & 15) << 2;     // 0..60

    for (int kt = 0; kt < 16; kt++) {
        // ---- load + split-convert A tile (128x16) ----
        #pragma unroll
        for (int q = 0; q < 2; q++) {
            int id = tid * 2 + q;
            int r  = id >> 2;
            int kc = (id & 3) << 2;
            float4 v = make_float4(0.f, 0.f, 0.f, 0.f);
            if (rowBase + r < N)
                v = *reinterpret_cast<const float4*>(&A[(size_t)(rowBase + r) * 256 + kt * 16 + kc]);
            float xs[4] = {v.x, v.y, v.z, v.w};
            #pragma unroll
            for (int i = 0; i < 4; i++) {
                float hi = __uint_as_float(f2tf(xs[i]));
                Ah[r][kc + i]  = hi;
                Alo[r][kc + i] = __uint_as_float(f2tf(xs[i] - hi));
            }
        }
        // ---- load + split-convert B tile (16x64) ----
        {
            float4 v = *reinterpret_cast<const float4*>(&B[(size_t)(kt * 16 + bkr) * M + colBase + bnc]);
            float xs[4] = {v.x, v.y, v.z, v.w};
            #pragma unroll
            for (int i = 0; i < 4; i++) {
                float hi = __uint_as_float(f2tf(xs[i]));
                Bh[bkr][bnc + i]  = hi;
                Blo[bkr][bnc + i] = __uint_as_float(f2tf(xs[i] - hi));
            }
        }
        __syncthreads();

        #pragma unroll
        for (int ks = 0; ks < 2; ks++) {
            const int k0 = ks * 8;
            unsigned ah[2][4], al[2][4], bh[4][2], bl[4][2];
            #pragma unroll
            for (int mt = 0; mt < 2; mt++) {
                int r = warpM * 32 + mt * 16 + g;
                ah[mt][0] = __float_as_uint(Ah[r][k0 + tg]);
                ah[mt][1] = __float_as_uint(Ah[r + 8][k0 + tg]);
                ah[mt][2] = __float_as_uint(Ah[r][k0 + tg + 4]);
                ah[mt][3] = __float_as_uint(Ah[r + 8][k0 + tg + 4]);
                al[mt][0] = __float_as_uint(Alo[r][k0 + tg]);
                al[mt][1] = __float_as_uint(Alo[r + 8][k0 + tg]);
                al[mt][2] = __float_as_uint(Alo[r][k0 + tg + 4]);
                al[mt][3] = __float_as_uint(Alo[r + 8][k0 + tg + 4]);
            }
            #pragma unroll
            for (int nt = 0; nt < 4; nt++) {
                int col = warpN * 32 + nt * 8 + g;
                bh[nt][0] = __float_as_uint(Bh[k0 + tg][col]);
                bh[nt][1] = __float_as_uint(Bh[k0 + tg + 4][col]);
                bl[nt][0] = __float_as_uint(Blo[k0 + tg][col]);
                bl[nt][1] = __float_as_uint(Blo[k0 + tg + 4][col]);
            }
            #pragma unroll
            for (int mt = 0; mt < 2; mt++)
                #pragma unroll
                for (int nt = 0; nt < 4; nt++) {
                    mma8(c[mt][nt], ah[mt], bh[nt]);
                    mma8(c[mt][nt], ah[mt], bl[nt]);
                    mma8(c[mt][nt], al[mt], bh[nt]);
                }
        }
        __syncthreads();
    }

    #pragma unroll
    for (int mt = 0; mt < 2; mt++) {
        int r0 = rowBase + warpM * 32 + mt * 16 + g;
        #pragma unroll
        for (int nt = 0; nt < 4; nt++) {
            int col = colBase + warpN * 32 + nt * 8 + tg * 2;
            if (r0 < N)
                *reinterpret_cast<float2*>(&C[(size_t)r0 * M + col]) = make_float2(c[mt][nt][0], c[mt][nt][1]);
            if (r0 + 8 < N)
                *reinterpret_cast<float2*>(&C[(size_t)(r0 + 8) * M + col]) = make_float2(c[mt][nt][2], c[mt][nt][3]);
        }
    }
}

// ============================================================
// Per-node attention logits: al_s = sum_c hs*a_src ; al_d = feat @ vdst
// ============================================================
template <int H>
__global__ void al_kernel(const float* __restrict__ feat, const float* __restrict__ hs,
                          const float* __restrict__ a_src, const float* __restrict__ vd,
                          int n, int K) {
    const int HC = H * 64;
    const int R  = HC / 32;
    const int G  = 64 / R;
    int w = (blockIdx.x * blockDim.x + threadIdx.x) >> 5;
    int lane = threadIdx.x & 31;
    if (w >= n) return;

    float ps = 0.f;
    #pragma unroll
    for (int r = 0; r < R; r++)
        ps += hs[(size_t)w * HC + lane * R + r] * a_src[lane * R + r];
    #pragma unroll
    for (int off = G / 2; off > 0; off >>= 1)
        ps += __shfl_xor_sync(0xffffffffu, ps, off);
    if ((lane & (G - 1)) == 0) g_als[w * H + lane / G] = ps;

    float pd[H];
    #pragma unroll
    for (int h = 0; h < H; h++) pd[h] = 0.f;
    for (int k = lane; k < K; k += 32) {
        float f = feat[(size_t)w * K + k];
        #pragma unroll
        for (int h = 0; h < H; h++) pd[h] += f * vd[k * H + h];
    }
    #pragma unroll
    for (int h = 0; h < H; h++) {
        float v = pd[h];
        #pragma unroll
        for (int off = 16; off > 0; off >>= 1)
            v += __shfl_xor_sync(0xffffffffu, v, off);
        if (lane == 0) g_ald[w * H + h] = v;
    }
}

// ============================================================
// Aggregation: warp per dst node, online softmax over sorted edges.
// ============================================================
template <int H>
__global__ void agg_kernel(const float* __restrict__ hs, const float* __restrict__ bias,
                           float* __restrict__ out, int n, int doRelu) {
    const int HC = H * 64;
    const int R  = HC / 32;
    int w = (blockIdx.x * blockDim.x + threadIdx.x) >> 5;
    int lane = threadIdx.x & 31;
    if (w >= n) return;
    int h = (lane * R) / 64;
    float ald_h = g_ald[w * H + h];

    float acc[R];
    #pragma unroll
    for (int r = 0; r < R; r++) acc[r] = 0.f;
    float m = -1e30f, den = 0.f;

    int beg = g_rowptr[w], end = g_rowptr[w + 1];
    for (int e = beg; e < end; e++) {
        int s = g_ssrc[e];
        float ev = g_als[s * H + h] + ald_h;
        ev = ev > 0.f ? ev : 0.2f * ev;
        float mn = fmaxf(m, ev);
        float sc = __expf(m - mn);
        float wg = __expf(ev - mn);
        den = den * sc + wg;
        const float* hp = &hs[(size_t)s * HC + lane * R];
        if (R == 8) {
            float4 v0 = *reinterpret_cast<const float4*>(hp);
            float4 v1 = *reinterpret_cast<const float4*>(hp + 4);
            acc[0] = acc[0] * sc + wg * v0.x; acc[1] = acc[1] * sc + wg * v0.y;
            acc[2] = acc[2] * sc + wg * v0.z; acc[3] = acc[3] * sc + wg * v0.w;
            acc[4] = acc[4] * sc + wg * v1.x; acc[5] = acc[5] * sc + wg * v1.y;
            acc[6] = acc[6] * sc + wg * v1.z; acc[7] = acc[7] * sc + wg * v1.w;
        } else {
            float2 v = *reinterpret_cast<const float2*>(hp);
            acc[0] = acc[0] * sc + wg * v.x;
            acc[1] = acc[1] * sc + wg * v.y;
        }
        m = mn;
    }
    float invd = (end > beg) ? 1.f / den : 0.f;
    #pragma unroll
    for (int r = 0; r < R; r++) {
        float o = acc[r] * invd + bias[lane * R + r];
        if (doRelu) o = fmaxf(o, 0.f);
        out[(size_t)w * HC + lane * R + r] = o;
    }
}

// ============================================================
// Launch
// ============================================================
extern "C" void kernel_launch(void* const* d_in, const int* in_sizes, int n_in,
                              void* d_out, int out_size) {
    const float* x  = (const float*)d_in[0];
    const int*   ei = (const int*)d_in[1];
    int n = in_sizes[0] / 256;
    int E = in_sizes[1] / 2;
    const int* src = ei;
    const int* dst = ei + E;

    const float *Ws[4], *Wd[4], *as_[4], *ad_[4], *bb[4];
    for (int l = 0; l < 4; l++) {
        Ws[l]  = (const float*)d_in[2 + 5 * l + 0];
        Wd[l]  = (const float*)d_in[2 + 5 * l + 1];
        as_[l] = (const float*)d_in[2 + 5 * l + 2];
        ad_[l] = (const float*)d_in[2 + 5 * l + 3];
        bb[l]  = (const float*)d_in[2 + 5 * l + 4];
    }

    void *p_hs, *p_f0, *p_f1, *p_cnt, *p_vd;
    cudaGetSymbolAddress(&p_hs, g_hs);
    cudaGetSymbolAddress(&p_f0, g_f0);
    cudaGetSymbolAddress(&p_f1, g_f1);
    cudaGetSymbolAddress(&p_cnt, g_cnt);
    cudaGetSymbolAddress(&p_vd, g_vdstAll);
    float* hs = (float*)p_hs;
    float* f0 = (float*)p_f0;
    float* f1 = (float*)p_f1;
    const float* vd = (const float*)p_vd;

    // ---- sort edges by dst ----
    int nb = (n + 1023) / 1024;
    cudaMemsetAsync(p_cnt, 0, (size_t)(n + 1) * sizeof(int));
    hist_kernel<<<(E + 255) / 256, 256>>>(dst, E);
    scanA_kernel<<<nb, 1024>>>(n);
    scanB_kernel<<<1, 64>>>(nb);
    scanC_kernel<<<nb, 1024>>>(n, E);
    scatter_kernel<<<(E + 255) / 256, 256>>>(src, dst, E);

    // ---- fold all layers' W_dst @ a_dst^T ----
    vdst_all_kernel<<<416, 256>>>(Wd[0], Wd[1], Wd[2], Wd[3],
                                  ad_[0], ad_[1], ad_[2], ad_[3]);

    int warpBlocks = (n * 32 + 255) / 256;
    dim3 gGrid((n + 127) / 128, 4);    // M=256 -> 4 col-blocks of 64
    dim3 gGrid4((n + 127) / 128, 1);   // M=64

    const float* fin = x;
    float* fouts[3] = {f0, f1, f0};
    for (int l = 0; l < 3; l++) {
        gemm_tc_kernel<<<gGrid, 256>>>(fin, Ws[l], hs, n, 256);
        al_kernel<4><<<warpBlocks, 256>>>(fin, hs, as_[l], vd + l * 1024, n, 256);
        agg_kernel<4><<<warpBlocks, 256>>>(hs, bb[l], fouts[l], n, 1);
        fin = fouts[l];
    }
    gemm_tc_kernel<<<gGrid4, 256>>>(fin, Ws[3], hs, n, 64);
    al_kernel<1><<<warpBlocks, 256>>>(fin, hs, as_[3], vd + 3 * 1024, n, 256);
    agg_kernel<1><<<warpBlocks, 256>>>(hs, bb[3], (float*)d_out, n, 0);
}

// round 7
// speedup vs baseline: 1.5926x; 1.3620x over previous
#include <cuda_runtime.h>
#include <cuda_bf16.h>

#define NMAX 50000
#define EMAX 500000

// ---- static device scratch (allocation-free contract) ----
__device__ float g_hs[(size_t)NMAX * 256];   // per-layer source projections
__device__ float g_f0[(size_t)NMAX * 256];   // feature ping
__device__ float g_f1[(size_t)NMAX * 256];   // feature pong
__device__ float g_als[NMAX * 4];            // per-node per-head source attn logit
__device__ float g_ald[NMAX * 4];            // per-node per-head dest attn logit
__device__ float g_attnAll[4 * 2048];        // folded [Ws@a_src^T | Wd@a_dst^T], [l][c][k]
__device__ int   g_cnt[NMAX + 1];
__device__ int   g_cur[NMAX + 1];
__device__ int   g_rowptr[NMAX + 1];
__device__ int   g_bsum[64];
__device__ int   g_ssrc[EMAX];               // src ids sorted by dst

// ============================================================
// Edge sort: counting sort by dst (hist -> 3-phase scan -> scatter)
// ============================================================
__global__ void hist_kernel(const int* __restrict__ dst, int E) {
    int e = blockIdx.x * blockDim.x + threadIdx.x;
    if (e < E) atomicAdd(&g_cnt[dst[e]], 1);
}

__global__ void scanA_kernel(int n) {
    __shared__ int sh[1024];
    int tid = threadIdx.x;
    int i = blockIdx.x * 1024 + tid;
    int v = (i < n) ? g_cnt[i] : 0;
    sh[tid] = v;
    __syncthreads();
    #pragma unroll
    for (int off = 1; off < 1024; off <<= 1) {
        int t = (tid >= off) ? sh[tid - off] : 0;
        __syncthreads();
        sh[tid] += t;
        __syncthreads();
    }
    if (i < n) g_rowptr[i] = sh[tid] - v;
    if (tid == 1023) g_bsum[blockIdx.x] = sh[1023];
}

__global__ void scanB_kernel(int nb) {
    __shared__ int sh[64];
    int tid = threadIdx.x;
    int v = (tid < nb) ? g_bsum[tid] : 0;
    sh[tid] = v;
    __syncthreads();
    #pragma unroll
    for (int off = 1; off < 64; off <<= 1) {
        int t = (tid >= off) ? sh[tid - off] : 0;
        __syncthreads();
        sh[tid] += t;
        __syncthreads();
    }
    if (tid < nb) g_bsum[tid] = sh[tid] - v;
}

__global__ void scanC_kernel(int n, int E) {
    int i = blockIdx.x * 1024 + threadIdx.x;
    if (i < n) {
        int r = g_rowptr[i] + g_bsum[blockIdx.x];
        g_rowptr[i] = r;
        g_cur[i] = r;
    }
    if (i == n) g_rowptr[n] = E;
}

__global__ void scatter_kernel(const int* __restrict__ src, const int* __restrict__ dst, int E) {
    int e = blockIdx.x * blockDim.x + threadIdx.x;
    if (e < E) {
        int d = dst[e];
        int p = atomicAdd(&g_cur[d], 1);
        g_ssrc[p] = src[e];
    }
}

// ============================================================
// Fold attention vectors for ALL layers into P[l][c][k]:
//   c<4 : Ws_l @ a_src_l^T (head c) ;  c>=4 : Wd_l @ a_dst_l^T (head c-4)
// Warp per (l,c,k). Unused heads -> 0.
// ============================================================
__global__ void attn_fold_kernel(const float* __restrict__ Ws0, const float* __restrict__ Ws1,
                                 const float* __restrict__ Ws2, const float* __restrict__ Ws3,
                                 const float* __restrict__ Wd0, const float* __restrict__ Wd1,
                                 const float* __restrict__ Wd2, const float* __restrict__ Wd3,
                                 const float* __restrict__ s0, const float* __restrict__ s1,
                                 const float* __restrict__ s2, const float* __restrict__ s3,
                                 const float* __restrict__ d0, const float* __restrict__ d1,
                                 const float* __restrict__ d2, const float* __restrict__ d3) {
    int w = blockIdx.x * (blockDim.x >> 5) + (threadIdx.x >> 5);
    int lane = threadIdx.x & 31;
    if (w >= 8192) return;
    int l = w >> 11;
    int rem = w & 2047;
    int c = rem >> 8;
    int k = rem & 255;
    int H = (l == 3) ? 1 : 4;
    int side = c >> 2;
    int h = c & 3;
    float val = 0.f;
    if (h < H) {
        const float* W;
        const float* a;
        if (side == 0) {
            W = (l == 0) ? Ws0 : (l == 1) ? Ws1 : (l == 2) ? Ws2 : Ws3;
            a = (l == 0) ? s0 : (l == 1) ? s1 : (l == 2) ? s2 : s3;
        } else {
            W = (l == 0) ? Wd0 : (l == 1) ? Wd1 : (l == 2) ? Wd2 : Wd3;
            a = (l == 0) ? d0 : (l == 1) ? d1 : (l == 2) ? d2 : d3;
        }
        int HC = H * 64;
        const float* wr = W + (size_t)k * HC + h * 64;
        const float* ar = a + h * 64;
        float sacc = wr[lane] * ar[lane] + wr[lane + 32] * ar[lane + 32];
        #pragma unroll
        for (int off = 16; off > 0; off >>= 1)
            sacc += __shfl_xor_sync(0xffffffffu, sacc, off);
        val = sacc;
    }
    if (lane == 0) g_attnAll[l * 2048 + c * 256 + k] = val;
}

// ============================================================
// Tensor-core GEMM via 3-term bf16 split (full-rate HMMA, k16).
// C[N,M] = A[N,256] * B[256,M]. BM=128, BN=64, BK=16, 256 threads,
// 8 warps (4M x 2N), warp tile 32x32, mma.m16n8k16.bf16.
// ============================================================
__device__ __forceinline__ unsigned pack2(__nv_bfloat16 e, __nv_bfloat16 o) {
    __nv_bfloat162 t = __halves2bfloat162(e, o);
    return *reinterpret_cast<unsigned*>(&t);
}

__device__ __forceinline__ void split4(const float4& v, unsigned& h0, unsigned& h1,
                                       unsigned& l0, unsigned& l1) {
    __nv_bfloat16 a = __float2bfloat16_rn(v.x);
    __nv_bfloat16 b = __float2bfloat16_rn(v.y);
    __nv_bfloat16 c = __float2bfloat16_rn(v.z);
    __nv_bfloat16 d = __float2bfloat16_rn(v.w);
    __nv_bfloat16 ra = __float2bfloat16_rn(v.x - __bfloat162float(a));
    __nv_bfloat16 rb = __float2bfloat16_rn(v.y - __bfloat162float(b));
    __nv_bfloat16 rc = __float2bfloat16_rn(v.z - __bfloat162float(c));
    __nv_bfloat16 rd = __float2bfloat16_rn(v.w - __bfloat162float(d));
    h0 = pack2(a, b); h1 = pack2(c, d);
    l0 = pack2(ra, rb); l1 = pack2(rc, rd);
}

__device__ __forceinline__ void mma16(float* c, const unsigned* a, const unsigned* b) {
    asm volatile(
        "mma.sync.aligned.m16n8k16.row.col.f32.bf16.bf16.f32 "
        "{%0,%1,%2,%3}, {%4,%5,%6,%7}, {%8,%9}, {%0,%1,%2,%3};\n"
        : "+f"(c[0]), "+f"(c[1]), "+f"(c[2]), "+f"(c[3])
        : "r"(a[0]), "r"(a[1]), "r"(a[2]), "r"(a[3]), "r"(b[0]), "r"(b[1]));
}

#define ASU 12  // A smem row stride in uint32 (conflict-free fragment LDS)
#define BSU 12  // B smem col stride in uint32

__global__ void gemm_bf3_kernel(const float* __restrict__ A, const float* __restrict__ B,
                                float* __restrict__ C, int N, int M) {
    __shared__ unsigned Ahi[128][ASU], Alo[128][ASU];
    __shared__ unsigned Bhi[64][BSU],  Blo[64][BSU];
    const int tid = threadIdx.x;
    const int lane = tid & 31;
    const int wid = tid >> 5;
    const int warpM = wid & 3;
    const int warpN = wid >> 2;
    const int g  = lane >> 2;
    const int tg = lane & 3;
    const int rowBase = blockIdx.x * 128;
    const int colBase = blockIdx.y * 64;

    // A load mapping: thread t loads row r=t>>1, k-offsets 8*(t&1) and 8*(t&1)+4
    const int aRow = tid >> 1;
    const int aK   = (tid & 1) << 3;
    const bool aOk = (rowBase + aRow) < N;
    const float* Ag = A + (size_t)(rowBase + aRow) * 256 + aK;

    // B load mapping: thread t handles kpair kp=t>>5, cols c2=(t&31)*2
    const int kp = tid >> 5;
    const int c2 = (tid & 31) << 1;
    const float* Bg = B + (size_t)(2 * kp) * M + colBase + c2;

    float c[2][4][4] = {};

    for (int kt = 0; kt < 16; kt++) {
        // ---- A tile: 128x16 fp32 -> bf16 hi/lo packed pairs ----
        {
            float4 v0 = make_float4(0.f, 0.f, 0.f, 0.f), v1 = v0;
            if (aOk) {
                v0 = *reinterpret_cast<const float4*>(Ag + kt * 16);
                v1 = *reinterpret_cast<const float4*>(Ag + kt * 16 + 4);
            }
            unsigned h0, h1, l0, l1;
            int kpb = aK >> 1;                 // kpair base: 0 or 4
            split4(v0, h0, h1, l0, l1);
            Ahi[aRow][kpb + 0] = h0; Ahi[aRow][kpb + 1] = h1;
            Alo[aRow][kpb + 0] = l0; Alo[aRow][kpb + 1] = l1;
            split4(v1, h0, h1, l0, l1);
            Ahi[aRow][kpb + 2] = h0; Ahi[aRow][kpb + 3] = h1;
            Alo[aRow][kpb + 2] = l0; Alo[aRow][kpb + 3] = l1;
        }
        // ---- B tile: 16x64 fp32 -> packed along k ----
        {
            const float* bp = Bg + (size_t)(kt * 16) * M;
            float2 r0 = *reinterpret_cast<const float2*>(bp);        // row 2kp
            float2 r1 = *reinterpret_cast<const float2*>(bp + M);    // row 2kp+1
            __nv_bfloat16 e0 = __float2bfloat16_rn(r0.x);
            __nv_bfloat16 o0 = __float2bfloat16_rn(r1.x);
            __nv_bfloat16 e1 = __float2bfloat16_rn(r0.y);
            __nv_bfloat16 o1 = __float2bfloat16_rn(r1.y);
            Bhi[c2][kp]     = pack2(e0, o0);
            Bhi[c2 + 1][kp] = pack2(e1, o1);
            __nv_bfloat16 re0 = __float2bfloat16_rn(r0.x - __bfloat162float(e0));
            __nv_bfloat16 ro0 = __float2bfloat16_rn(r1.x - __bfloat162float(o0));
            __nv_bfloat16 re1 = __float2bfloat16_rn(r0.y - __bfloat162float(e1));
            __nv_bfloat16 ro1 = __float2bfloat16_rn(r1.y - __bfloat162float(o1));
            Blo[c2][kp]     = pack2(re0, ro0);
            Blo[c2 + 1][kp] = pack2(re1, ro1);
        }
        __syncthreads();

        unsigned ah[2][4], al[2][4], bh[4][2], bl[4][2];
        #pragma unroll
        for (int mt = 0; mt < 2; mt++) {
            int r = warpM * 32 + mt * 16 + g;
            ah[mt][0] = Ahi[r][tg];     ah[mt][1] = Ahi[r + 8][tg];
            ah[mt][2] = Ahi[r][tg + 4]; ah[mt][3] = Ahi[r + 8][tg + 4];
            al[mt][0] = Alo[r][tg];     al[mt][1] = Alo[r + 8][tg];
            al[mt][2] = Alo[r][tg + 4]; al[mt][3] = Alo[r + 8][tg + 4];
        }
        #pragma unroll
        for (int nt = 0; nt < 4; nt++) {
            int col = warpN * 32 + nt * 8 + g;
            bh[nt][0] = Bhi[col][tg]; bh[nt][1] = Bhi[col][tg + 4];
            bl[nt][0] = Blo[col][tg]; bl[nt][1] = Blo[col][tg + 4];
        }
        #pragma unroll
        for (int mt = 0; mt < 2; mt++)
            #pragma unroll
            for (int nt = 0; nt < 4; nt++) {
                mma16(c[mt][nt], ah[mt], bh[nt]);
                mma16(c[mt][nt], ah[mt], bl[nt]);
                mma16(c[mt][nt], al[mt], bh[nt]);
            }
        __syncthreads();
    }

    #pragma unroll
    for (int mt = 0; mt < 2; mt++) {
        int r0 = rowBase + warpM * 32 + mt * 16 + g;
        #pragma unroll
        for (int nt = 0; nt < 4; nt++) {
            int col = colBase + warpN * 32 + nt * 8 + tg * 2;
            if (r0 < N)
                *reinterpret_cast<float2*>(&C[(size_t)r0 * M + col]) = make_float2(c[mt][nt][0], c[mt][nt][1]);
            if (r0 + 8 < N)
                *reinterpret_cast<float2*>(&C[(size_t)(r0 + 8) * M + col]) = make_float2(c[mt][nt][2], c[mt][nt][3]);
        }
    }
}

// ============================================================
// Attention logits from folded P: [als | ald] = feat @ P.  Warp per node.
// ============================================================
template <int H>
__global__ void attn_kernel(const float* __restrict__ feat, const float* __restrict__ P,
                            int n) {
    __shared__ float sP[2048];                 // [c][256]
    for (int i = threadIdx.x; i < 2048; i += blockDim.x) sP[i] = P[i];
    __syncthreads();
    int w = (blockIdx.x * blockDim.x + threadIdx.x) >> 5;
    int lane = threadIdx.x & 31;
    if (w >= n) return;
    float acc[8] = {};
    const float* fr = feat + (size_t)w * 256;
    #pragma unroll
    for (int j = 0; j < 8; j++) {
        int k = lane + 32 * j;
        float f = fr[k];
        #pragma unroll
        for (int cc = 0; cc < 8; cc++) acc[cc] += f * sP[cc * 256 + k];
    }
    #pragma unroll
    for (int cc = 0; cc < 8; cc++) {
        float v = acc[cc];
        #pragma unroll
        for (int off = 16; off > 0; off >>= 1)
            v += __shfl_xor_sync(0xffffffffu, v, off);
        if (lane == 0) {
            if (cc < H) g_als[w * H + cc] = v;
            else if (cc >= 4 && cc < 4 + H) g_ald[w * H + (cc - 4)] = v;
        }
    }
}

// ============================================================
// Aggregation: warp per dst node, online softmax, edge-ahead prefetch.
// ============================================================
template <int H>
__global__ void agg_kernel(const float* __restrict__ hs, const float* __restrict__ bias,
                           float* __restrict__ out, int n, int doRelu) {
    const int HC = H * 64;
    const int R  = HC / 32;
    int w = (blockIdx.x * blockDim.x + threadIdx.x) >> 5;
    int lane = threadIdx.x & 31;
    if (w >= n) return;
    int h = (lane * R) / 64;
    float ald_h = g_ald[w * H + h];

    float acc[R];
    #pragma unroll
    for (int r = 0; r < R; r++) acc[r] = 0.f;
    float m = -1e30f, den = 0.f;

    int beg = g_rowptr[w], end = g_rowptr[w + 1];
    int sNext = 0; float aNext = 0.f;
    if (beg < end) { sNext = g_ssrc[beg]; aNext = g_als[sNext * H + h]; }
    for (int e = beg; e < end; e++) {
        int s = sNext; float als_v = aNext;
        if (e + 1 < end) { sNext = g_ssrc[e + 1]; aNext = g_als[sNext * H + h]; }
        float ev = als_v + ald_h;
        ev = ev > 0.f ? ev : 0.2f * ev;
        float mn = fmaxf(m, ev);
        float sc = __expf(m - mn);
        float wg = __expf(ev - mn);
        den = den * sc + wg;
        const float* hp = &hs[(size_t)s * HC + lane * R];
        if (R == 8) {
            float4 v0 = *reinterpret_cast<const float4*>(hp);
            float4 v1 = *reinterpret_cast<const float4*>(hp + 4);
            acc[0] = acc[0] * sc + wg * v0.x; acc[1] = acc[1] * sc + wg * v0.y;
            acc[2] = acc[2] * sc + wg * v0.z; acc[3] = acc[3] * sc + wg * v0.w;
            acc[4] = acc[4] * sc + wg * v1.x; acc[5] = acc[5] * sc + wg * v1.y;
            acc[6] = acc[6] * sc + wg * v1.z; acc[7] = acc[7] * sc + wg * v1.w;
        } else {
            float2 v = *reinterpret_cast<const float2*>(hp);
            acc[0] = acc[0] * sc + wg * v.x;
            acc[1] = acc[1] * sc + wg * v.y;
        }
        m = mn;
    }
    float invd = (end > beg) ? 1.f / den : 0.f;
    #pragma unroll
    for (int r = 0; r < R; r++) {
        float o = acc[r] * invd + bias[lane * R + r];
        if (doRelu) o = fmaxf(o, 0.f);
        out[(size_t)w * HC + lane * R + r] = o;
    }
}

// ============================================================
// Launch
// ============================================================
extern "C" void kernel_launch(void* const* d_in, const int* in_sizes, int n_in,
                              void* d_out, int out_size) {
    const float* x  = (const float*)d_in[0];
    const int*   ei = (const int*)d_in[1];
    int n = in_sizes[0] / 256;
    int E = in_sizes[1] / 2;
    const int* src = ei;
    const int* dst = ei + E;

    const float *Ws[4], *Wd[4], *as_[4], *ad_[4], *bb[4];
    for (int l = 0; l < 4; l++) {
        Ws[l]  = (const float*)d_in[2 + 5 * l + 0];
        Wd[l]  = (const float*)d_in[2 + 5 * l + 1];
        as_[l] = (const float*)d_in[2 + 5 * l + 2];
        ad_[l] = (const float*)d_in[2 + 5 * l + 3];
        bb[l]  = (const float*)d_in[2 + 5 * l + 4];
    }

    void *p_hs, *p_f0, *p_f1, *p_cnt, *p_at;
    cudaGetSymbolAddress(&p_hs, g_hs);
    cudaGetSymbolAddress(&p_f0, g_f0);
    cudaGetSymbolAddress(&p_f1, g_f1);
    cudaGetSymbolAddress(&p_cnt, g_cnt);
    cudaGetSymbolAddress(&p_at, g_attnAll);
    float* hs = (float*)p_hs;
    float* f0 = (float*)p_f0;
    float* f1 = (float*)p_f1;
    const float* at = (const float*)p_at;

    // ---- sort edges by dst ----
    int nb = (n + 1023) / 1024;
    cudaMemsetAsync(p_cnt, 0, (size_t)(n + 1) * sizeof(int));
    hist_kernel<<<(E + 255) / 256, 256>>>(dst, E);
    scanA_kernel<<<nb, 1024>>>(n);
    scanB_kernel<<<1, 64>>>(nb);
    scanC_kernel<<<nb, 1024>>>(n, E);
    scatter_kernel<<<(E + 255) / 256, 256>>>(src, dst, E);

    // ---- fold all layers' attention vectors ----
    attn_fold_kernel<<<1024, 256>>>(Ws[0], Ws[1], Ws[2], Ws[3],
                                    Wd[0], Wd[1], Wd[2], Wd[3],
                                    as_[0], as_[1], as_[2], as_[3],
                                    ad_[0], ad_[1], ad_[2], ad_[3]);

    int warpBlocks = (n * 32 + 255) / 256;
    dim3 gGrid((n + 127) / 128, 4);    // M=256
    dim3 gGrid4((n + 127) / 128, 1);   // M=64

    const float* fin = x;
    float* fouts[3] = {f0, f1, f0};
    for (int l = 0; l < 3; l++) {
        gemm_bf3_kernel<<<gGrid, 256>>>(fin, Ws[l], hs, n, 256);
        attn_kernel<4><<<warpBlocks, 256>>>(fin, at + l * 2048, n);
        agg_kernel<4><<<warpBlocks, 256>>>(hs, bb[l], fouts[l], n, 1);
        fin = fouts[l];
    }
    gemm_bf3_kernel<<<gGrid4, 256>>>(fin, Ws[3], hs, n, 64);
    attn_kernel<1><<<warpBlocks, 256>>>(fin, at + 3 * 2048, n);
    agg_kernel<1><<<warpBlocks, 256>>>(hs, bb[3], (float*)d_out, n, 0);
}

// round 8
// speedup vs baseline: 1.6230x; 1.0191x over previous
#include <cuda_runtime.h>
#include <cuda_bf16.h>

#define NMAX 50000
#define EMAX 500000

// ---- static device scratch (allocation-free contract) ----
__device__ float g_hs[(size_t)NMAX * 256];   // per-layer source projections
__device__ float g_f0[(size_t)NMAX * 256];   // feature ping
__device__ float g_f1[(size_t)NMAX * 256];   // feature pong
__device__ float g_als[NMAX * 4];            // per-node per-head source attn logit
__device__ float g_ald[NMAX * 4];            // per-node per-head dest attn logit
__device__ float g_attnAll[4 * 2048];        // folded [Ws@a_src^T | Wd@a_dst^T], [l][c][k]
__device__ int   g_cnt[NMAX + 1];
__device__ int   g_cur[NMAX + 1];
__device__ int   g_rowptr[NMAX + 1];
__device__ int   g_bsum[64];
__device__ int   g_ssrc[EMAX];               // src ids sorted by dst

// ============================================================
// Edge sort: counting sort by dst (hist -> 3-phase scan -> scatter)
// ============================================================
__global__ void hist_kernel(const int* __restrict__ dst, int E) {
    int e = blockIdx.x * blockDim.x + threadIdx.x;
    if (e < E) atomicAdd(&g_cnt[dst[e]], 1);
}

__global__ void scanA_kernel(int n) {
    __shared__ int sh[1024];
    int tid = threadIdx.x;
    int i = blockIdx.x * 1024 + tid;
    int v = (i < n) ? g_cnt[i] : 0;
    sh[tid] = v;
    __syncthreads();
    #pragma unroll
    for (int off = 1; off < 1024; off <<= 1) {
        int t = (tid >= off) ? sh[tid - off] : 0;
        __syncthreads();
        sh[tid] += t;
        __syncthreads();
    }
    if (i < n) g_rowptr[i] = sh[tid] - v;
    if (tid == 1023) g_bsum[blockIdx.x] = sh[1023];
}

__global__ void scanB_kernel(int nb) {
    __shared__ int sh[64];
    int tid = threadIdx.x;
    int v = (tid < nb) ? g_bsum[tid] : 0;
    sh[tid] = v;
    __syncthreads();
    #pragma unroll
    for (int off = 1; off < 64; off <<= 1) {
        int t = (tid >= off) ? sh[tid - off] : 0;
        __syncthreads();
        sh[tid] += t;
        __syncthreads();
    }
    if (tid < nb) g_bsum[tid] = sh[tid] - v;
}

__global__ void scanC_kernel(int n, int E) {
    int i = blockIdx.x * 1024 + threadIdx.x;
    if (i < n) {
        int r = g_rowptr[i] + g_bsum[blockIdx.x];
        g_rowptr[i] = r;
        g_cur[i] = r;
    }
    if (i == n) g_rowptr[n] = E;
}

__global__ void scatter_kernel(const int* __restrict__ src, const int* __restrict__ dst, int E) {
    int e = blockIdx.x * blockDim.x + threadIdx.x;
    if (e < E) {
        int d = dst[e];
        int p = atomicAdd(&g_cur[d], 1);
        g_ssrc[p] = src[e];
    }
}

// ============================================================
// Fold attention vectors for ALL layers into P[l][c][k]:
//   c<4 : Ws_l @ a_src_l^T (head c) ;  c>=4 : Wd_l @ a_dst_l^T (head c-4)
// ============================================================
__global__ void attn_fold_kernel(const float* __restrict__ Ws0, const float* __restrict__ Ws1,
                                 const float* __restrict__ Ws2, const float* __restrict__ Ws3,
                                 const float* __restrict__ Wd0, const float* __restrict__ Wd1,
                                 const float* __restrict__ Wd2, const float* __restrict__ Wd3,
                                 const float* __restrict__ s0, const float* __restrict__ s1,
                                 const float* __restrict__ s2, const float* __restrict__ s3,
                                 const float* __restrict__ d0, const float* __restrict__ d1,
                                 const float* __restrict__ d2, const float* __restrict__ d3) {
    int w = blockIdx.x * (blockDim.x >> 5) + (threadIdx.x >> 5);
    int lane = threadIdx.x & 31;
    if (w >= 8192) return;
    int l = w >> 11;
    int rem = w & 2047;
    int c = rem >> 8;
    int k = rem & 255;
    int H = (l == 3) ? 1 : 4;
    int side = c >> 2;
    int h = c & 3;
    float val = 0.f;
    if (h < H) {
        const float* W;
        const float* a;
        if (side == 0) {
            W = (l == 0) ? Ws0 : (l == 1) ? Ws1 : (l == 2) ? Ws2 : Ws3;
            a = (l == 0) ? s0 : (l == 1) ? s1 : (l == 2) ? s2 : s3;
        } else {
            W = (l == 0) ? Wd0 : (l == 1) ? Wd1 : (l == 2) ? Wd2 : Wd3;
            a = (l == 0) ? d0 : (l == 1) ? d1 : (l == 2) ? d2 : d3;
        }
        int HC = H * 64;
        const float* wr = W + (size_t)k * HC + h * 64;
        const float* ar = a + h * 64;
        float sacc = wr[lane] * ar[lane] + wr[lane + 32] * ar[lane + 32];
        #pragma unroll
        for (int off = 16; off > 0; off >>= 1)
            sacc += __shfl_xor_sync(0xffffffffu, sacc, off);
        val = sacc;
    }
    if (lane == 0) g_attnAll[l * 2048 + c * 256 + k] = val;
}

// ============================================================
// Fused tensor-core GEMM (3-term bf16 split) + attention logits.
// Grid y: [0, gridDim.y-2] = gemm col-blocks; y == gridDim.y-1 = attn plane.
// ============================================================
__device__ __forceinline__ unsigned pack2(__nv_bfloat16 e, __nv_bfloat16 o) {
    __nv_bfloat162 t = __halves2bfloat162(e, o);
    return *reinterpret_cast<unsigned*>(&t);
}

__device__ __forceinline__ void split4(const float4& v, unsigned& h0, unsigned& h1,
                                       unsigned& l0, unsigned& l1) {
    __nv_bfloat16 a = __float2bfloat16_rn(v.x);
    __nv_bfloat16 b = __float2bfloat16_rn(v.y);
    __nv_bfloat16 c = __float2bfloat16_rn(v.z);
    __nv_bfloat16 d = __float2bfloat16_rn(v.w);
    __nv_bfloat16 ra = __float2bfloat16_rn(v.x - __bfloat162float(a));
    __nv_bfloat16 rb = __float2bfloat16_rn(v.y - __bfloat162float(b));
    __nv_bfloat16 rc = __float2bfloat16_rn(v.z - __bfloat162float(c));
    __nv_bfloat16 rd = __float2bfloat16_rn(v.w - __bfloat162float(d));
    h0 = pack2(a, b); h1 = pack2(c, d);
    l0 = pack2(ra, rb); l1 = pack2(rc, rd);
}

__device__ __forceinline__ void mma16(float* c, const unsigned* a, const unsigned* b) {
    asm volatile(
        "mma.sync.aligned.m16n8k16.row.col.f32.bf16.bf16.f32 "
        "{%0,%1,%2,%3}, {%4,%5,%6,%7}, {%8,%9}, {%0,%1,%2,%3};\n"
        : "+f"(c[0]), "+f"(c[1]), "+f"(c[2]), "+f"(c[3])
        : "r"(a[0]), "r"(a[1]), "r"(a[2]), "r"(a[3]), "r"(b[0]), "r"(b[1]));
}

#define ASU 12
#define BSU 12

__global__ void gemm_attn_kernel(const float* __restrict__ A, const float* __restrict__ B,
                                 const float* __restrict__ P, float* __restrict__ C,
                                 int N, int M, int H) {
    const int tid = threadIdx.x;
    const int lane = tid & 31;
    const int wid = tid >> 5;
    const int rowBase = blockIdx.x * 128;

    // ---------------- attn plane ----------------
    if (blockIdx.y == gridDim.y - 1) {
        // P[c][k] into registers: 64 floats/lane covering this lane's k-slice
        float pk[2][4][8];
        #pragma unroll
        for (int j = 0; j < 2; j++)
            #pragma unroll
            for (int u = 0; u < 4; u++)
                #pragma unroll
                for (int c = 0; c < 8; c++)
                    pk[j][u][c] = P[c * 256 + 128 * j + lane * 4 + u];

        for (int i = 0; i < 16; i++) {
            int node = rowBase + wid * 16 + i;
            if (node >= N) break;                       // uniform per warp
            float acc[8] = {};
            #pragma unroll
            for (int j = 0; j < 2; j++) {
                float4 f = *reinterpret_cast<const float4*>(&A[(size_t)node * 256 + 128 * j + lane * 4]);
                float fv[4] = {f.x, f.y, f.z, f.w};
                #pragma unroll
                for (int u = 0; u < 4; u++)
                    #pragma unroll
                    for (int c = 0; c < 8; c++)
                        acc[c] += fv[u] * pk[j][u][c];
            }
            #pragma unroll
            for (int c = 0; c < 8; c++) {
                float v = acc[c];
                #pragma unroll
                for (int off = 16; off > 0; off >>= 1)
                    v += __shfl_xor_sync(0xffffffffu, v, off);
                acc[c] = v;
            }
            if (lane == 0) {
                for (int c = 0; c < H; c++) g_als[node * H + c] = acc[c];
                for (int c = 0; c < H; c++) g_ald[node * H + c] = acc[4 + c];
            }
        }
        return;
    }

    // ---------------- gemm plane ----------------
    __shared__ unsigned Ahi[128][ASU], Alo[128][ASU];
    __shared__ unsigned Bhi[64][BSU],  Blo[64][BSU];
    const int warpM = wid & 3;
    const int warpN = wid >> 2;
    const int g  = lane >> 2;
    const int tg = lane & 3;
    const int colBase = blockIdx.y * 64;

    const int aRow = tid >> 1;
    const int aK   = (tid & 1) << 3;
    const bool aOk = (rowBase + aRow) < N;
    const float* Ag = A + (size_t)(rowBase + aRow) * 256 + aK;

    const int kp = tid >> 5;
    const int c2 = (tid & 31) << 1;
    const float* Bg = B + (size_t)(2 * kp) * M + colBase + c2;

    float c[2][4][4] = {};

    // raw prefetch registers
    float4 ar0 = make_float4(0.f, 0.f, 0.f, 0.f), ar1 = ar0;
    float2 br0, br1;
    if (aOk) {
        ar0 = *reinterpret_cast<const float4*>(Ag);
        ar1 = *reinterpret_cast<const float4*>(Ag + 4);
    }
    br0 = *reinterpret_cast<const float2*>(Bg);
    br1 = *reinterpret_cast<const float2*>(Bg + M);

    for (int kt = 0; kt < 16; kt++) {
        // convert + store current raw
        {
            unsigned h0, h1, l0, l1;
            int kpb = aK >> 1;
            split4(ar0, h0, h1, l0, l1);
            Ahi[aRow][kpb + 0] = h0; Ahi[aRow][kpb + 1] = h1;
            Alo[aRow][kpb + 0] = l0; Alo[aRow][kpb + 1] = l1;
            split4(ar1, h0, h1, l0, l1);
            Ahi[aRow][kpb + 2] = h0; Ahi[aRow][kpb + 3] = h1;
            Alo[aRow][kpb + 2] = l0; Alo[aRow][kpb + 3] = l1;

            __nv_bfloat16 e0 = __float2bfloat16_rn(br0.x);
            __nv_bfloat16 o0 = __float2bfloat16_rn(br1.x);
            __nv_bfloat16 e1 = __float2bfloat16_rn(br0.y);
            __nv_bfloat16 o1 = __float2bfloat16_rn(br1.y);
            Bhi[c2][kp]     = pack2(e0, o0);
            Bhi[c2 + 1][kp] = pack2(e1, o1);
            __nv_bfloat16 re0 = __float2bfloat16_rn(br0.x - __bfloat162float(e0));
            __nv_bfloat16 ro0 = __float2bfloat16_rn(br1.x - __bfloat162float(o0));
            __nv_bfloat16 re1 = __float2bfloat16_rn(br0.y - __bfloat162float(e1));
            __nv_bfloat16 ro1 = __float2bfloat16_rn(br1.y - __bfloat162float(o1));
            Blo[c2][kp]     = pack2(re0, ro0);
            Blo[c2 + 1][kp] = pack2(re1, ro1);
        }
        __syncthreads();

        // issue next tile's global loads (overlap with mma below)
        if (kt + 1 < 16) {
            if (aOk) {
                ar0 = *reinterpret_cast<const float4*>(Ag + (kt + 1) * 16);
                ar1 = *reinterpret_cast<const float4*>(Ag + (kt + 1) * 16 + 4);
            }
            const float* bp = Bg + (size_t)((kt + 1) * 16) * M;
            br0 = *reinterpret_cast<const float2*>(bp);
            br1 = *reinterpret_cast<const float2*>(bp + M);
        }

        unsigned ah[2][4], al[2][4], bh[4][2], bl[4][2];
        #pragma unroll
        for (int mt = 0; mt < 2; mt++) {
            int r = warpM * 32 + mt * 16 + g;
            ah[mt][0] = Ahi[r][tg];     ah[mt][1] = Ahi[r + 8][tg];
            ah[mt][2] = Ahi[r][tg + 4]; ah[mt][3] = Ahi[r + 8][tg + 4];
            al[mt][0] = Alo[r][tg];     al[mt][1] = Alo[r + 8][tg];
            al[mt][2] = Alo[r][tg + 4]; al[mt][3] = Alo[r + 8][tg + 4];
        }
        #pragma unroll
        for (int nt = 0; nt < 4; nt++) {
            int col = warpN * 32 + nt * 8 + g;
            bh[nt][0] = Bhi[col][tg]; bh[nt][1] = Bhi[col][tg + 4];
            bl[nt][0] = Blo[col][tg]; bl[nt][1] = Blo[col][tg + 4];
        }
        #pragma unroll
        for (int mt = 0; mt < 2; mt++)
            #pragma unroll
            for (int nt = 0; nt < 4; nt++) {
                mma16(c[mt][nt], ah[mt], bh[nt]);
                mma16(c[mt][nt], ah[mt], bl[nt]);
                mma16(c[mt][nt], al[mt], bh[nt]);
            }
        __syncthreads();
    }

    #pragma unroll
    for (int mt = 0; mt < 2; mt++) {
        int r0 = rowBase + warpM * 32 + mt * 16 + g;
        #pragma unroll
        for (int nt = 0; nt < 4; nt++) {
            int col = colBase + warpN * 32 + nt * 8 + tg * 2;
            if (r0 < N)
                *reinterpret_cast<float2*>(&C[(size_t)r0 * M + col]) = make_float2(c[mt][nt][0], c[mt][nt][1]);
            if (r0 + 8 < N)
                *reinterpret_cast<float2*>(&C[(size_t)(r0 + 8) * M + col]) = make_float2(c[mt][nt][2], c[mt][nt][3]);
        }
    }
}

// ============================================================
// Aggregation: warp per dst node. No-max softmax (logits bounded;
// exp headroom to 88 is enormous), 2-edge unroll for MLP.
// ============================================================
template <int H>
__global__ void agg_kernel(const float* __restrict__ hs, const float* __restrict__ bias,
                           float* __restrict__ out, int n, int doRelu) {
    const int HC = H * 64;
    const int R  = HC / 32;
    int w = (blockIdx.x * blockDim.x + threadIdx.x) >> 5;
    int lane = threadIdx.x & 31;
    if (w >= n) return;
    int h = (lane * R) / 64;
    float ald_h = g_ald[w * H + h];

    float acc[R];
    #pragma unroll
    for (int r = 0; r < R; r++) acc[r] = 0.f;
    float den = 0.f;

    int beg = g_rowptr[w], end = g_rowptr[w + 1];
    int e = beg;
    for (; e + 1 < end; e += 2) {
        int s0 = g_ssrc[e];
        int s1 = g_ssrc[e + 1];
        float a0 = g_als[s0 * H + h];
        float a1 = g_als[s1 * H + h];
        float ev0 = a0 + ald_h; ev0 = ev0 > 0.f ? ev0 : 0.2f * ev0;
        float ev1 = a1 + ald_h; ev1 = ev1 > 0.f ? ev1 : 0.2f * ev1;
        float w0 = __expf(ev0), w1 = __expf(ev1);
        den += w0 + w1;
        const float* hp0 = &hs[(size_t)s0 * HC + lane * R];
        const float* hp1 = &hs[(size_t)s1 * HC + lane * R];
        if (R == 8) {
            float4 x0 = *reinterpret_cast<const float4*>(hp0);
            float4 x1 = *reinterpret_cast<const float4*>(hp0 + 4);
            float4 y0 = *reinterpret_cast<const float4*>(hp1);
            float4 y1 = *reinterpret_cast<const float4*>(hp1 + 4);
            acc[0] += w0 * x0.x + w1 * y0.x; acc[1] += w0 * x0.y + w1 * y0.y;
            acc[2] += w0 * x0.z + w1 * y0.z; acc[3] += w0 * x0.w + w1 * y0.w;
            acc[4] += w0 * x1.x + w1 * y1.x; acc[5] += w0 * x1.y + w1 * y1.y;
            acc[6] += w0 * x1.z + w1 * y1.z; acc[7] += w0 * x1.w + w1 * y1.w;
        } else {
            float2 x = *reinterpret_cast<const float2*>(hp0);
            float2 y = *reinterpret_cast<const float2*>(hp1);
            acc[0] += w0 * x.x + w1 * y.x;
            acc[1] += w0 * x.y + w1 * y.y;
        }
    }
    if (e < end) {
        int s = g_ssrc[e];
        float ev = g_als[s * H + h] + ald_h;
        ev = ev > 0.f ? ev : 0.2f * ev;
        float wg = __expf(ev);
        den += wg;
        const float* hp = &hs[(size_t)s * HC + lane * R];
        if (R == 8) {
            float4 v0 = *reinterpret_cast<const float4*>(hp);
            float4 v1 = *reinterpret_cast<const float4*>(hp + 4);
            acc[0] += wg * v0.x; acc[1] += wg * v0.y;
            acc[2] += wg * v0.z; acc[3] += wg * v0.w;
            acc[4] += wg * v1.x; acc[5] += wg * v1.y;
            acc[6] += wg * v1.z; acc[7] += wg * v1.w;
        } else {
            float2 v = *reinterpret_cast<const float2*>(hp);
            acc[0] += wg * v.x;
            acc[1] += wg * v.y;
        }
    }
    float invd = (end > beg) ? 1.f / den : 0.f;
    #pragma unroll
    for (int r = 0; r < R; r++) {
        float o = acc[r] * invd + bias[lane * R + r];
        if (doRelu) o = fmaxf(o, 0.f);
        out[(size_t)w * HC + lane * R + r] = o;
    }
}

// ============================================================
// Launch
// ============================================================
extern "C" void kernel_launch(void* const* d_in, const int* in_sizes, int n_in,
                              void* d_out, int out_size) {
    const float* x  = (const float*)d_in[0];
    const int*   ei = (const int*)d_in[1];
    int n = in_sizes[0] / 256;
    int E = in_sizes[1] / 2;
    const int* src = ei;
    const int* dst = ei + E;

    const float *Ws[4], *Wd[4], *as_[4], *ad_[4], *bb[4];
    for (int l = 0; l < 4; l++) {
        Ws[l]  = (const float*)d_in[2 + 5 * l + 0];
        Wd[l]  = (const float*)d_in[2 + 5 * l + 1];
        as_[l] = (const float*)d_in[2 + 5 * l + 2];
        ad_[l] = (const float*)d_in[2 + 5 * l + 3];
        bb[l]  = (const float*)d_in[2 + 5 * l + 4];
    }

    void *p_hs, *p_f0, *p_f1, *p_cnt, *p_at;
    cudaGetSymbolAddress(&p_hs, g_hs);
    cudaGetSymbolAddress(&p_f0, g_f0);
    cudaGetSymbolAddress(&p_f1, g_f1);
    cudaGetSymbolAddress(&p_cnt, g_cnt);
    cudaGetSymbolAddress(&p_at, g_attnAll);
    float* hs = (float*)p_hs;
    float* f0 = (float*)p_f0;
    float* f1 = (float*)p_f1;
    const float* at = (const float*)p_at;

    // ---- sort edges by dst ----
    int nb = (n + 1023) / 1024;
    cudaMemsetAsync(p_cnt, 0, (size_t)(n + 1) * sizeof(int));
    hist_kernel<<<(E + 255) / 256, 256>>>(dst, E);
    scanA_kernel<<<nb, 1024>>>(n);
    scanB_kernel<<<1, 64>>>(nb);
    scanC_kernel<<<nb, 1024>>>(n, E);
    scatter_kernel<<<(E + 255) / 256, 256>>>(src, dst, E);

    // ---- fold all layers' attention vectors ----
    attn_fold_kernel<<<1024, 256>>>(Ws[0], Ws[1], Ws[2], Ws[3],
                                    Wd[0], Wd[1], Wd[2], Wd[3],
                                    as_[0], as_[1], as_[2], as_[3],
                                    ad_[0], ad_[1], ad_[2], ad_[3]);

    int warpBlocks = (n * 32 + 255) / 256;
    int gx = (n + 127) / 128;
    dim3 gGrid(gx, 5);     // y 0..3 gemm (M=256), y=4 attn
    dim3 gGrid4(gx, 2);    // y 0 gemm (M=64), y=1 attn

    const float* fin = x;
    float* fouts[3] = {f0, f1, f0};
    for (int l = 0; l < 3; l++) {
        gemm_attn_kernel<<<gGrid, 256>>>(fin, Ws[l], at + l * 2048, hs, n, 256, 4);
        agg_kernel<4><<<warpBlocks, 256>>>(hs, bb[l], fouts[l], n, 1);
        fin = fouts[l];
    }
    gemm_attn_kernel<<<gGrid4, 256>>>(fin, Ws[3], at + 3 * 2048, hs, n, 64, 1);
    agg_kernel<1><<<warpBlocks, 256>>>(hs, bb[3], (float*)d_out, n, 0);
}

// round 9
// speedup vs baseline: 1.7784x; 1.0958x over previous
#include <cuda_runtime.h>
#include <cuda_bf16.h>

#define NMAX 50000
#define EMAX 500000

// ---- static device scratch (allocation-free contract) ----
__device__ float    g_hs[(size_t)NMAX * 256];     // per-layer source projections (fp32)
__device__ unsigned g_b0hi[(size_t)NMAX * 128];   // feature buffer 0, bf16 hi (k-pair packed)
__device__ unsigned g_b0lo[(size_t)NMAX * 128];
__device__ unsigned g_b1hi[(size_t)NMAX * 128];   // feature buffer 1
__device__ unsigned g_b1lo[(size_t)NMAX * 128];
__device__ unsigned g_Whi[106496];                // weights bf16 hi, k-major [kp][m], all layers
__device__ unsigned g_Wlo[106496];
__device__ float    g_als[NMAX * 4];
__device__ float    g_ald[NMAX * 4];
__device__ float    g_attnAll[4 * 2048];          // folded [Ws@a_src^T | Wd@a_dst^T]
__device__ int      g_cnt[NMAX + 1];
__device__ int      g_cur[NMAX + 1];
__device__ int      g_rowptr[NMAX + 1];
__device__ int      g_bsum[64];
__device__ int      g_ssrc[EMAX];

// ============================================================
// helpers
// ============================================================
__device__ __forceinline__ unsigned pack2(__nv_bfloat16 e, __nv_bfloat16 o) {
    __nv_bfloat162 t = __halves2bfloat162(e, o);
    return *reinterpret_cast<unsigned*>(&t);
}
__device__ __forceinline__ void split2(float a, float b, unsigned& hi, unsigned& lo) {
    __nv_bfloat16 ha = __float2bfloat16_rn(a);
    __nv_bfloat16 hb = __float2bfloat16_rn(b);
    hi = pack2(ha, hb);
    lo = pack2(__float2bfloat16_rn(a - __bfloat162float(ha)),
               __float2bfloat16_rn(b - __bfloat162float(hb)));
}
__device__ __forceinline__ float2 unpack2(unsigned hi, unsigned lo) {
    __nv_bfloat162 h = *reinterpret_cast<__nv_bfloat162*>(&hi);
    __nv_bfloat162 l = *reinterpret_cast<__nv_bfloat162*>(&lo);
    return make_float2(__bfloat162float(h.x) + __bfloat162float(l.x),
                       __bfloat162float(h.y) + __bfloat162float(l.y));
}
__device__ __forceinline__ void mma16(float* c, const unsigned* a, const unsigned* b) {
    asm volatile(
        "mma.sync.aligned.m16n8k16.row.col.f32.bf16.bf16.f32 "
        "{%0,%1,%2,%3}, {%4,%5,%6,%7}, {%8,%9}, {%0,%1,%2,%3};\n"
        : "+f"(c[0]), "+f"(c[1]), "+f"(c[2]), "+f"(c[3])
        : "r"(a[0]), "r"(a[1]), "r"(a[2]), "r"(a[3]), "r"(b[0]), "r"(b[1]));
}

// ============================================================
// Edge sort: counting sort by dst
// ============================================================
__global__ void hist_kernel(const int* __restrict__ dst, int E) {
    int e = blockIdx.x * blockDim.x + threadIdx.x;
    if (e < E) atomicAdd(&g_cnt[dst[e]], 1);
}
__global__ void scanA_kernel(int n) {
    __shared__ int sh[1024];
    int tid = threadIdx.x;
    int i = blockIdx.x * 1024 + tid;
    int v = (i < n) ? g_cnt[i] : 0;
    sh[tid] = v;
    __syncthreads();
    #pragma unroll
    for (int off = 1; off < 1024; off <<= 1) {
        int t = (tid >= off) ? sh[tid - off] : 0;
        __syncthreads();
        sh[tid] += t;
        __syncthreads();
    }
    if (i < n) g_rowptr[i] = sh[tid] - v;
    if (tid == 1023) g_bsum[blockIdx.x] = sh[1023];
}
__global__ void scanB_kernel(int nb) {
    __shared__ int sh[64];
    int tid = threadIdx.x;
    int v = (tid < nb) ? g_bsum[tid] : 0;
    sh[tid] = v;
    __syncthreads();
    #pragma unroll
    for (int off = 1; off < 64; off <<= 1) {
        int t = (tid >= off) ? sh[tid - off] : 0;
        __syncthreads();
        sh[tid] += t;
        __syncthreads();
    }
    if (tid < nb) g_bsum[tid] = sh[tid] - v;
}
__global__ void scanC_kernel(int n, int E) {
    int i = blockIdx.x * 1024 + threadIdx.x;
    if (i < n) {
        int r = g_rowptr[i] + g_bsum[blockIdx.x];
        g_rowptr[i] = r;
        g_cur[i] = r;
    }
    if (i == n) g_rowptr[n] = E;
}
__global__ void scatter_kernel(const int* __restrict__ src, const int* __restrict__ dst, int E) {
    int e = blockIdx.x * blockDim.x + threadIdx.x;
    if (e < E) {
        int d = dst[e];
        int p = atomicAdd(&g_cur[d], 1);
        g_ssrc[p] = src[e];
    }
}

// ============================================================
// Fold attention vectors (fp32, tiny)
// ============================================================
__global__ void attn_fold_kernel(const float* __restrict__ Ws0, const float* __restrict__ Ws1,
                                 const float* __restrict__ Ws2, const float* __restrict__ Ws3,
                                 const float* __restrict__ Wd0, const float* __restrict__ Wd1,
                                 const float* __restrict__ Wd2, const float* __restrict__ Wd3,
                                 const float* __restrict__ s0, const float* __restrict__ s1,
                                 const float* __restrict__ s2, const float* __restrict__ s3,
                                 const float* __restrict__ d0, const float* __restrict__ d1,
                                 const float* __restrict__ d2, const float* __restrict__ d3) {
    int w = blockIdx.x * (blockDim.x >> 5) + (threadIdx.x >> 5);
    int lane = threadIdx.x & 31;
    if (w >= 8192) return;
    int l = w >> 11;
    int rem = w & 2047;
    int c = rem >> 8;
    int k = rem & 255;
    int H = (l == 3) ? 1 : 4;
    int side = c >> 2;
    int h = c & 3;
    float val = 0.f;
    if (h < H) {
        const float* W;
        const float* a;
        if (side == 0) {
            W = (l == 0) ? Ws0 : (l == 1) ? Ws1 : (l == 2) ? Ws2 : Ws3;
            a = (l == 0) ? s0 : (l == 1) ? s1 : (l == 2) ? s2 : s3;
        } else {
            W = (l == 0) ? Wd0 : (l == 1) ? Wd1 : (l == 2) ? Wd2 : Wd3;
            a = (l == 0) ? d0 : (l == 1) ? d1 : (l == 2) ? d2 : d3;
        }
        int HC = H * 64;
        const float* wr = W + (size_t)k * HC + h * 64;
        const float* ar = a + h * 64;
        float sacc = wr[lane] * ar[lane] + wr[lane + 32] * ar[lane + 32];
        #pragma unroll
        for (int off = 16; off > 0; off >>= 1)
            sacc += __shfl_xor_sync(0xffffffffu, sacc, off);
        val = sacc;
    }
    if (lane == 0) g_attnAll[l * 2048 + c * 256 + k] = val;
}

// ============================================================
// Pre-split x (layer-1 features) into bf16 hi/lo packed (k-pairs).
// ============================================================
__global__ void presplit_x_kernel(const float* __restrict__ x, int total) {
    int i = blockIdx.x * blockDim.x + threadIdx.x;   // one uint32 (2 k) each
    if (i >= total) return;
    float2 v = reinterpret_cast<const float2*>(x)[i];
    unsigned hi, lo;
    split2(v.x, v.y, hi, lo);
    g_b0hi[i] = hi;
    g_b0lo[i] = lo;
}

// ============================================================
// Pre-split all Ws weights into k-major packed hi/lo: out[kp*M + m].
// ============================================================
__global__ void presplit_W_kernel(const float* __restrict__ W0, const float* __restrict__ W1,
                                  const float* __restrict__ W2, const float* __restrict__ W3) {
    int t = blockIdx.x * blockDim.x + threadIdx.x;
    if (t >= 106496) return;
    const float* W;
    int M, kp, m, base;
    if (t < 98304) {
        int l = t >> 15;
        int within = t & 32767;
        M = 256; kp = within >> 8; m = within & 255;
        base = l << 15;
        W = (l == 0) ? W0 : (l == 1) ? W1 : W2;
    } else {
        int within = t - 98304;
        M = 64; kp = within >> 6; m = within & 63;
        base = 98304;
        W = W3;
    }
    float a = W[(size_t)(2 * kp) * M + m];
    float b = W[(size_t)(2 * kp + 1) * M + m];
    unsigned hi, lo;
    split2(a, b, hi, lo);
    g_Whi[base + kp * M + m] = hi;
    g_Wlo[base + kp * M + m] = lo;
}

// ============================================================
// Fused GEMM (pre-split bf16, 3-term) + attention-logit plane.
// C[N,M] = A[N,256]*B[256,M].  BM=128, BK=32, 256 threads,
// 8 warps (4M x 2N), warp tile 32x32, mma.m16n8k16.
// Grid y: last plane = attn; others = 64-wide col blocks.
// ============================================================
#define ASTR 20
#define BSTR 72

__global__ __launch_bounds__(256, 1)
void gemm_attn_kernel(const unsigned* __restrict__ Ahi, const unsigned* __restrict__ Alo,
                      const unsigned* __restrict__ Bhi, const unsigned* __restrict__ Blo,
                      const float* __restrict__ P, float* __restrict__ C,
                      int N, int M, int H) {
    const int tid = threadIdx.x;
    const int lane = tid & 31;
    const int wid = tid >> 5;
    const int rowBase = blockIdx.x * 128;

    // ---------------- attn plane ----------------
    if (blockIdx.y == gridDim.y - 1) {
        float pk[8][8];   // pk[u][c], k = lane*8+u
        #pragma unroll
        for (int u = 0; u < 8; u++)
            #pragma unroll
            for (int c = 0; c < 8; c++)
                pk[u][c] = P[c * 256 + lane * 8 + u];

        for (int i = 0; i < 16; i++) {
            int node = rowBase + wid * 16 + i;
            if (node >= N) break;
            uint4 vh = *reinterpret_cast<const uint4*>(&Ahi[(size_t)node * 128 + lane * 4]);
            uint4 vl = *reinterpret_cast<const uint4*>(&Alo[(size_t)node * 128 + lane * 4]);
            float f[8];
            { float2 t = unpack2(vh.x, vl.x); f[0] = t.x; f[1] = t.y; }
            { float2 t = unpack2(vh.y, vl.y); f[2] = t.x; f[3] = t.y; }
            { float2 t = unpack2(vh.z, vl.z); f[4] = t.x; f[5] = t.y; }
            { float2 t = unpack2(vh.w, vl.w); f[6] = t.x; f[7] = t.y; }
            float acc[8] = {};
            #pragma unroll
            for (int u = 0; u < 8; u++)
                #pragma unroll
                for (int c = 0; c < 8; c++)
                    acc[c] += f[u] * pk[u][c];
            #pragma unroll
            for (int c = 0; c < 8; c++) {
                float v = acc[c];
                #pragma unroll
                for (int off = 16; off > 0; off >>= 1)
                    v += __shfl_xor_sync(0xffffffffu, v, off);
                acc[c] = v;
            }
            if (lane == 0) {
                for (int c = 0; c < H; c++) g_als[node * H + c] = acc[c];
                for (int c = 0; c < H; c++) g_ald[node * H + c] = acc[4 + c];
            }
        }
        return;
    }

    // ---------------- gemm plane ----------------
    __shared__ unsigned sAh[128][ASTR], sAl[128][ASTR];
    __shared__ unsigned sBh[32][BSTR],  sBl[32][BSTR];   // [kp 0..15 used][col]
    const int warpM = wid & 3;
    const int warpN = wid >> 2;
    const int g  = lane >> 2;
    const int tg = lane & 3;
    const int colBase = blockIdx.y * 64;

    // A mapping: row = tid>>1, kp-half = (tid&1)*8 : 2x uint4 (hi) + 2x (lo)
    const int aRow = tid >> 1;
    const int aH8  = (tid & 1) << 3;
    const bool aOk = (rowBase + aRow) < N;
    const unsigned* Agh = Ahi + (size_t)(rowBase + aRow) * 128 + aH8;
    const unsigned* Agl = Alo + (size_t)(rowBase + aRow) * 128 + aH8;

    // B mapping: kp_l = tid>>4 (0..15), m4 = (tid&15)*4 : 1x uint4 hi + lo
    const int bKp = tid >> 4;
    const int bM4 = (tid & 15) << 2;
    const unsigned* Bgh = Bhi + (size_t)bKp * M + colBase + bM4;
    const unsigned* Bgl = Blo + (size_t)bKp * M + colBase + bM4;

    float c[2][4][4] = {};

    uint4 rah0, rah1, ral0, ral1, rbh, rbl;
    const uint4 Z = make_uint4(0, 0, 0, 0);
    if (aOk) {
        rah0 = *reinterpret_cast<const uint4*>(Agh);
        rah1 = *reinterpret_cast<const uint4*>(Agh + 4);
        ral0 = *reinterpret_cast<const uint4*>(Agl);
        ral1 = *reinterpret_cast<const uint4*>(Agl + 4);
    } else { rah0 = rah1 = ral0 = ral1 = Z; }
    rbh = *reinterpret_cast<const uint4*>(Bgh);
    rbl = *reinterpret_cast<const uint4*>(Bgl);

    for (int kt = 0; kt < 8; kt++) {               // BK = 32 (16 kp)
        *reinterpret_cast<uint4*>(&sAh[aRow][aH8])     = rah0;
        *reinterpret_cast<uint4*>(&sAh[aRow][aH8 + 4]) = rah1;
        *reinterpret_cast<uint4*>(&sAl[aRow][aH8])     = ral0;
        *reinterpret_cast<uint4*>(&sAl[aRow][aH8 + 4]) = ral1;
        *reinterpret_cast<uint4*>(&sBh[bKp][bM4]) = rbh;
        *reinterpret_cast<uint4*>(&sBl[bKp][bM4]) = rbl;
        __syncthreads();

        if (kt + 1 < 8) {
            if (aOk) {
                rah0 = *reinterpret_cast<const uint4*>(Agh + (kt + 1) * 16);
                rah1 = *reinterpret_cast<const uint4*>(Agh + (kt + 1) * 16 + 4);
                ral0 = *reinterpret_cast<const uint4*>(Agl + (kt + 1) * 16);
                ral1 = *reinterpret_cast<const uint4*>(Agl + (kt + 1) * 16 + 4);
            }
            rbh = *reinterpret_cast<const uint4*>(Bgh + (size_t)(kt + 1) * 16 * M);
            rbl = *reinterpret_cast<const uint4*>(Bgl + (size_t)(kt + 1) * 16 * M);
        }

        #pragma unroll
        for (int k0 = 0; k0 < 2; k0++) {
            unsigned ah[2][4], al[2][4], bh[4][2], bl[4][2];
            #pragma unroll
            for (int mt = 0; mt < 2; mt++) {
                int r = warpM * 32 + mt * 16 + g;
                ah[mt][0] = sAh[r][k0 * 8 + tg];     ah[mt][1] = sAh[r + 8][k0 * 8 + tg];
                ah[mt][2] = sAh[r][k0 * 8 + tg + 4]; ah[mt][3] = sAh[r + 8][k0 * 8 + tg + 4];
                al[mt][0] = sAl[r][k0 * 8 + tg];     al[mt][1] = sAl[r + 8][k0 * 8 + tg];
                al[mt][2] = sAl[r][k0 * 8 + tg + 4]; al[mt][3] = sAl[r + 8][k0 * 8 + tg + 4];
            }
            #pragma unroll
            for (int nt = 0; nt < 4; nt++) {
                int col = warpN * 32 + nt * 8 + g;
                bh[nt][0] = sBh[k0 * 8 + tg][col]; bh[nt][1] = sBh[k0 * 8 + tg + 4][col];
                bl[nt][0] = sBl[k0 * 8 + tg][col]; bl[nt][1] = sBl[k0 * 8 + tg + 4][col];
            }
            #pragma unroll
            for (int mt = 0; mt < 2; mt++)
                #pragma unroll
                for (int nt = 0; nt < 4; nt++) {
                    mma16(c[mt][nt], ah[mt], bh[nt]);
                    mma16(c[mt][nt], ah[mt], bl[nt]);
                    mma16(c[mt][nt], al[mt], bh[nt]);
                }
        }
        __syncthreads();
    }

    #pragma unroll
    for (int mt = 0; mt < 2; mt++) {
        int r0 = rowBase + warpM * 32 + mt * 16 + g;
        #pragma unroll
        for (int nt = 0; nt < 4; nt++) {
            int col = colBase + warpN * 32 + nt * 8 + tg * 2;
            if (r0 < N)
                *reinterpret_cast<float2*>(&C[(size_t)r0 * M + col]) = make_float2(c[mt][nt][0], c[mt][nt][1]);
            if (r0 + 8 < N)
                *reinterpret_cast<float2*>(&C[(size_t)(r0 + 8) * M + col]) = make_float2(c[mt][nt][2], c[mt][nt][3]);
        }
    }
}

// ============================================================
// Aggregation: warp per dst node, no-max softmax, 2-edge unroll.
// SPLIT: write bf16 hi/lo packed (next layer's A). Else fp32 out.
// ============================================================
template <int H, int SPLIT>
__global__ void agg_kernel(const float* __restrict__ hs, const float* __restrict__ bias,
                           float* __restrict__ out, unsigned* __restrict__ ohi,
                           unsigned* __restrict__ olo, int n, int doRelu) {
    const int HC = H * 64;
    const int R  = HC / 32;
    int w = (blockIdx.x * blockDim.x + threadIdx.x) >> 5;
    int lane = threadIdx.x & 31;
    if (w >= n) return;
    int h = (lane * R) / 64;
    float ald_h = g_ald[w * H + h];

    float acc[R];
    #pragma unroll
    for (int r = 0; r < R; r++) acc[r] = 0.f;
    float den = 0.f;

    int beg = g_rowptr[w], end = g_rowptr[w + 1];
    int e = beg;
    for (; e + 1 < end; e += 2) {
        int s0 = g_ssrc[e];
        int s1 = g_ssrc[e + 1];
        float a0 = g_als[s0 * H + h];
        float a1 = g_als[s1 * H + h];
        float ev0 = a0 + ald_h; ev0 = ev0 > 0.f ? ev0 : 0.2f * ev0;
        float ev1 = a1 + ald_h; ev1 = ev1 > 0.f ? ev1 : 0.2f * ev1;
        float w0 = __expf(ev0), w1 = __expf(ev1);
        den += w0 + w1;
        const float* hp0 = &hs[(size_t)s0 * HC + lane * R];
        const float* hp1 = &hs[(size_t)s1 * HC + lane * R];
        if (R == 8) {
            float4 x0 = *reinterpret_cast<const float4*>(hp0);
            float4 x1 = *reinterpret_cast<const float4*>(hp0 + 4);
            float4 y0 = *reinterpret_cast<const float4*>(hp1);
            float4 y1 = *reinterpret_cast<const float4*>(hp1 + 4);
            acc[0] += w0 * x0.x + w1 * y0.x; acc[1] += w0 * x0.y + w1 * y0.y;
            acc[2] += w0 * x0.z + w1 * y0.z; acc[3] += w0 * x0.w + w1 * y0.w;
            acc[4] += w0 * x1.x + w1 * y1.x; acc[5] += w0 * x1.y + w1 * y1.y;
            acc[6] += w0 * x1.z + w1 * y1.z; acc[7] += w0 * x1.w + w1 * y1.w;
        } else {
            float2 x = *reinterpret_cast<const float2*>(hp0);
            float2 y = *reinterpret_cast<const float2*>(hp1);
            acc[0] += w0 * x.x + w1 * y.x;
            acc[1] += w0 * x.y + w1 * y.y;
        }
    }
    if (e < end) {
        int s = g_ssrc[e];
        float ev = g_als[s * H + h] + ald_h;
        ev = ev > 0.f ? ev : 0.2f * ev;
        float wg = __expf(ev);
        den += wg;
        const float* hp = &hs[(size_t)s * HC + lane * R];
        if (R == 8) {
            float4 v0 = *reinterpret_cast<const float4*>(hp);
            float4 v1 = *reinterpret_cast<const float4*>(hp + 4);
            acc[0] += wg * v0.x; acc[1] += wg * v0.y;
            acc[2] += wg * v0.z; acc[3] += wg * v0.w;
            acc[4] += wg * v1.x; acc[5] += wg * v1.y;
            acc[6] += wg * v1.z; acc[7] += wg * v1.w;
        } else {
            float2 v = *reinterpret_cast<const float2*>(hp);
            acc[0] += wg * v.x;
            acc[1] += wg * v.y;
        }
    }
    float invd = (end > beg) ? 1.f / den : 0.f;
    float o[R];
    #pragma unroll
    for (int r = 0; r < R; r++) {
        float v = acc[r] * invd + bias[lane * R + r];
        if (doRelu) v = fmaxf(v, 0.f);
        o[r] = v;
    }
    if (SPLIT) {   // R == 8 path
        uint4 vh, vl;
        split2(o[0], o[1], vh.x, vl.x);
        split2(o[2], o[3], vh.y, vl.y);
        split2(o[4], o[5], vh.z, vl.z);
        split2(o[6], o[7], vh.w, vl.w);
        *reinterpret_cast<uint4*>(&ohi[(size_t)w * 128 + lane * 4]) = vh;
        *reinterpret_cast<uint4*>(&olo[(size_t)w * 128 + lane * 4]) = vl;
    } else {
        #pragma unroll
        for (int r = 0; r < R; r++)
            out[(size_t)w * HC + lane * R + r] = o[r];
    }
}

// ============================================================
// Launch
// ============================================================
extern "C" void kernel_launch(void* const* d_in, const int* in_sizes, int n_in,
                              void* d_out, int out_size) {
    const float* x  = (const float*)d_in[0];
    const int*   ei = (const int*)d_in[1];
    int n = in_sizes[0] / 256;
    int E = in_sizes[1] / 2;
    const int* src = ei;
    const int* dst = ei + E;

    const float *Ws[4], *Wd[4], *as_[4], *ad_[4], *bb[4];
    for (int l = 0; l < 4; l++) {
        Ws[l]  = (const float*)d_in[2 + 5 * l + 0];
        Wd[l]  = (const float*)d_in[2 + 5 * l + 1];
        as_[l] = (const float*)d_in[2 + 5 * l + 2];
        ad_[l] = (const float*)d_in[2 + 5 * l + 3];
        bb[l]  = (const float*)d_in[2 + 5 * l + 4];
    }

    void *p_hs, *p_cnt, *p_at, *p_whi, *p_wlo;
    void *p_b0h, *p_b0l, *p_b1h, *p_b1l;
    cudaGetSymbolAddress(&p_hs, g_hs);
    cudaGetSymbolAddress(&p_cnt, g_cnt);
    cudaGetSymbolAddress(&p_at, g_attnAll);
    cudaGetSymbolAddress(&p_whi, g_Whi);
    cudaGetSymbolAddress(&p_wlo, g_Wlo);
    cudaGetSymbolAddress(&p_b0h, g_b0hi);
    cudaGetSymbolAddress(&p_b0l, g_b0lo);
    cudaGetSymbolAddress(&p_b1h, g_b1hi);
    cudaGetSymbolAddress(&p_b1l, g_b1lo);
    float* hs = (float*)p_hs;
    const float* at = (const float*)p_at;
    unsigned* whi = (unsigned*)p_whi;
    unsigned* wlo = (unsigned*)p_wlo;
    unsigned* bufh[2] = {(unsigned*)p_b0h, (unsigned*)p_b1h};
    unsigned* bufl[2] = {(unsigned*)p_b0l, (unsigned*)p_b1l};

    // ---- sort edges by dst ----
    int nb = (n + 1023) / 1024;
    cudaMemsetAsync(p_cnt, 0, (size_t)(n + 1) * sizeof(int));
    hist_kernel<<<(E + 255) / 256, 256>>>(dst, E);
    scanA_kernel<<<nb, 1024>>>(n);
    scanB_kernel<<<1, 64>>>(nb);
    scanC_kernel<<<nb, 1024>>>(n, E);
    scatter_kernel<<<(E + 255) / 256, 256>>>(src, dst, E);

    // ---- one-shot folds / pre-splits ----
    attn_fold_kernel<<<1024, 256>>>(Ws[0], Ws[1], Ws[2], Ws[3],
                                    Wd[0], Wd[1], Wd[2], Wd[3],
                                    as_[0], as_[1], as_[2], as_[3],
                                    ad_[0], ad_[1], ad_[2], ad_[3]);
    presplit_W_kernel<<<(106496 + 255) / 256, 256>>>(Ws[0], Ws[1], Ws[2], Ws[3]);
    presplit_x_kernel<<<(n * 128 + 255) / 256, 256>>>(x, n * 128);

    int warpBlocks = (n * 32 + 255) / 256;
    int gx = (n + 127) / 128;
    dim3 gGrid(gx, 5);     // y 0..3 gemm (M=256), y=4 attn
    dim3 gGrid4(gx, 2);    // y 0 gemm (M=64),  y=1 attn

    // layer buffers: A for layer l -> buf[l&1]; agg out -> buf[(l+1)&1]
    for (int l = 0; l < 3; l++) {
        int ia = l & 1, io = (l + 1) & 1;
        gemm_attn_kernel<<<gGrid, 256>>>(bufh[ia], bufl[ia],
                                         whi + l * 32768, wlo + l * 32768,
                                         at + l * 2048, hs, n, 256, 4);
        agg_kernel<4, 1><<<warpBlocks, 256>>>(hs, bb[l], nullptr,
                                              bufh[io], bufl[io], n, 1);
    }
    gemm_attn_kernel<<<gGrid4, 256>>>(bufh[1], bufl[1],
                                      whi + 98304, wlo + 98304,
                                      at + 3 * 2048, hs, n, 64, 1);
    agg_kernel<1, 0><<<warpBlocks, 256>>>(hs, bb[3], (float*)d_out,
                                          nullptr, nullptr, n, 0);
}

// round 11
// speedup vs baseline: 1.8018x; 1.0131x over previous
#include <cuda_runtime.h>
#include <cuda_bf16.h>

#define NMAX 50000
#define EMAX 500000

// ---- static device scratch (allocation-free contract) ----
__device__ float    g_hs[(size_t)NMAX * 256];     // per-layer source projections (fp32)
__device__ unsigned g_b0hi[(size_t)NMAX * 128];   // feature buffer 0, bf16 hi (k-pair packed)
__device__ unsigned g_b0lo[(size_t)NMAX * 128];
__device__ unsigned g_b1hi[(size_t)NMAX * 128];   // feature buffer 1
__device__ unsigned g_b1lo[(size_t)NMAX * 128];
__device__ unsigned g_Whi[106496];                // weights bf16 hi, k-major [kp][m], all layers
__device__ unsigned g_Wlo[106496];
__device__ float    g_als[NMAX * 4];
__device__ float    g_ald[NMAX * 4];
__device__ float    g_attnAll[4 * 2048];          // folded [Ws@a_src^T | Wd@a_dst^T]
__device__ int      g_cnt[NMAX + 1];
__device__ int      g_cur[NMAX + 1];
__device__ int      g_rowptr[NMAX + 1];
__device__ int      g_bsum[64];
__device__ int      g_ssrc[EMAX];

// ============================================================
// helpers
// ============================================================
__device__ __forceinline__ unsigned pack2(__nv_bfloat16 e, __nv_bfloat16 o) {
    __nv_bfloat162 t = __halves2bfloat162(e, o);
    return *reinterpret_cast<unsigned*>(&t);
}
__device__ __forceinline__ void split2(float a, float b, unsigned& hi, unsigned& lo) {
    __nv_bfloat16 ha = __float2bfloat16_rn(a);
    __nv_bfloat16 hb = __float2bfloat16_rn(b);
    hi = pack2(ha, hb);
    lo = pack2(__float2bfloat16_rn(a - __bfloat162float(ha)),
               __float2bfloat16_rn(b - __bfloat162float(hb)));
}
__device__ __forceinline__ float2 unpack2(unsigned hi, unsigned lo) {
    __nv_bfloat162 h = *reinterpret_cast<__nv_bfloat162*>(&hi);
    __nv_bfloat162 l = *reinterpret_cast<__nv_bfloat162*>(&lo);
    return make_float2(__bfloat162float(h.x) + __bfloat162float(l.x),
                       __bfloat162float(h.y) + __bfloat162float(l.y));
}
__device__ __forceinline__ void mma16(float* c, const unsigned* a, const unsigned* b) {
    asm volatile(
        "mma.sync.aligned.m16n8k16.row.col.f32.bf16.bf16.f32 "
        "{%0,%1,%2,%3}, {%4,%5,%6,%7}, {%8,%9}, {%0,%1,%2,%3};\n"
        : "+f"(c[0]), "+f"(c[1]), "+f"(c[2]), "+f"(c[3])
        : "r"(a[0]), "r"(a[1]), "r"(a[2]), "r"(a[3]), "r"(b[0]), "r"(b[1]));
}

// ============================================================
// Edge sort: counting sort by dst
// ============================================================
__global__ void hist_kernel(const int* __restrict__ dst, int E) {
    int e = blockIdx.x * blockDim.x + threadIdx.x;
    if (e < E) atomicAdd(&g_cnt[dst[e]], 1);
}
__global__ void scanA_kernel(int n) {
    __shared__ int sh[1024];
    int tid = threadIdx.x;
    int i = blockIdx.x * 1024 + tid;
    int v = (i < n) ? g_cnt[i] : 0;
    sh[tid] = v;
    __syncthreads();
    #pragma unroll
    for (int off = 1; off < 1024; off <<= 1) {
        int t = (tid >= off) ? sh[tid - off] : 0;
        __syncthreads();
        sh[tid] += t;
        __syncthreads();
    }
    if (i < n) g_rowptr[i] = sh[tid] - v;
    if (tid == 1023) g_bsum[blockIdx.x] = sh[1023];
}
__global__ void scanB_kernel(int nb) {
    __shared__ int sh[64];
    int tid = threadIdx.x;
    int v = (tid < nb) ? g_bsum[tid] : 0;
    sh[tid] = v;
    __syncthreads();
    #pragma unroll
    for (int off = 1; off < 64; off <<= 1) {
        int t = (tid >= off) ? sh[tid - off] : 0;
        __syncthreads();
        sh[tid] += t;
        __syncthreads();
    }
    if (tid < nb) g_bsum[tid] = sh[tid] - v;
}
__global__ void scanC_kernel(int n, int E) {
    int i = blockIdx.x * 1024 + threadIdx.x;
    if (i < n) {
        int r = g_rowptr[i] + g_bsum[blockIdx.x];
        g_rowptr[i] = r;
        g_cur[i] = r;
    }
    if (i == n) g_rowptr[n] = E;
}
__global__ void scatter_kernel(const int* __restrict__ src, const int* __restrict__ dst, int E) {
    int e = blockIdx.x * blockDim.x + threadIdx.x;
    if (e < E) {
        int d = dst[e];
        int p = atomicAdd(&g_cur[d], 1);
        g_ssrc[p] = src[e];
    }
}

// ============================================================
// Fold attention vectors (fp32, tiny)
// ============================================================
__global__ void attn_fold_kernel(const float* __restrict__ Ws0, const float* __restrict__ Ws1,
                                 const float* __restrict__ Ws2, const float* __restrict__ Ws3,
                                 const float* __restrict__ Wd0, const float* __restrict__ Wd1,
                                 const float* __restrict__ Wd2, const float* __restrict__ Wd3,
                                 const float* __restrict__ s0, const float* __restrict__ s1,
                                 const float* __restrict__ s2, const float* __restrict__ s3,
                                 const float* __restrict__ d0, const float* __restrict__ d1,
                                 const float* __restrict__ d2, const float* __restrict__ d3) {
    int w = blockIdx.x * (blockDim.x >> 5) + (threadIdx.x >> 5);
    int lane = threadIdx.x & 31;
    if (w >= 8192) return;
    int l = w >> 11;
    int rem = w & 2047;
    int c = rem >> 8;
    int k = rem & 255;
    int H = (l == 3) ? 1 : 4;
    int side = c >> 2;
    int h = c & 3;
    float val = 0.f;
    if (h < H) {
        const float* W;
        const float* a;
        if (side == 0) {
            W = (l == 0) ? Ws0 : (l == 1) ? Ws1 : (l == 2) ? Ws2 : Ws3;
            a = (l == 0) ? s0 : (l == 1) ? s1 : (l == 2) ? s2 : s3;
        } else {
            W = (l == 0) ? Wd0 : (l == 1) ? Wd1 : (l == 2) ? Wd2 : Wd3;
            a = (l == 0) ? d0 : (l == 1) ? d1 : (l == 2) ? d2 : d3;
        }
        int HC = H * 64;
        const float* wr = W + (size_t)k * HC + h * 64;
        const float* ar = a + h * 64;
        float sacc = wr[lane] * ar[lane] + wr[lane + 32] * ar[lane + 32];
        #pragma unroll
        for (int off = 16; off > 0; off >>= 1)
            sacc += __shfl_xor_sync(0xffffffffu, sacc, off);
        val = sacc;
    }
    if (lane == 0) g_attnAll[l * 2048 + c * 256 + k] = val;
}

// ============================================================
// Pre-split x (layer-1 features) into bf16 hi/lo packed (k-pairs).
// ============================================================
__global__ void presplit_x_kernel(const float* __restrict__ x, int total) {
    int i = blockIdx.x * blockDim.x + threadIdx.x;
    if (i >= total) return;
    float2 v = reinterpret_cast<const float2*>(x)[i];
    unsigned hi, lo;
    split2(v.x, v.y, hi, lo);
    g_b0hi[i] = hi;
    g_b0lo[i] = lo;
}

// ============================================================
// Pre-split all Ws weights into k-major packed hi/lo: out[kp*M + m].
// ============================================================
__global__ void presplit_W_kernel(const float* __restrict__ W0, const float* __restrict__ W1,
                                  const float* __restrict__ W2, const float* __restrict__ W3) {
    int t = blockIdx.x * blockDim.x + threadIdx.x;
    if (t >= 106496) return;
    const float* W;
    int M, kp, m, base;
    if (t < 98304) {
        int l = t >> 15;
        int within = t & 32767;
        M = 256; kp = within >> 8; m = within & 255;
        base = l << 15;
        W = (l == 0) ? W0 : (l == 1) ? W1 : W2;
    } else {
        int within = t - 98304;
        M = 64; kp = within >> 6; m = within & 63;
        base = 98304;
        W = W3;
    }
    float a = W[(size_t)(2 * kp) * M + m];
    float b = W[(size_t)(2 * kp + 1) * M + m];
    unsigned hi, lo;
    split2(a, b, hi, lo);
    g_Whi[base + kp * M + m] = hi;
    g_Wlo[base + kp * M + m] = lo;
}

// ============================================================
// Fused GEMM (pre-split bf16, 3-term) + attention-logit plane.
// BM=128, BK=32, 256 threads, double-buffered DYNAMIC smem
// (1 sync/tile), 2 CTAs/SM.  Grid y: last plane = attn.
// ============================================================
#define ASTR 20
#define BSTR 72
// dynamic smem layout (uint32 units)
#define OFF_AH 0
#define OFF_AL (2 * 128 * ASTR)
#define OFF_BH (OFF_AL + 2 * 128 * ASTR)
#define OFF_BL (OFF_BH + 2 * 16 * BSTR)
#define SMEM_UINTS (OFF_BL + 2 * 16 * BSTR)
#define SMEM_BYTES (SMEM_UINTS * 4)

__global__ __launch_bounds__(256, 2)
void gemm_attn_kernel(const unsigned* __restrict__ Ahi, const unsigned* __restrict__ Alo,
                      const unsigned* __restrict__ Bhi, const unsigned* __restrict__ Blo,
                      const float* __restrict__ P, float* __restrict__ C,
                      int N, int M, int H) {
    const int tid = threadIdx.x;
    const int lane = tid & 31;
    const int wid = tid >> 5;
    const int rowBase = blockIdx.x * 128;

    // ---------------- attn plane ----------------
    if (blockIdx.y == gridDim.y - 1) {
        float pk[8][8];
        #pragma unroll
        for (int u = 0; u < 8; u++)
            #pragma unroll
            for (int c = 0; c < 8; c++)
                pk[u][c] = P[c * 256 + lane * 8 + u];

        for (int i = 0; i < 16; i++) {
            int node = rowBase + wid * 16 + i;
            if (node >= N) break;
            uint4 vh = *reinterpret_cast<const uint4*>(&Ahi[(size_t)node * 128 + lane * 4]);
            uint4 vl = *reinterpret_cast<const uint4*>(&Alo[(size_t)node * 128 + lane * 4]);
            float f[8];
            { float2 t = unpack2(vh.x, vl.x); f[0] = t.x; f[1] = t.y; }
            { float2 t = unpack2(vh.y, vl.y); f[2] = t.x; f[3] = t.y; }
            { float2 t = unpack2(vh.z, vl.z); f[4] = t.x; f[5] = t.y; }
            { float2 t = unpack2(vh.w, vl.w); f[6] = t.x; f[7] = t.y; }
            float acc[8] = {};
            #pragma unroll
            for (int u = 0; u < 8; u++)
                #pragma unroll
                for (int c = 0; c < 8; c++)
                    acc[c] += f[u] * pk[u][c];
            #pragma unroll
            for (int c = 0; c < 8; c++) {
                float v = acc[c];
                #pragma unroll
                for (int off = 16; off > 0; off >>= 1)
                    v += __shfl_xor_sync(0xffffffffu, v, off);
                acc[c] = v;
            }
            if (lane == 0) {
                for (int c = 0; c < H; c++) g_als[node * H + c] = acc[c];
                for (int c = 0; c < H; c++) g_ald[node * H + c] = acc[4 + c];
            }
        }
        return;
    }

    // ---------------- gemm plane ----------------
    extern __shared__ unsigned dynsmem[];
    unsigned* sAh = dynsmem + OFF_AH;   // [2][128][ASTR]
    unsigned* sAl = dynsmem + OFF_AL;
    unsigned* sBh = dynsmem + OFF_BH;   // [2][16][BSTR]
    unsigned* sBl = dynsmem + OFF_BL;

    const int warpM = wid & 3;
    const int warpN = wid >> 2;
    const int g  = lane >> 2;
    const int tg = lane & 3;
    const int colBase = blockIdx.y * 64;

    const int aRow = tid >> 1;
    const int aH8  = (tid & 1) << 3;
    const bool aOk = (rowBase + aRow) < N;
    const unsigned* Agh = Ahi + (size_t)(rowBase + aRow) * 128 + aH8;
    const unsigned* Agl = Alo + (size_t)(rowBase + aRow) * 128 + aH8;

    const int bKp = tid >> 4;
    const int bM4 = (tid & 15) << 2;
    const unsigned* Bgh = Bhi + (size_t)bKp * M + colBase + bM4;
    const unsigned* Bgl = Blo + (size_t)bKp * M + colBase + bM4;

    float c[2][4][4] = {};

    uint4 rah0, rah1, ral0, ral1, rbh, rbl;
    const uint4 Z = make_uint4(0, 0, 0, 0);
    if (aOk) {
        rah0 = *reinterpret_cast<const uint4*>(Agh);
        rah1 = *reinterpret_cast<const uint4*>(Agh + 4);
        ral0 = *reinterpret_cast<const uint4*>(Agl);
        ral1 = *reinterpret_cast<const uint4*>(Agl + 4);
    } else { rah0 = rah1 = ral0 = ral1 = Z; }
    rbh = *reinterpret_cast<const uint4*>(Bgh);
    rbl = *reinterpret_cast<const uint4*>(Bgl);

    const int aIdx = aRow * ASTR + aH8;          // within one A buffer
    const int bIdx = bKp * BSTR + bM4;           // within one B buffer

    // store tile 0 into buffer 0
    *reinterpret_cast<uint4*>(&sAh[aIdx])     = rah0;
    *reinterpret_cast<uint4*>(&sAh[aIdx + 4]) = rah1;
    *reinterpret_cast<uint4*>(&sAl[aIdx])     = ral0;
    *reinterpret_cast<uint4*>(&sAl[aIdx + 4]) = ral1;
    *reinterpret_cast<uint4*>(&sBh[bIdx]) = rbh;
    *reinterpret_cast<uint4*>(&sBl[bIdx]) = rbl;
    __syncthreads();

    for (int kt = 0; kt < 8; kt++) {
        const int curA = (kt & 1) * 128 * ASTR;
        const int curB = (kt & 1) * 16 * BSTR;
        // issue next tile's global loads
        if (kt + 1 < 8) {
            if (aOk) {
                rah0 = *reinterpret_cast<const uint4*>(Agh + (kt + 1) * 16);
                rah1 = *reinterpret_cast<const uint4*>(Agh + (kt + 1) * 16 + 4);
                ral0 = *reinterpret_cast<const uint4*>(Agl + (kt + 1) * 16);
                ral1 = *reinterpret_cast<const uint4*>(Agl + (kt + 1) * 16 + 4);
            }
            rbh = *reinterpret_cast<const uint4*>(Bgh + (size_t)(kt + 1) * 16 * M);
            rbl = *reinterpret_cast<const uint4*>(Bgl + (size_t)(kt + 1) * 16 * M);
        }

        #pragma unroll
        for (int k0 = 0; k0 < 2; k0++) {
            unsigned ah[2][4], al[2][4], bh[4][2], bl[4][2];
            #pragma unroll
            for (int mt = 0; mt < 2; mt++) {
                int r = warpM * 32 + mt * 16 + g;
                const unsigned* pAh = &sAh[curA + r * ASTR + k0 * 8 + tg];
                const unsigned* pAl = &sAl[curA + r * ASTR + k0 * 8 + tg];
                ah[mt][0] = pAh[0];             ah[mt][1] = pAh[8 * ASTR];
                ah[mt][2] = pAh[4];             ah[mt][3] = pAh[8 * ASTR + 4];
                al[mt][0] = pAl[0];             al[mt][1] = pAl[8 * ASTR];
                al[mt][2] = pAl[4];             al[mt][3] = pAl[8 * ASTR + 4];
            }
            #pragma unroll
            for (int nt = 0; nt < 4; nt++) {
                int col = warpN * 32 + nt * 8 + g;
                bh[nt][0] = sBh[curB + (k0 * 8 + tg) * BSTR + col];
                bh[nt][1] = sBh[curB + (k0 * 8 + tg + 4) * BSTR + col];
                bl[nt][0] = sBl[curB + (k0 * 8 + tg) * BSTR + col];
                bl[nt][1] = sBl[curB + (k0 * 8 + tg + 4) * BSTR + col];
            }
            #pragma unroll
            for (int mt = 0; mt < 2; mt++)
                #pragma unroll
                for (int nt = 0; nt < 4; nt++) {
                    mma16(c[mt][nt], ah[mt], bh[nt]);
                    mma16(c[mt][nt], ah[mt], bl[nt]);
                    mma16(c[mt][nt], al[mt], bh[nt]);
                }
        }

        if (kt + 1 < 8) {
            const int nxtA = ((kt + 1) & 1) * 128 * ASTR;
            const int nxtB = ((kt + 1) & 1) * 16 * BSTR;
            *reinterpret_cast<uint4*>(&sAh[nxtA + aIdx])     = rah0;
            *reinterpret_cast<uint4*>(&sAh[nxtA + aIdx + 4]) = rah1;
            *reinterpret_cast<uint4*>(&sAl[nxtA + aIdx])     = ral0;
            *reinterpret_cast<uint4*>(&sAl[nxtA + aIdx + 4]) = ral1;
            *reinterpret_cast<uint4*>(&sBh[nxtB + bIdx]) = rbh;
            *reinterpret_cast<uint4*>(&sBl[nxtB + bIdx]) = rbl;
            __syncthreads();
        }
    }

    #pragma unroll
    for (int mt = 0; mt < 2; mt++) {
        int r0 = rowBase + warpM * 32 + mt * 16 + g;
        #pragma unroll
        for (int nt = 0; nt < 4; nt++) {
            int col = colBase + warpN * 32 + nt * 8 + tg * 2;
            if (r0 < N)
                *reinterpret_cast<float2*>(&C[(size_t)r0 * M + col]) = make_float2(c[mt][nt][0], c[mt][nt][1]);
            if (r0 + 8 < N)
                *reinterpret_cast<float2*>(&C[(size_t)(r0 + 8) * M + col]) = make_float2(c[mt][nt][2], c[mt][nt][3]);
        }
    }
}

// ============================================================
// Aggregation: warp per dst node, no-max softmax, 4-edge unroll.
// SPLIT: write bf16 hi/lo packed (next layer's A). Else fp32 out.
// ============================================================
template <int H, int SPLIT>
__global__ void agg_kernel(const float* __restrict__ hs, const float* __restrict__ bias,
                           float* __restrict__ out, unsigned* __restrict__ ohi,
                           unsigned* __restrict__ olo, int n, int doRelu) {
    const int HC = H * 64;
    const int R  = HC / 32;
    int w = (blockIdx.x * blockDim.x + threadIdx.x) >> 5;
    int lane = threadIdx.x & 31;
    if (w >= n) return;
    int h = (lane * R) / 64;
    float ald_h = g_ald[w * H + h];

    float acc[R];
    #pragma unroll
    for (int r = 0; r < R; r++) acc[r] = 0.f;
    float den = 0.f;

    int beg = g_rowptr[w], end = g_rowptr[w + 1];
    int e = beg;
    for (; e + 3 < end; e += 4) {
        int s0 = g_ssrc[e];
        int s1 = g_ssrc[e + 1];
        int s2 = g_ssrc[e + 2];
        int s3 = g_ssrc[e + 3];
        float a0 = g_als[s0 * H + h];
        float a1 = g_als[s1 * H + h];
        float a2 = g_als[s2 * H + h];
        float a3 = g_als[s3 * H + h];
        float ev0 = a0 + ald_h; ev0 = ev0 > 0.f ? ev0 : 0.2f * ev0;
        float ev1 = a1 + ald_h; ev1 = ev1 > 0.f ? ev1 : 0.2f * ev1;
        float ev2 = a2 + ald_h; ev2 = ev2 > 0.f ? ev2 : 0.2f * ev2;
        float ev3 = a3 + ald_h; ev3 = ev3 > 0.f ? ev3 : 0.2f * ev3;
        float w0 = __expf(ev0), w1 = __expf(ev1), w2 = __expf(ev2), w3 = __expf(ev3);
        den += (w0 + w1) + (w2 + w3);
        const float* hp0 = &hs[(size_t)s0 * HC + lane * R];
        const float* hp1 = &hs[(size_t)s1 * HC + lane * R];
        const float* hp2 = &hs[(size_t)s2 * HC + lane * R];
        const float* hp3 = &hs[(size_t)s3 * HC + lane * R];
        if (R == 8) {
            float4 x0 = *reinterpret_cast<const float4*>(hp0);
            float4 x1 = *reinterpret_cast<const float4*>(hp0 + 4);
            float4 y0 = *reinterpret_cast<const float4*>(hp1);
            float4 y1 = *reinterpret_cast<const float4*>(hp1 + 4);
            float4 z0 = *reinterpret_cast<const float4*>(hp2);
            float4 z1 = *reinterpret_cast<const float4*>(hp2 + 4);
            float4 u0 = *reinterpret_cast<const float4*>(hp3);
            float4 u1 = *reinterpret_cast<const float4*>(hp3 + 4);
            acc[0] += w0 * x0.x + w1 * y0.x + w2 * z0.x + w3 * u0.x;
            acc[1] += w0 * x0.y + w1 * y0.y + w2 * z0.y + w3 * u0.y;
            acc[2] += w0 * x0.z + w1 * y0.z + w2 * z0.z + w3 * u0.z;
            acc[3] += w0 * x0.w + w1 * y0.w + w2 * z0.w + w3 * u0.w;
            acc[4] += w0 * x1.x + w1 * y1.x + w2 * z1.x + w3 * u1.x;
            acc[5] += w0 * x1.y + w1 * y1.y + w2 * z1.y + w3 * u1.y;
            acc[6] += w0 * x1.z + w1 * y1.z + w2 * z1.z + w3 * u1.z;
            acc[7] += w0 * x1.w + w1 * y1.w + w2 * z1.w + w3 * u1.w;
        } else {
            float2 x = *reinterpret_cast<const float2*>(hp0);
            float2 y = *reinterpret_cast<const float2*>(hp1);
            float2 z = *reinterpret_cast<const float2*>(hp2);
            float2 u = *reinterpret_cast<const float2*>(hp3);
            acc[0] += w0 * x.x + w1 * y.x + w2 * z.x + w3 * u.x;
            acc[1] += w0 * x.y + w1 * y.y + w2 * z.y + w3 * u.y;
        }
    }
    for (; e < end; e++) {
        int s = g_ssrc[e];
        float ev = g_als[s * H + h] + ald_h;
        ev = ev > 0.f ? ev : 0.2f * ev;
        float wg = __expf(ev);
        den += wg;
        const float* hp = &hs[(size_t)s * HC + lane * R];
        if (R == 8) {
            float4 v0 = *reinterpret_cast<const float4*>(hp);
            float4 v1 = *reinterpret_cast<const float4*>(hp + 4);
            acc[0] += wg * v0.x; acc[1] += wg * v0.y;
            acc[2] += wg * v0.z; acc[3] += wg * v0.w;
            acc[4] += wg * v1.x; acc[5] += wg * v1.y;
            acc[6] += wg * v1.z; acc[7] += wg * v1.w;
        } else {
            float2 v = *reinterpret_cast<const float2*>(hp);
            acc[0] += wg * v.x;
            acc[1] += wg * v.y;
        }
    }
    float invd = (end > beg) ? 1.f / den : 0.f;
    float o[R];
    #pragma unroll
    for (int r = 0; r < R; r++) {
        float v = acc[r] * invd + bias[lane * R + r];
        if (doRelu) v = fmaxf(v, 0.f);
        o[r] = v;
    }
    if (SPLIT) {
        uint4 vh, vl;
        split2(o[0], o[1], vh.x, vl.x);
        split2(o[2], o[3], vh.y, vl.y);
        split2(o[4], o[5], vh.z, vl.z);
        split2(o[6], o[7], vh.w, vl.w);
        *reinterpret_cast<uint4*>(&ohi[(size_t)w * 128 + lane * 4]) = vh;
        *reinterpret_cast<uint4*>(&olo[(size_t)w * 128 + lane * 4]) = vl;
    } else {
        #pragma unroll
        for (int r = 0; r < R; r++)
            out[(size_t)w * HC + lane * R + r] = o[r];
    }
}

// ============================================================
// Launch
// ============================================================
extern "C" void kernel_launch(void* const* d_in, const int* in_sizes, int n_in,
                              void* d_out, int out_size) {
    const float* x  = (const float*)d_in[0];
    const int*   ei = (const int*)d_in[1];
    int n = in_sizes[0] / 256;
    int E = in_sizes[1] / 2;
    const int* src = ei;
    const int* dst = ei + E;

    const float *Ws[4], *Wd[4], *as_[4], *ad_[4], *bb[4];
    for (int l = 0; l < 4; l++) {
        Ws[l]  = (const float*)d_in[2 + 5 * l + 0];
        Wd[l]  = (const float*)d_in[2 + 5 * l + 1];
        as_[l] = (const float*)d_in[2 + 5 * l + 2];
        ad_[l] = (const float*)d_in[2 + 5 * l + 3];
        bb[l]  = (const float*)d_in[2 + 5 * l + 4];
    }

    void *p_hs, *p_cnt, *p_at, *p_whi, *p_wlo;
    void *p_b0h, *p_b0l, *p_b1h, *p_b1l;
    cudaGetSymbolAddress(&p_hs, g_hs);
    cudaGetSymbolAddress(&p_cnt, g_cnt);
    cudaGetSymbolAddress(&p_at, g_attnAll);
    cudaGetSymbolAddress(&p_whi, g_Whi);
    cudaGetSymbolAddress(&p_wlo, g_Wlo);
    cudaGetSymbolAddress(&p_b0h, g_b0hi);
    cudaGetSymbolAddress(&p_b0l, g_b0lo);
    cudaGetSymbolAddress(&p_b1h, g_b1hi);
    cudaGetSymbolAddress(&p_b1l, g_b1lo);
    float* hs = (float*)p_hs;
    const float* at = (const float*)p_at;
    unsigned* whi = (unsigned*)p_whi;
    unsigned* wlo = (unsigned*)p_wlo;
    unsigned* bufh[2] = {(unsigned*)p_b0h, (unsigned*)p_b1h};
    unsigned* bufl[2] = {(unsigned*)p_b0l, (unsigned*)p_b1l};

    // opt-in to >48KB dynamic smem (host-side attribute; graph-capture safe)
    cudaFuncSetAttribute(gemm_attn_kernel,
                         cudaFuncAttributeMaxDynamicSharedMemorySize, SMEM_BYTES);

    // ---- sort edges by dst ----
    int nb = (n + 1023) / 1024;
    cudaMemsetAsync(p_cnt, 0, (size_t)(n + 1) * sizeof(int));
    hist_kernel<<<(E + 255) / 256, 256>>>(dst, E);
    scanA_kernel<<<nb, 1024>>>(n);
    scanB_kernel<<<1, 64>>>(nb);
    scanC_kernel<<<nb, 1024>>>(n, E);
    scatter_kernel<<<(E + 255) / 256, 256>>>(src, dst, E);

    // ---- one-shot folds / pre-splits ----
    attn_fold_kernel<<<1024, 256>>>(Ws[0], Ws[1], Ws[2], Ws[3],
                                    Wd[0], Wd[1], Wd[2], Wd[3],
                                    as_[0], as_[1], as_[2], as_[3],
                                    ad_[0], ad_[1], ad_[2], ad_[3]);
    presplit_W_kernel<<<(106496 + 255) / 256, 256>>>(Ws[0], Ws[1], Ws[2], Ws[3]);
    presplit_x_kernel<<<(n * 128 + 255) / 256, 256>>>(x, n * 128);

    int warpBlocks = (n * 32 + 255) / 256;
    int gx = (n + 127) / 128;
    dim3 gGrid(gx, 5);     // y 0..3 gemm (M=256), y=4 attn
    dim3 gGrid4(gx, 2);    // y 0 gemm (M=64),  y=1 attn

    for (int l = 0; l < 3; l++) {
        int ia = l & 1, io = (l + 1) & 1;
        gemm_attn_kernel<<<gGrid, 256, SMEM_BYTES>>>(bufh[ia], bufl[ia],
                                                     whi + l * 32768, wlo + l * 32768,
                                                     at + l * 2048, hs, n, 256, 4);
        agg_kernel<4, 1><<<warpBlocks, 256>>>(hs, bb[l], nullptr,
                                              bufh[io], bufl[io], n, 1);
    }
    gemm_attn_kernel<<<gGrid4, 256, SMEM_BYTES>>>(bufh[1], bufl[1],
                                                  whi + 98304, wlo + 98304,
                                                  at + 3 * 2048, hs, n, 64, 1);
    agg_kernel<1, 0><<<warpBlocks, 256>>>(hs, bb[3], (float*)d_out,
                                          nullptr, nullptr, n, 0);
}

// round 14
// speedup vs baseline: 1.9219x; 1.0667x over previous
#include <cuda_runtime.h>
#include <cuda_bf16.h>
#include <cuda_fp16.h>

#define NMAX 50000
#define EMAX 500000

// ---- static device scratch (allocation-free contract) ----
__device__ unsigned g_hs2[(size_t)NMAX * 128];    // projections, fp16 half2-packed (max M=256)
__device__ unsigned g_b0hi[(size_t)NMAX * 128];   // feature buffer 0, bf16 hi (k-pair packed)
__device__ unsigned g_b0lo[(size_t)NMAX * 128];
__device__ unsigned g_b1hi[(size_t)NMAX * 128];   // feature buffer 1
__device__ unsigned g_b1lo[(size_t)NMAX * 128];
__device__ unsigned g_Whi[106496];                // weights bf16 hi, k-major [kp][m], all layers
__device__ unsigned g_Wlo[106496];
__device__ float    g_alsA[NMAX * 4];             // logit ping buffer
__device__ float    g_aldA[NMAX * 4];
__device__ float    g_alsB[NMAX * 4];             // logit pong buffer
__device__ float    g_aldB[NMAX * 4];
__device__ float    g_attnAll[4 * 2048];          // folded [Ws@a_src^T | Wd@a_dst^T]
__device__ int      g_cnt[NMAX + 1];
__device__ int      g_cur[NMAX + 1];
__device__ int      g_rowptr[NMAX + 1];
__device__ int      g_bsum[64];
__device__ int      g_ssrc[EMAX];

// ============================================================
// helpers
// ============================================================
__device__ __forceinline__ unsigned pack2(__nv_bfloat16 e, __nv_bfloat16 o) {
    __nv_bfloat162 t = __halves2bfloat162(e, o);
    return *reinterpret_cast<unsigned*>(&t);
}
__device__ __forceinline__ void split2(float a, float b, unsigned& hi, unsigned& lo) {
    __nv_bfloat16 ha = __float2bfloat16_rn(a);
    __nv_bfloat16 hb = __float2bfloat16_rn(b);
    hi = pack2(ha, hb);
    lo = pack2(__float2bfloat16_rn(a - __bfloat162float(ha)),
               __float2bfloat16_rn(b - __bfloat162float(hb)));
}
__device__ __forceinline__ void mma16(float* c, const unsigned* a, const unsigned* b) {
    asm volatile(
        "mma.sync.aligned.m16n8k16.row.col.f32.bf16.bf16.f32 "
        "{%0,%1,%2,%3}, {%4,%5,%6,%7}, {%8,%9}, {%0,%1,%2,%3};\n"
        : "+f"(c[0]), "+f"(c[1]), "+f"(c[2]), "+f"(c[3])
        : "r"(a[0]), "r"(a[1]), "r"(a[2]), "r"(a[3]), "r"(b[0]), "r"(b[1]));
}
__device__ __forceinline__ float2 h2f(unsigned u) {
    return __half22float2(*reinterpret_cast<__half2*>(&u));
}

// ============================================================
// Edge sort: counting sort by dst
// ============================================================
__global__ void hist_kernel(const int* __restrict__ dst, int E) {
    int e = blockIdx.x * blockDim.x + threadIdx.x;
    if (e < E) atomicAdd(&g_cnt[dst[e]], 1);
}
__global__ void scanA_kernel(int n) {
    __shared__ int sh[1024];
    int tid = threadIdx.x;
    int i = blockIdx.x * 1024 + tid;
    int v = (i < n) ? g_cnt[i] : 0;
    sh[tid] = v;
    __syncthreads();
    #pragma unroll
    for (int off = 1; off < 1024; off <<= 1) {
        int t = (tid >= off) ? sh[tid - off] : 0;
        __syncthreads();
        sh[tid] += t;
        __syncthreads();
    }
    if (i < n) g_rowptr[i] = sh[tid] - v;
    if (tid == 1023) g_bsum[blockIdx.x] = sh[1023];
}
__global__ void scanB_kernel(int nb) {
    __shared__ int sh[64];
    int tid = threadIdx.x;
    int v = (tid < nb) ? g_bsum[tid] : 0;
    sh[tid] = v;
    __syncthreads();
    #pragma unroll
    for (int off = 1; off < 64; off <<= 1) {
        int t = (tid >= off) ? sh[tid - off] : 0;
        __syncthreads();
        sh[tid] += t;
        __syncthreads();
    }
    if (tid < nb) g_bsum[tid] = sh[tid] - v;
}
__global__ void scanC_kernel(int n, int E) {
    int i = blockIdx.x * 1024 + threadIdx.x;
    if (i < n) {
        int r = g_rowptr[i] + g_bsum[blockIdx.x];
        g_rowptr[i] = r;
        g_cur[i] = r;
    }
    if (i == n) g_rowptr[n] = E;
}
__global__ void scatter_kernel(const int* __restrict__ src, const int* __restrict__ dst, int E) {
    int e = blockIdx.x * blockDim.x + threadIdx.x;
    if (e < E) {
        int d = dst[e];
        int p = atomicAdd(&g_cur[d], 1);
        g_ssrc[p] = src[e];
    }
}

// ============================================================
// Fold attention vectors (fp32, tiny)
// ============================================================
__global__ void attn_fold_kernel(const float* __restrict__ Ws0, const float* __restrict__ Ws1,
                                 const float* __restrict__ Ws2, const float* __restrict__ Ws3,
                                 const float* __restrict__ Wd0, const float* __restrict__ Wd1,
                                 const float* __restrict__ Wd2, const float* __restrict__ Wd3,
                                 const float* __restrict__ s0, const float* __restrict__ s1,
                                 const float* __restrict__ s2, const float* __restrict__ s3,
                                 const float* __restrict__ d0, const float* __restrict__ d1,
                                 const float* __restrict__ d2, const float* __restrict__ d3) {
    int w = blockIdx.x * (blockDim.x >> 5) + (threadIdx.x >> 5);
    int lane = threadIdx.x & 31;
    if (w >= 8192) return;
    int l = w >> 11;
    int rem = w & 2047;
    int c = rem >> 8;
    int k = rem & 255;
    int H = (l == 3) ? 1 : 4;
    int side = c >> 2;
    int h = c & 3;
    float val = 0.f;
    if (h < H) {
        const float* W;
        const float* a;
        if (side == 0) {
            W = (l == 0) ? Ws0 : (l == 1) ? Ws1 : (l == 2) ? Ws2 : Ws3;
            a = (l == 0) ? s0 : (l == 1) ? s1 : (l == 2) ? s2 : s3;
        } else {
            W = (l == 0) ? Wd0 : (l == 1) ? Wd1 : (l == 2) ? Wd2 : Wd3;
            a = (l == 0) ? d0 : (l == 1) ? d1 : (l == 2) ? d2 : d3;
        }
        int HC = H * 64;
        const float* wr = W + (size_t)k * HC + h * 64;
        const float* ar = a + h * 64;
        float sacc = wr[lane] * ar[lane] + wr[lane + 32] * ar[lane + 32];
        #pragma unroll
        for (int off = 16; off > 0; off >>= 1)
            sacc += __shfl_xor_sync(0xffffffffu, sacc, off);
        val = sacc;
    }
    if (lane == 0) g_attnAll[l * 2048 + c * 256 + k] = val;
}

// ============================================================
// Pre-split all Ws weights into k-major packed hi/lo: out[kp*M + m].
// ============================================================
__global__ void presplit_W_kernel(const float* __restrict__ W0, const float* __restrict__ W1,
                                  const float* __restrict__ W2, const float* __restrict__ W3) {
    int t = blockIdx.x * blockDim.x + threadIdx.x;
    if (t >= 106496) return;
    const float* W;
    int M, kp, m, base;
    if (t < 98304) {
        int l = t >> 15;
        int within = t & 32767;
        M = 256; kp = within >> 8; m = within & 255;
        base = l << 15;
        W = (l == 0) ? W0 : (l == 1) ? W1 : W2;
    } else {
        int within = t - 98304;
        M = 64; kp = within >> 6; m = within & 63;
        base = 98304;
        W = W3;
    }
    float a = W[(size_t)(2 * kp) * M + m];
    float b = W[(size_t)(2 * kp + 1) * M + m];
    unsigned hi, lo;
    split2(a, b, hi, lo);
    g_Whi[base + kp * M + m] = hi;
    g_Wlo[base + kp * M + m] = lo;
}

// ============================================================
// Pre-split x into bf16 hi/lo + compute layer-1 attn logits (-> buf A).
// ============================================================
__global__ void presplit_x_attn_kernel(const float* __restrict__ x,
                                       const float* __restrict__ P, int n) {
    __shared__ float sP[2048];
    for (int i = threadIdx.x; i < 2048; i += blockDim.x) sP[i] = P[i];
    __syncthreads();
    int w = (blockIdx.x * blockDim.x + threadIdx.x) >> 5;
    int lane = threadIdx.x & 31;
    if (w >= n) return;
    float4 f0 = *reinterpret_cast<const float4*>(&x[(size_t)w * 256 + lane * 8]);
    float4 f1 = *reinterpret_cast<const float4*>(&x[(size_t)w * 256 + lane * 8 + 4]);
    float f[8] = {f0.x, f0.y, f0.z, f0.w, f1.x, f1.y, f1.z, f1.w};
    uint4 vh, vl;
    split2(f[0], f[1], vh.x, vl.x);
    split2(f[2], f[3], vh.y, vl.y);
    split2(f[4], f[5], vh.z, vl.z);
    split2(f[6], f[7], vh.w, vl.w);
    *reinterpret_cast<uint4*>(&g_b0hi[(size_t)w * 128 + lane * 4]) = vh;
    *reinterpret_cast<uint4*>(&g_b0lo[(size_t)w * 128 + lane * 4]) = vl;
    float acc[8] = {};
    #pragma unroll
    for (int u = 0; u < 8; u++)
        #pragma unroll
        for (int c = 0; c < 8; c++)
            acc[c] += f[u] * sP[c * 256 + lane * 8 + u];
    #pragma unroll
    for (int c = 0; c < 8; c++) {
        float v = acc[c];
        #pragma unroll
        for (int off = 16; off > 0; off >>= 1)
            v += __shfl_xor_sync(0xffffffffu, v, off);
        acc[c] = v;
    }
    if (lane == 0) {
        for (int c = 0; c < 4; c++) g_alsA[w * 4 + c] = acc[c];
        for (int c = 0; c < 4; c++) g_aldA[w * 4 + c] = acc[4 + c];
    }
}

// ============================================================
// GEMM (pre-split bf16, 3-term), fp16 half2-packed output.
// BM=128, BK=32, 256 threads, double-buffered dynamic smem, 2 CTAs/SM.
// ============================================================
#define ASTR 20
#define BSTR 72
#define OFF_AH 0
#define OFF_AL (2 * 128 * ASTR)
#define OFF_BH (OFF_AL + 2 * 128 * ASTR)
#define OFF_BL (OFF_BH + 2 * 16 * BSTR)
#define SMEM_UINTS (OFF_BL + 2 * 16 * BSTR)
#define SMEM_BYTES (SMEM_UINTS * 4)

__global__ __launch_bounds__(256, 2)
void gemm_kernel(const unsigned* __restrict__ Ahi, const unsigned* __restrict__ Alo,
                 const unsigned* __restrict__ Bhi, const unsigned* __restrict__ Blo,
                 unsigned* __restrict__ C2, int N, int M) {
    extern __shared__ unsigned dynsmem[];
    unsigned* sAh = dynsmem + OFF_AH;
    unsigned* sAl = dynsmem + OFF_AL;
    unsigned* sBh = dynsmem + OFF_BH;
    unsigned* sBl = dynsmem + OFF_BL;

    const int tid = threadIdx.x;
    const int lane = tid & 31;
    const int wid = tid >> 5;
    const int rowBase = blockIdx.x * 128;
    const int warpM = wid & 3;
    const int warpN = wid >> 2;
    const int g  = lane >> 2;
    const int tg = lane & 3;
    const int colBase = blockIdx.y * 64;

    const int aRow = tid >> 1;
    const int aH8  = (tid & 1) << 3;
    const bool aOk = (rowBase + aRow) < N;
    const unsigned* Agh = Ahi + (size_t)(rowBase + aRow) * 128 + aH8;
    const unsigned* Agl = Alo + (size_t)(rowBase + aRow) * 128 + aH8;

    const int bKp = tid >> 4;
    const int bM4 = (tid & 15) << 2;
    const unsigned* Bgh = Bhi + (size_t)bKp * M + colBase + bM4;
    const unsigned* Bgl = Blo + (size_t)bKp * M + colBase + bM4;

    float c[2][4][4] = {};

    uint4 rah0, rah1, ral0, ral1, rbh, rbl;
    const uint4 Z = make_uint4(0, 0, 0, 0);
    if (aOk) {
        rah0 = *reinterpret_cast<const uint4*>(Agh);
        rah1 = *reinterpret_cast<const uint4*>(Agh + 4);
        ral0 = *reinterpret_cast<const uint4*>(Agl);
        ral1 = *reinterpret_cast<const uint4*>(Agl + 4);
    } else { rah0 = rah1 = ral0 = ral1 = Z; }
    rbh = *reinterpret_cast<const uint4*>(Bgh);
    rbl = *reinterpret_cast<const uint4*>(Bgl);

    const int aIdx = aRow * ASTR + aH8;
    const int bIdx = bKp * BSTR + bM4;

    *reinterpret_cast<uint4*>(&sAh[aIdx])     = rah0;
    *reinterpret_cast<uint4*>(&sAh[aIdx + 4]) = rah1;
    *reinterpret_cast<uint4*>(&sAl[aIdx])     = ral0;
    *reinterpret_cast<uint4*>(&sAl[aIdx + 4]) = ral1;
    *reinterpret_cast<uint4*>(&sBh[bIdx]) = rbh;
    *reinterpret_cast<uint4*>(&sBl[bIdx]) = rbl;
    __syncthreads();

    for (int kt = 0; kt < 8; kt++) {
        const int curA = (kt & 1) * 128 * ASTR;
        const int curB = (kt & 1) * 16 * BSTR;
        if (kt + 1 < 8) {
            if (aOk) {
                rah0 = *reinterpret_cast<const uint4*>(Agh + (kt + 1) * 16);
                rah1 = *reinterpret_cast<const uint4*>(Agh + (kt + 1) * 16 + 4);
                ral0 = *reinterpret_cast<const uint4*>(Agl + (kt + 1) * 16);
                ral1 = *reinterpret_cast<const uint4*>(Agl + (kt + 1) * 16 + 4);
            }
            rbh = *reinterpret_cast<const uint4*>(Bgh + (size_t)(kt + 1) * 16 * M);
            rbl = *reinterpret_cast<const uint4*>(Bgl + (size_t)(kt + 1) * 16 * M);
        }

        #pragma unroll
        for (int k0 = 0; k0 < 2; k0++) {
            unsigned ah[2][4], al[2][4], bh[4][2], bl[4][2];
            #pragma unroll
            for (int mt = 0; mt < 2; mt++) {
                int r = warpM * 32 + mt * 16 + g;
                const unsigned* pAh = &sAh[curA + r * ASTR + k0 * 8 + tg];
                const unsigned* pAl = &sAl[curA + r * ASTR + k0 * 8 + tg];
                ah[mt][0] = pAh[0];             ah[mt][1] = pAh[8 * ASTR];
                ah[mt][2] = pAh[4];             ah[mt][3] = pAh[8 * ASTR + 4];
                al[mt][0] = pAl[0];             al[mt][1] = pAl[8 * ASTR];
                al[mt][2] = pAl[4];             al[mt][3] = pAl[8 * ASTR + 4];
            }
            #pragma unroll
            for (int nt = 0; nt < 4; nt++) {
                int col = warpN * 32 + nt * 8 + g;
                bh[nt][0] = sBh[curB + (k0 * 8 + tg) * BSTR + col];
                bh[nt][1] = sBh[curB + (k0 * 8 + tg + 4) * BSTR + col];
                bl[nt][0] = sBl[curB + (k0 * 8 + tg) * BSTR + col];
                bl[nt][1] = sBl[curB + (k0 * 8 + tg + 4) * BSTR + col];
            }
            #pragma unroll
            for (int mt = 0; mt < 2; mt++)
                #pragma unroll
                for (int nt = 0; nt < 4; nt++) {
                    mma16(c[mt][nt], ah[mt], bh[nt]);
                    mma16(c[mt][nt], ah[mt], bl[nt]);
                    mma16(c[mt][nt], al[mt], bh[nt]);
                }
        }

        if (kt + 1 < 8) {
            const int nxtA = ((kt + 1) & 1) * 128 * ASTR;
            const int nxtB = ((kt + 1) & 1) * 16 * BSTR;
            *reinterpret_cast<uint4*>(&sAh[nxtA + aIdx])     = rah0;
            *reinterpret_cast<uint4*>(&sAh[nxtA + aIdx + 4]) = rah1;
            *reinterpret_cast<uint4*>(&sAl[nxtA + aIdx])     = ral0;
            *reinterpret_cast<uint4*>(&sAl[nxtA + aIdx + 4]) = ral1;
            *reinterpret_cast<uint4*>(&sBh[nxtB + bIdx]) = rbh;
            *reinterpret_cast<uint4*>(&sBl[nxtB + bIdx]) = rbl;
            __syncthreads();
        }
    }

    const int M2 = M >> 1;
    #pragma unroll
    for (int mt = 0; mt < 2; mt++) {
        int r0 = rowBase + warpM * 32 + mt * 16 + g;
        #pragma unroll
        for (int nt = 0; nt < 4; nt++) {
            int colH = (colBase + warpN * 32 + nt * 8) / 2 + tg;
            __half2 v0 = __floats2half2_rn(c[mt][nt][0], c[mt][nt][1]);
            __half2 v1 = __floats2half2_rn(c[mt][nt][2], c[mt][nt][3]);
            if (r0 < N)
                C2[(size_t)r0 * M2 + colH] = *reinterpret_cast<unsigned*>(&v0);
            if (r0 + 8 < N)
                C2[(size_t)(r0 + 8) * M2 + colH] = *reinterpret_cast<unsigned*>(&v1);
        }
    }
}

// ============================================================
// Aggregation: warp per dst node, no-max softmax, 4-edge unroll,
// fp16 hs gathers.  Reads logits from (alsIn, aldIn); MODE 1 writes
// next-layer logits to (alsOut, aldOut)  — DIFFERENT buffers (no race).
// ============================================================
template <int H, int MODE>
__global__ void agg_kernel(const unsigned* __restrict__ hs2, const float* __restrict__ bias,
                           float* __restrict__ out, unsigned* __restrict__ ohi,
                           unsigned* __restrict__ olo, const float* __restrict__ Pnext,
                           const float* __restrict__ alsIn, const float* __restrict__ aldIn,
                           float* __restrict__ alsOut, float* __restrict__ aldOut,
                           int Hnext, int n, int doRelu) {
    const int HC = H * 64;
    const int R  = HC / 32;
    const int W2 = HC / 2;
    __shared__ float sP[2048];
    if (MODE == 1) {
        for (int i = threadIdx.x; i < 2048; i += blockDim.x) sP[i] = Pnext[i];
        __syncthreads();
    }
    int w = (blockIdx.x * blockDim.x + threadIdx.x) >> 5;
    int lane = threadIdx.x & 31;
    if (w >= n) return;
    int h = (lane * R) / 64;
    float ald_h = aldIn[w * H + h];

    float acc[R];
    #pragma unroll
    for (int r = 0; r < R; r++) acc[r] = 0.f;
    float den = 0.f;

    int beg = g_rowptr[w], end = g_rowptr[w + 1];
    int e = beg;
    for (; e + 3 < end; e += 4) {
        int s0 = g_ssrc[e];
        int s1 = g_ssrc[e + 1];
        int s2 = g_ssrc[e + 2];
        int s3 = g_ssrc[e + 3];
        float a0 = alsIn[s0 * H + h];
        float a1 = alsIn[s1 * H + h];
        float a2 = alsIn[s2 * H + h];
        float a3 = alsIn[s3 * H + h];
        float ev0 = a0 + ald_h; ev0 = ev0 > 0.f ? ev0 : 0.2f * ev0;
        float ev1 = a1 + ald_h; ev1 = ev1 > 0.f ? ev1 : 0.2f * ev1;
        float ev2 = a2 + ald_h; ev2 = ev2 > 0.f ? ev2 : 0.2f * ev2;
        float ev3 = a3 + ald_h; ev3 = ev3 > 0.f ? ev3 : 0.2f * ev3;
        float w0 = __expf(ev0), w1 = __expf(ev1), w2 = __expf(ev2), w3 = __expf(ev3);
        den += (w0 + w1) + (w2 + w3);
        if (R == 8) {
            uint4 q0 = *reinterpret_cast<const uint4*>(&hs2[(size_t)s0 * W2 + lane * 4]);
            uint4 q1 = *reinterpret_cast<const uint4*>(&hs2[(size_t)s1 * W2 + lane * 4]);
            uint4 q2 = *reinterpret_cast<const uint4*>(&hs2[(size_t)s2 * W2 + lane * 4]);
            uint4 q3 = *reinterpret_cast<const uint4*>(&hs2[(size_t)s3 * W2 + lane * 4]);
            float2 t;
            t = h2f(q0.x); acc[0] += w0 * t.x; acc[1] += w0 * t.y;
            t = h2f(q0.y); acc[2] += w0 * t.x; acc[3] += w0 * t.y;
            t = h2f(q0.z); acc[4] += w0 * t.x; acc[5] += w0 * t.y;
            t = h2f(q0.w); acc[6] += w0 * t.x; acc[7] += w0 * t.y;
            t = h2f(q1.x); acc[0] += w1 * t.x; acc[1] += w1 * t.y;
            t = h2f(q1.y); acc[2] += w1 * t.x; acc[3] += w1 * t.y;
            t = h2f(q1.z); acc[4] += w1 * t.x; acc[5] += w1 * t.y;
            t = h2f(q1.w); acc[6] += w1 * t.x; acc[7] += w1 * t.y;
            t = h2f(q2.x); acc[0] += w2 * t.x; acc[1] += w2 * t.y;
            t = h2f(q2.y); acc[2] += w2 * t.x; acc[3] += w2 * t.y;
            t = h2f(q2.z); acc[4] += w2 * t.x; acc[5] += w2 * t.y;
            t = h2f(q2.w); acc[6] += w2 * t.x; acc[7] += w2 * t.y;
            t = h2f(q3.x); acc[0] += w3 * t.x; acc[1] += w3 * t.y;
            t = h2f(q3.y); acc[2] += w3 * t.x; acc[3] += w3 * t.y;
            t = h2f(q3.z); acc[4] += w3 * t.x; acc[5] += w3 * t.y;
            t = h2f(q3.w); acc[6] += w3 * t.x; acc[7] += w3 * t.y;
        } else {
            float2 t;
            t = h2f(hs2[(size_t)s0 * W2 + lane]); acc[0] += w0 * t.x; acc[1] += w0 * t.y;
            t = h2f(hs2[(size_t)s1 * W2 + lane]); acc[0] += w1 * t.x; acc[1] += w1 * t.y;
            t = h2f(hs2[(size_t)s2 * W2 + lane]); acc[0] += w2 * t.x; acc[1] += w2 * t.y;
            t = h2f(hs2[(size_t)s3 * W2 + lane]); acc[0] += w3 * t.x; acc[1] += w3 * t.y;
        }
    }
    for (; e < end; e++) {
        int s = g_ssrc[e];
        float ev = alsIn[s * H + h] + ald_h;
        ev = ev > 0.f ? ev : 0.2f * ev;
        float wg = __expf(ev);
        den += wg;
        if (R == 8) {
            uint4 q = *reinterpret_cast<const uint4*>(&hs2[(size_t)s * W2 + lane * 4]);
            float2 t;
            t = h2f(q.x); acc[0] += wg * t.x; acc[1] += wg * t.y;
            t = h2f(q.y); acc[2] += wg * t.x; acc[3] += wg * t.y;
            t = h2f(q.z); acc[4] += wg * t.x; acc[5] += wg * t.y;
            t = h2f(q.w); acc[6] += wg * t.x; acc[7] += wg * t.y;
        } else {
            float2 t = h2f(hs2[(size_t)s * W2 + lane]);
            acc[0] += wg * t.x; acc[1] += wg * t.y;
        }
    }
    float invd = (end > beg) ? 1.f / den : 0.f;
    float o[R];
    #pragma unroll
    for (int r = 0; r < R; r++) {
        float v = acc[r] * invd + bias[lane * R + r];
        if (doRelu) v = fmaxf(v, 0.f);
        o[r] = v;
    }
    if (MODE == 1) {
        uint4 vh, vl;
        split2(o[0], o[1], vh.x, vl.x);
        split2(o[2], o[3], vh.y, vl.y);
        split2(o[4], o[5], vh.z, vl.z);
        split2(o[6], o[7], vh.w, vl.w);
        *reinterpret_cast<uint4*>(&ohi[(size_t)w * 128 + lane * 4]) = vh;
        *reinterpret_cast<uint4*>(&olo[(size_t)w * 128 + lane * 4]) = vl;
        float at[8] = {};
        #pragma unroll
        for (int u = 0; u < 8; u++)
            #pragma unroll
            for (int c = 0; c < 8; c++)
                at[c] += o[u] * sP[c * 256 + lane * 8 + u];
        #pragma unroll
        for (int c = 0; c < 8; c++) {
            float v = at[c];
            #pragma unroll
            for (int off = 16; off > 0; off >>= 1)
                v += __shfl_xor_sync(0xffffffffu, v, off);
            at[c] = v;
        }
        if (lane == 0) {
            for (int c = 0; c < Hnext; c++) alsOut[w * Hnext + c] = at[c];
            for (int c = 0; c < Hnext; c++) aldOut[w * Hnext + c] = at[4 + c];
        }
    } else {
        #pragma unroll
        for (int r = 0; r < R; r++)
            out[(size_t)w * HC + lane * R + r] = o[r];
    }
}

// ============================================================
// Launch
// ============================================================
extern "C" void kernel_launch(void* const* d_in, const int* in_sizes, int n_in,
                              void* d_out, int out_size) {
    const float* x  = (const float*)d_in[0];
    const int*   ei = (const int*)d_in[1];
    int n = in_sizes[0] / 256;
    int E = in_sizes[1] / 2;
    const int* src = ei;
    const int* dst = ei + E;

    const float *Ws[4], *Wd[4], *as_[4], *ad_[4], *bb[4];
    for (int l = 0; l < 4; l++) {
        Ws[l]  = (const float*)d_in[2 + 5 * l + 0];
        Wd[l]  = (const float*)d_in[2 + 5 * l + 1];
        as_[l] = (const float*)d_in[2 + 5 * l + 2];
        ad_[l] = (const float*)d_in[2 + 5 * l + 3];
        bb[l]  = (const float*)d_in[2 + 5 * l + 4];
    }

    void *p_hs2, *p_cnt, *p_at, *p_whi, *p_wlo;
    void *p_b0h, *p_b0l, *p_b1h, *p_b1l;
    void *p_alsA, *p_aldA, *p_alsB, *p_aldB;
    cudaGetSymbolAddress(&p_hs2, g_hs2);
    cudaGetSymbolAddress(&p_cnt, g_cnt);
    cudaGetSymbolAddress(&p_at, g_attnAll);
    cudaGetSymbolAddress(&p_whi, g_Whi);
    cudaGetSymbolAddress(&p_wlo, g_Wlo);
    cudaGetSymbolAddress(&p_b0h, g_b0hi);
    cudaGetSymbolAddress(&p_b0l, g_b0lo);
    cudaGetSymbolAddress(&p_b1h, g_b1hi);
    cudaGetSymbolAddress(&p_b1l, g_b1lo);
    cudaGetSymbolAddress(&p_alsA, g_alsA);
    cudaGetSymbolAddress(&p_aldA, g_aldA);
    cudaGetSymbolAddress(&p_alsB, g_alsB);
    cudaGetSymbolAddress(&p_aldB, g_aldB);
    unsigned* hs2 = (unsigned*)p_hs2;
    const float* at = (const float*)p_at;
    unsigned* whi = (unsigned*)p_whi;
    unsigned* wlo = (unsigned*)p_wlo;
    unsigned* bufh[2] = {(unsigned*)p_b0h, (unsigned*)p_b1h};
    unsigned* bufl[2] = {(unsigned*)p_b0l, (unsigned*)p_b1l};
    float* als[2] = {(float*)p_alsA, (float*)p_alsB};
    float* ald[2] = {(float*)p_aldA, (float*)p_aldB};

    cudaFuncSetAttribute(gemm_kernel,
                         cudaFuncAttributeMaxDynamicSharedMemorySize, SMEM_BYTES);

    // ---- sort edges by dst ----
    int nb = (n + 1023) / 1024;
    cudaMemsetAsync(p_cnt, 0, (size_t)(n + 1) * sizeof(int));
    hist_kernel<<<(E + 255) / 256, 256>>>(dst, E);
    scanA_kernel<<<nb, 1024>>>(n);
    scanB_kernel<<<1, 64>>>(nb);
    scanC_kernel<<<nb, 1024>>>(n, E);
    scatter_kernel<<<(E + 255) / 256, 256>>>(src, dst, E);

    // ---- one-shot folds / pre-splits (+ layer-1 attn logits -> buf A) ----
    attn_fold_kernel<<<1024, 256>>>(Ws[0], Ws[1], Ws[2], Ws[3],
                                    Wd[0], Wd[1], Wd[2], Wd[3],
                                    as_[0], as_[1], as_[2], as_[3],
                                    ad_[0], ad_[1], ad_[2], ad_[3]);
    presplit_W_kernel<<<(106496 + 255) / 256, 256>>>(Ws[0], Ws[1], Ws[2], Ws[3]);

    int warpBlocks = (n * 32 + 255) / 256;
    presplit_x_attn_kernel<<<warpBlocks, 256>>>(x, at, n);

    int gx = (n + 127) / 128;
    dim3 gGrid(gx, 4);     // M=256
    dim3 gGrid4(gx, 1);    // M=64

    // layer l: logits in buf (l&1), logits out buf ((l+1)&1)
    for (int l = 0; l < 3; l++) {
        int ia = l & 1, io = (l + 1) & 1;
        gemm_kernel<<<gGrid, 256, SMEM_BYTES>>>(bufh[ia], bufl[ia],
                                                whi + l * 32768, wlo + l * 32768,
                                                hs2, n, 256);
        agg_kernel<4, 1><<<warpBlocks, 256>>>(hs2, bb[l], nullptr,
                                              bufh[io], bufl[io],
                                              at + (l + 1) * 2048,
                                              als[ia], ald[ia], als[io], ald[io],
                                              (l == 2) ? 1 : 4, n, 1);
    }
    gemm_kernel<<<gGrid4, 256, SMEM_BYTES>>>(bufh[1], bufl[1],
                                             whi + 98304, wlo + 98304,
                                             hs2, n, 64);
    agg_kernel<1, 0><<<warpBlocks, 256>>>(hs2, bb[3], (float*)d_out,
                                          nullptr, nullptr, nullptr,
                                          als[1], ald[1], nullptr, nullptr,
                                          0, n, 0);
}

// round 15
// speedup vs baseline: 2.4243x; 1.2614x over previous
#include <cuda_runtime.h>
#include <cuda_fp16.h>

#define NMAX 50000
#define EMAX 500000

// ---- static device scratch (allocation-free contract) ----
__device__ unsigned g_hs2[(size_t)NMAX * 128];    // projections, fp16 half2-packed (max M=256)
__device__ unsigned g_b0[(size_t)NMAX * 128];     // feature buffer 0, fp16 k-pair packed
__device__ unsigned g_b1[(size_t)NMAX * 128];     // feature buffer 1
__device__ unsigned g_Whi[106496];                // weights fp16 hi, k-major [kp][m], all layers
__device__ unsigned g_Wlo[106496];                // weights fp16 lo (residual)
__device__ float    g_alsA[NMAX * 4];             // logit ping buffer
__device__ float    g_aldA[NMAX * 4];
__device__ float    g_alsB[NMAX * 4];             // logit pong buffer
__device__ float    g_aldB[NMAX * 4];
__device__ float    g_attnAll[4 * 2048];          // folded [Ws@a_src^T | Wd@a_dst^T]
__device__ int      g_cnt[NMAX + 1];
__device__ int      g_cur[NMAX + 1];
__device__ int      g_rowptr[NMAX + 1];
__device__ int      g_bsum[64];
__device__ int      g_ssrc[EMAX];

// ============================================================
// helpers
// ============================================================
__device__ __forceinline__ unsigned packh2(__half a, __half b) {
    __half2 t = __halves2half2(a, b);
    return *reinterpret_cast<unsigned*>(&t);
}
__device__ __forceinline__ unsigned f2h2(float a, float b) {
    __half2 t = __floats2half2_rn(a, b);
    return *reinterpret_cast<unsigned*>(&t);
}
__device__ __forceinline__ void splitW2(float a, float b, unsigned& hi, unsigned& lo) {
    __half ha = __float2half_rn(a);
    __half hb = __float2half_rn(b);
    hi = packh2(ha, hb);
    lo = packh2(__float2half_rn(a - __half2float(ha)),
                __float2half_rn(b - __half2float(hb)));
}
__device__ __forceinline__ void mma16h(float* c, const unsigned* a, const unsigned* b) {
    asm volatile(
        "mma.sync.aligned.m16n8k16.row.col.f32.f16.f16.f32 "
        "{%0,%1,%2,%3}, {%4,%5,%6,%7}, {%8,%9}, {%0,%1,%2,%3};\n"
        : "+f"(c[0]), "+f"(c[1]), "+f"(c[2]), "+f"(c[3])
        : "r"(a[0]), "r"(a[1]), "r"(a[2]), "r"(a[3]), "r"(b[0]), "r"(b[1]));
}
__device__ __forceinline__ float2 h2f(unsigned u) {
    return __half22float2(*reinterpret_cast<__half2*>(&u));
}

// ============================================================
// Edge sort: counting sort by dst
// ============================================================
__global__ void hist_kernel(const int* __restrict__ dst, int E) {
    int e = blockIdx.x * blockDim.x + threadIdx.x;
    if (e < E) atomicAdd(&g_cnt[dst[e]], 1);
}
__global__ void scanA_kernel(int n) {
    __shared__ int sh[1024];
    int tid = threadIdx.x;
    int i = blockIdx.x * 1024 + tid;
    int v = (i < n) ? g_cnt[i] : 0;
    sh[tid] = v;
    __syncthreads();
    #pragma unroll
    for (int off = 1; off < 1024; off <<= 1) {
        int t = (tid >= off) ? sh[tid - off] : 0;
        __syncthreads();
        sh[tid] += t;
        __syncthreads();
    }
    if (i < n) g_rowptr[i] = sh[tid] - v;
    if (tid == 1023) g_bsum[blockIdx.x] = sh[1023];
}
__global__ void scanB_kernel(int nb) {
    __shared__ int sh[64];
    int tid = threadIdx.x;
    int v = (tid < nb) ? g_bsum[tid] : 0;
    sh[tid] = v;
    __syncthreads();
    #pragma unroll
    for (int off = 1; off < 64; off <<= 1) {
        int t = (tid >= off) ? sh[tid - off] : 0;
        __syncthreads();
        sh[tid] += t;
        __syncthreads();
    }
    if (tid < nb) g_bsum[tid] = sh[tid] - v;
}
__global__ void scanC_kernel(int n, int E) {
    int i = blockIdx.x * 1024 + threadIdx.x;
    if (i < n) {
        int r = g_rowptr[i] + g_bsum[blockIdx.x];
        g_rowptr[i] = r;
        g_cur[i] = r;
    }
    if (i == n) g_rowptr[n] = E;
}
__global__ void scatter_kernel(const int* __restrict__ src, const int* __restrict__ dst, int E) {
    int e = blockIdx.x * blockDim.x + threadIdx.x;
    if (e < E) {
        int d = dst[e];
        int p = atomicAdd(&g_cur[d], 1);
        g_ssrc[p] = src[e];
    }
}

// ============================================================
// Fold attention vectors (fp32, tiny)
// ============================================================
__global__ void attn_fold_kernel(const float* __restrict__ Ws0, const float* __restrict__ Ws1,
                                 const float* __restrict__ Ws2, const float* __restrict__ Ws3,
                                 const float* __restrict__ Wd0, const float* __restrict__ Wd1,
                                 const float* __restrict__ Wd2, const float* __restrict__ Wd3,
                                 const float* __restrict__ s0, const float* __restrict__ s1,
                                 const float* __restrict__ s2, const float* __restrict__ s3,
                                 const float* __restrict__ d0, const float* __restrict__ d1,
                                 const float* __restrict__ d2, const float* __restrict__ d3) {
    int w = blockIdx.x * (blockDim.x >> 5) + (threadIdx.x >> 5);
    int lane = threadIdx.x & 31;
    if (w >= 8192) return;
    int l = w >> 11;
    int rem = w & 2047;
    int c = rem >> 8;
    int k = rem & 255;
    int H = (l == 3) ? 1 : 4;
    int side = c >> 2;
    int h = c & 3;
    float val = 0.f;
    if (h < H) {
        const float* W;
        const float* a;
        if (side == 0) {
            W = (l == 0) ? Ws0 : (l == 1) ? Ws1 : (l == 2) ? Ws2 : Ws3;
            a = (l == 0) ? s0 : (l == 1) ? s1 : (l == 2) ? s2 : s3;
        } else {
            W = (l == 0) ? Wd0 : (l == 1) ? Wd1 : (l == 2) ? Wd2 : Wd3;
            a = (l == 0) ? d0 : (l == 1) ? d1 : (l == 2) ? d2 : d3;
        }
        int HC = H * 64;
        const float* wr = W + (size_t)k * HC + h * 64;
        const float* ar = a + h * 64;
        float sacc = wr[lane] * ar[lane] + wr[lane + 32] * ar[lane + 32];
        #pragma unroll
        for (int off = 16; off > 0; off >>= 1)
            sacc += __shfl_xor_sync(0xffffffffu, sacc, off);
        val = sacc;
    }
    if (lane == 0) g_attnAll[l * 2048 + c * 256 + k] = val;
}

// ============================================================
// Pre-split all Ws weights into fp16 hi/lo, k-major: out[kp*M + m].
// ============================================================
__global__ void presplit_W_kernel(const float* __restrict__ W0, const float* __restrict__ W1,
                                  const float* __restrict__ W2, const float* __restrict__ W3) {
    int t = blockIdx.x * blockDim.x + threadIdx.x;
    if (t >= 106496) return;
    const float* W;
    int M, kp, m, base;
    if (t < 98304) {
        int l = t >> 15;
        int within = t & 32767;
        M = 256; kp = within >> 8; m = within & 255;
        base = l << 15;
        W = (l == 0) ? W0 : (l == 1) ? W1 : W2;
    } else {
        int within = t - 98304;
        M = 64; kp = within >> 6; m = within & 63;
        base = 98304;
        W = W3;
    }
    float a = W[(size_t)(2 * kp) * M + m];
    float b = W[(size_t)(2 * kp + 1) * M + m];
    unsigned hi, lo;
    splitW2(a, b, hi, lo);
    g_Whi[base + kp * M + m] = hi;
    g_Wlo[base + kp * M + m] = lo;
}

// ============================================================
// Pack x to fp16 + compute layer-1 attn logits (-> buf A).
// ============================================================
__global__ void presplit_x_attn_kernel(const float* __restrict__ x,
                                       const float* __restrict__ P, int n) {
    __shared__ float sP[2048];
    for (int i = threadIdx.x; i < 2048; i += blockDim.x) sP[i] = P[i];
    __syncthreads();
    int w = (blockIdx.x * blockDim.x + threadIdx.x) >> 5;
    int lane = threadIdx.x & 31;
    if (w >= n) return;
    float4 f0 = *reinterpret_cast<const float4*>(&x[(size_t)w * 256 + lane * 8]);
    float4 f1 = *reinterpret_cast<const float4*>(&x[(size_t)w * 256 + lane * 8 + 4]);
    float f[8] = {f0.x, f0.y, f0.z, f0.w, f1.x, f1.y, f1.z, f1.w};
    uint4 v;
    v.x = f2h2(f[0], f[1]);
    v.y = f2h2(f[2], f[3]);
    v.z = f2h2(f[4], f[5]);
    v.w = f2h2(f[6], f[7]);
    *reinterpret_cast<uint4*>(&g_b0[(size_t)w * 128 + lane * 4]) = v;
    float acc[8] = {};
    #pragma unroll
    for (int u = 0; u < 8; u++)
        #pragma unroll
        for (int c = 0; c < 8; c++)
            acc[c] += f[u] * sP[c * 256 + lane * 8 + u];
    #pragma unroll
    for (int c = 0; c < 8; c++) {
        float v2 = acc[c];
        #pragma unroll
        for (int off = 16; off > 0; off >>= 1)
            v2 += __shfl_xor_sync(0xffffffffu, v2, off);
        acc[c] = v2;
    }
    if (lane == 0) {
        for (int c = 0; c < 4; c++) g_alsA[w * 4 + c] = acc[c];
        for (int c = 0; c < 4; c++) g_aldA[w * 4 + c] = acc[4 + c];
    }
}

// ============================================================
// GEMM: fp16 A (single) x fp16 hi/lo W (2-term), fp16 output.
// BM=128, BK=32, 256 threads, double-buffered dynamic smem, 2 CTAs/SM.
// ============================================================
#define ASTR 20
#define BSTR 72
#define OFF_A  0
#define OFF_BH (2 * 128 * ASTR)
#define OFF_BL (OFF_BH + 2 * 16 * BSTR)
#define SMEM_UINTS (OFF_BL + 2 * 16 * BSTR)
#define SMEM_BYTES (SMEM_UINTS * 4)

__global__ __launch_bounds__(256, 2)
void gemm_kernel(const unsigned* __restrict__ A, const unsigned* __restrict__ Bhi,
                 const unsigned* __restrict__ Blo, unsigned* __restrict__ C2,
                 int N, int M) {
    extern __shared__ unsigned dynsmem[];
    unsigned* sA  = dynsmem + OFF_A;    // [2][128][ASTR]
    unsigned* sBh = dynsmem + OFF_BH;   // [2][16][BSTR]
    unsigned* sBl = dynsmem + OFF_BL;

    const int tid = threadIdx.x;
    const int lane = tid & 31;
    const int wid = tid >> 5;
    const int rowBase = blockIdx.x * 128;
    const int warpM = wid & 3;
    const int warpN = wid >> 2;
    const int g  = lane >> 2;
    const int tg = lane & 3;
    const int colBase = blockIdx.y * 64;

    const int aRow = tid >> 1;
    const int aH8  = (tid & 1) << 3;
    const bool aOk = (rowBase + aRow) < N;
    const unsigned* Ag = A + (size_t)(rowBase + aRow) * 128 + aH8;

    const int bKp = tid >> 4;
    const int bM4 = (tid & 15) << 2;
    const unsigned* Bgh = Bhi + (size_t)bKp * M + colBase + bM4;
    const unsigned* Bgl = Blo + (size_t)bKp * M + colBase + bM4;

    float c[2][4][4] = {};

    uint4 ra0, ra1, rbh, rbl;
    const uint4 Z = make_uint4(0, 0, 0, 0);
    if (aOk) {
        ra0 = *reinterpret_cast<const uint4*>(Ag);
        ra1 = *reinterpret_cast<const uint4*>(Ag + 4);
    } else { ra0 = ra1 = Z; }
    rbh = *reinterpret_cast<const uint4*>(Bgh);
    rbl = *reinterpret_cast<const uint4*>(Bgl);

    const int aIdx = aRow * ASTR + aH8;
    const int bIdx = bKp * BSTR + bM4;

    *reinterpret_cast<uint4*>(&sA[aIdx])     = ra0;
    *reinterpret_cast<uint4*>(&sA[aIdx + 4]) = ra1;
    *reinterpret_cast<uint4*>(&sBh[bIdx]) = rbh;
    *reinterpret_cast<uint4*>(&sBl[bIdx]) = rbl;
    __syncthreads();

    for (int kt = 0; kt < 8; kt++) {
        const int curA = (kt & 1) * 128 * ASTR;
        const int curB = (kt & 1) * 16 * BSTR;
        if (kt + 1 < 8) {
            if (aOk) {
                ra0 = *reinterpret_cast<const uint4*>(Ag + (kt + 1) * 16);
                ra1 = *reinterpret_cast<const uint4*>(Ag + (kt + 1) * 16 + 4);
            }
            rbh = *reinterpret_cast<const uint4*>(Bgh + (size_t)(kt + 1) * 16 * M);
            rbl = *reinterpret_cast<const uint4*>(Bgl + (size_t)(kt + 1) * 16 * M);
        }

        #pragma unroll
        for (int k0 = 0; k0 < 2; k0++) {
            unsigned ah[2][4], bh[4][2], bl[4][2];
            #pragma unroll
            for (int mt = 0; mt < 2; mt++) {
                int r = warpM * 32 + mt * 16 + g;
                const unsigned* pA = &sA[curA + r * ASTR + k0 * 8 + tg];
                ah[mt][0] = pA[0];   ah[mt][1] = pA[8 * ASTR];
                ah[mt][2] = pA[4];   ah[mt][3] = pA[8 * ASTR + 4];
            }
            #pragma unroll
            for (int nt = 0; nt < 4; nt++) {
                int col = warpN * 32 + nt * 8 + g;
                bh[nt][0] = sBh[curB + (k0 * 8 + tg) * BSTR + col];
                bh[nt][1] = sBh[curB + (k0 * 8 + tg + 4) * BSTR + col];
                bl[nt][0] = sBl[curB + (k0 * 8 + tg) * BSTR + col];
                bl[nt][1] = sBl[curB + (k0 * 8 + tg + 4) * BSTR + col];
            }
            #pragma unroll
            for (int mt = 0; mt < 2; mt++)
                #pragma unroll
                for (int nt = 0; nt < 4; nt++) {
                    mma16h(c[mt][nt], ah[mt], bh[nt]);
                    mma16h(c[mt][nt], ah[mt], bl[nt]);
                }
        }

        if (kt + 1 < 8) {
            const int nxtA = ((kt + 1) & 1) * 128 * ASTR;
            const int nxtB = ((kt + 1) & 1) * 16 * BSTR;
            *reinterpret_cast<uint4*>(&sA[nxtA + aIdx])     = ra0;
            *reinterpret_cast<uint4*>(&sA[nxtA + aIdx + 4]) = ra1;
            *reinterpret_cast<uint4*>(&sBh[nxtB + bIdx]) = rbh;
            *reinterpret_cast<uint4*>(&sBl[nxtB + bIdx]) = rbl;
            __syncthreads();
        }
    }

    const int M2 = M >> 1;
    #pragma unroll
    for (int mt = 0; mt < 2; mt++) {
        int r0 = rowBase + warpM * 32 + mt * 16 + g;
        #pragma unroll
        for (int nt = 0; nt < 4; nt++) {
            int colH = (colBase + warpN * 32 + nt * 8) / 2 + tg;
            unsigned v0 = f2h2(c[mt][nt][0], c[mt][nt][1]);
            unsigned v1 = f2h2(c[mt][nt][2], c[mt][nt][3]);
            if (r0 < N)
                C2[(size_t)r0 * M2 + colH] = v0;
            if (r0 + 8 < N)
                C2[(size_t)(r0 + 8) * M2 + colH] = v1;
        }
    }
}

// ============================================================
// Aggregation: warp per dst node, no-max softmax, 4-edge unroll,
// fp16 hs gathers.  Reads logits from (alsIn, aldIn); MODE 1 writes
// fp16 features + next-layer logits to separate ping-pong buffers.
// ============================================================
template <int H, int MODE>
__global__ void agg_kernel(const unsigned* __restrict__ hs2, const float* __restrict__ bias,
                           float* __restrict__ out, unsigned* __restrict__ ofeat,
                           const float* __restrict__ Pnext,
                           const float* __restrict__ alsIn, const float* __restrict__ aldIn,
                           float* __restrict__ alsOut, float* __restrict__ aldOut,
                           int Hnext, int n, int doRelu) {
    const int HC = H * 64;
    const int R  = HC / 32;
    const int W2 = HC / 2;
    __shared__ float sP[2048];
    if (MODE == 1) {
        for (int i = threadIdx.x; i < 2048; i += blockDim.x) sP[i] = Pnext[i];
        __syncthreads();
    }
    int w = (blockIdx.x * blockDim.x + threadIdx.x) >> 5;
    int lane = threadIdx.x & 31;
    if (w >= n) return;
    int h = (lane * R) / 64;
    float ald_h = aldIn[w * H + h];

    float acc[R];
    #pragma unroll
    for (int r = 0; r < R; r++) acc[r] = 0.f;
    float den = 0.f;

    int beg = g_rowptr[w], end = g_rowptr[w + 1];
    int e = beg;
    for (; e + 3 < end; e += 4) {
        int s0 = g_ssrc[e];
        int s1 = g_ssrc[e + 1];
        int s2 = g_ssrc[e + 2];
        int s3 = g_ssrc[e + 3];
        float a0 = alsIn[s0 * H + h];
        float a1 = alsIn[s1 * H + h];
        float a2 = alsIn[s2 * H + h];
        float a3 = alsIn[s3 * H + h];
        float ev0 = a0 + ald_h; ev0 = ev0 > 0.f ? ev0 : 0.2f * ev0;
        float ev1 = a1 + ald_h; ev1 = ev1 > 0.f ? ev1 : 0.2f * ev1;
        float ev2 = a2 + ald_h; ev2 = ev2 > 0.f ? ev2 : 0.2f * ev2;
        float ev3 = a3 + ald_h; ev3 = ev3 > 0.f ? ev3 : 0.2f * ev3;
        float w0 = __expf(ev0), w1 = __expf(ev1), w2 = __expf(ev2), w3 = __expf(ev3);
        den += (w0 + w1) + (w2 + w3);
        if (R == 8) {
            uint4 q0 = *reinterpret_cast<const uint4*>(&hs2[(size_t)s0 * W2 + lane * 4]);
            uint4 q1 = *reinterpret_cast<const uint4*>(&hs2[(size_t)s1 * W2 + lane * 4]);
            uint4 q2 = *reinterpret_cast<const uint4*>(&hs2[(size_t)s2 * W2 + lane * 4]);
            uint4 q3 = *reinterpret_cast<const uint4*>(&hs2[(size_t)s3 * W2 + lane * 4]);
            float2 t;
            t = h2f(q0.x); acc[0] += w0 * t.x; acc[1] += w0 * t.y;
            t = h2f(q0.y); acc[2] += w0 * t.x; acc[3] += w0 * t.y;
            t = h2f(q0.z); acc[4] += w0 * t.x; acc[5] += w0 * t.y;
            t = h2f(q0.w); acc[6] += w0 * t.x; acc[7] += w0 * t.y;
            t = h2f(q1.x); acc[0] += w1 * t.x; acc[1] += w1 * t.y;
            t = h2f(q1.y); acc[2] += w1 * t.x; acc[3] += w1 * t.y;
            t = h2f(q1.z); acc[4] += w1 * t.x; acc[5] += w1 * t.y;
            t = h2f(q1.w); acc[6] += w1 * t.x; acc[7] += w1 * t.y;
            t = h2f(q2.x); acc[0] += w2 * t.x; acc[1] += w2 * t.y;
            t = h2f(q2.y); acc[2] += w2 * t.x; acc[3] += w2 * t.y;
            t = h2f(q2.z); acc[4] += w2 * t.x; acc[5] += w2 * t.y;
            t = h2f(q2.w); acc[6] += w2 * t.x; acc[7] += w2 * t.y;
            t = h2f(q3.x); acc[0] += w3 * t.x; acc[1] += w3 * t.y;
            t = h2f(q3.y); acc[2] += w3 * t.x; acc[3] += w3 * t.y;
            t = h2f(q3.z); acc[4] += w3 * t.x; acc[5] += w3 * t.y;
            t = h2f(q3.w); acc[6] += w3 * t.x; acc[7] += w3 * t.y;
        } else {
            float2 t;
            t = h2f(hs2[(size_t)s0 * W2 + lane]); acc[0] += w0 * t.x; acc[1] += w0 * t.y;
            t = h2f(hs2[(size_t)s1 * W2 + lane]); acc[0] += w1 * t.x; acc[1] += w1 * t.y;
            t = h2f(hs2[(size_t)s2 * W2 + lane]); acc[0] += w2 * t.x; acc[1] += w2 * t.y;
            t = h2f(hs2[(size_t)s3 * W2 + lane]); acc[0] += w3 * t.x; acc[1] += w3 * t.y;
        }
    }
    for (; e < end; e++) {
        int s = g_ssrc[e];
        float ev = alsIn[s * H + h] + ald_h;
        ev = ev > 0.f ? ev : 0.2f * ev;
        float wg = __expf(ev);
        den += wg;
        if (R == 8) {
            uint4 q = *reinterpret_cast<const uint4*>(&hs2[(size_t)s * W2 + lane * 4]);
            float2 t;
            t = h2f(q.x); acc[0] += wg * t.x; acc[1] += wg * t.y;
            t = h2f(q.y); acc[2] += wg * t.x; acc[3] += wg * t.y;
            t = h2f(q.z); acc[4] += wg * t.x; acc[5] += wg * t.y;
            t = h2f(q.w); acc[6] += wg * t.x; acc[7] += wg * t.y;
        } else {
            float2 t = h2f(hs2[(size_t)s * W2 + lane]);
            acc[0] += wg * t.x; acc[1] += wg * t.y;
        }
    }
    float invd = (end > beg) ? 1.f / den : 0.f;
    float o[R];
    #pragma unroll
    for (int r = 0; r < R; r++) {
        float v = acc[r] * invd + bias[lane * R + r];
        if (doRelu) v = fmaxf(v, 0.f);
        o[r] = v;
    }
    if (MODE == 1) {
        uint4 v;
        v.x = f2h2(o[0], o[1]);
        v.y = f2h2(o[2], o[3]);
        v.z = f2h2(o[4], o[5]);
        v.w = f2h2(o[6], o[7]);
        *reinterpret_cast<uint4*>(&ofeat[(size_t)w * 128 + lane * 4]) = v;
        float at[8] = {};
        #pragma unroll
        for (int u = 0; u < 8; u++)
            #pragma unroll
            for (int c = 0; c < 8; c++)
                at[c] += o[u] * sP[c * 256 + lane * 8 + u];
        #pragma unroll
        for (int c = 0; c < 8; c++) {
            float vv = at[c];
            #pragma unroll
            for (int off = 16; off > 0; off >>= 1)
                vv += __shfl_xor_sync(0xffffffffu, vv, off);
            at[c] = vv;
        }
        if (lane == 0) {
            for (int c = 0; c < Hnext; c++) alsOut[w * Hnext + c] = at[c];
            for (int c = 0; c < Hnext; c++) aldOut[w * Hnext + c] = at[4 + c];
        }
    } else {
        #pragma unroll
        for (int r = 0; r < R; r++)
            out[(size_t)w * HC + lane * R + r] = o[r];
    }
}

// ============================================================
// Launch
// ============================================================
extern "C" void kernel_launch(void* const* d_in, const int* in_sizes, int n_in,
                              void* d_out, int out_size) {
    const float* x  = (const float*)d_in[0];
    const int*   ei = (const int*)d_in[1];
    int n = in_sizes[0] / 256;
    int E = in_sizes[1] / 2;
    const int* src = ei;
    const int* dst = ei + E;

    const float *Ws[4], *Wd[4], *as_[4], *ad_[4], *bb[4];
    for (int l = 0; l < 4; l++) {
        Ws[l]  = (const float*)d_in[2 + 5 * l + 0];
        Wd[l]  = (const float*)d_in[2 + 5 * l + 1];
        as_[l] = (const float*)d_in[2 + 5 * l + 2];
        ad_[l] = (const float*)d_in[2 + 5 * l + 3];
        bb[l]  = (const float*)d_in[2 + 5 * l + 4];
    }

    void *p_hs2, *p_cnt, *p_at, *p_whi, *p_wlo;
    void *p_b0, *p_b1;
    void *p_alsA, *p_aldA, *p_alsB, *p_aldB;
    cudaGetSymbolAddress(&p_hs2, g_hs2);
    cudaGetSymbolAddress(&p_cnt, g_cnt);
    cudaGetSymbolAddress(&p_at, g_attnAll);
    cudaGetSymbolAddress(&p_whi, g_Whi);
    cudaGetSymbolAddress(&p_wlo, g_Wlo);
    cudaGetSymbolAddress(&p_b0, g_b0);
    cudaGetSymbolAddress(&p_b1, g_b1);
    cudaGetSymbolAddress(&p_alsA, g_alsA);
    cudaGetSymbolAddress(&p_aldA, g_aldA);
    cudaGetSymbolAddress(&p_alsB, g_alsB);
    cudaGetSymbolAddress(&p_aldB, g_aldB);
    unsigned* hs2 = (unsigned*)p_hs2;
    const float* at = (const float*)p_at;
    unsigned* whi = (unsigned*)p_whi;
    unsigned* wlo = (unsigned*)p_wlo;
    unsigned* buf[2] = {(unsigned*)p_b0, (unsigned*)p_b1};
    float* als[2] = {(float*)p_alsA, (float*)p_alsB};
    float* ald[2] = {(float*)p_aldA, (float*)p_aldB};

    cudaFuncSetAttribute(gemm_kernel,
                         cudaFuncAttributeMaxDynamicSharedMemorySize, SMEM_BYTES);

    // ---- sort edges by dst ----
    int nb = (n + 1023) / 1024;
    cudaMemsetAsync(p_cnt, 0, (size_t)(n + 1) * sizeof(int));
    hist_kernel<<<(E + 255) / 256, 256>>>(dst, E);
    scanA_kernel<<<nb, 1024>>>(n);
    scanB_kernel<<<1, 64>>>(nb);
    scanC_kernel<<<nb, 1024>>>(n, E);
    scatter_kernel<<<(E + 255) / 256, 256>>>(src, dst, E);

    // ---- one-shot folds / pre-splits (+ layer-1 attn logits -> buf A) ----
    attn_fold_kernel<<<1024, 256>>>(Ws[0], Ws[1], Ws[2], Ws[3],
                                    Wd[0], Wd[1], Wd[2], Wd[3],
                                    as_[0], as_[1], as_[2], as_[3],
                                    ad_[0], ad_[1], ad_[2], ad_[3]);
    presplit_W_kernel<<<(106496 + 255) / 256, 256>>>(Ws[0], Ws[1], Ws[2], Ws[3]);

    int warpBlocks = (n * 32 + 255) / 256;
    presplit_x_attn_kernel<<<warpBlocks, 256>>>(x, at, n);

    int gx = (n + 127) / 128;
    dim3 gGrid(gx, 4);     // M=256
    dim3 gGrid4(gx, 1);    // M=64

    // layer l: features/logits in buf (l&1), out buf ((l+1)&1)
    for (int l = 0; l < 3; l++) {
        int ia = l & 1, io = (l + 1) & 1;
        gemm_kernel<<<gGrid, 256, SMEM_BYTES>>>(buf[ia],
                                                whi + l * 32768, wlo + l * 32768,
                                                hs2, n, 256);
        agg_kernel<4, 1><<<warpBlocks, 256>>>(hs2, bb[l], nullptr, buf[io],
                                              at + (l + 1) * 2048,
                                              als[ia], ald[ia], als[io], ald[io],
                                              (l == 2) ? 1 : 4, n, 1);
    }
    gemm_kernel<<<gGrid4, 256, SMEM_BYTES>>>(buf[1],
                                             whi + 98304, wlo + 98304,
                                             hs2, n, 64);
    agg_kernel<1, 0><<<warpBlocks, 256>>>(hs2, bb[3], (float*)d_out, nullptr,
                                          nullptr, als[1], ald[1], nullptr, nullptr,
                                          0, n, 0);
}

// round 16
// speedup vs baseline: 2.6398x; 1.0889x over previous
#include <cuda_runtime.h>
#include <cuda_fp16.h>

#define NMAX 50000
#define EMAX 500000

// ---- static device scratch (allocation-free contract) ----
__device__ unsigned g_hs2[(size_t)NMAX * 128];    // projections, fp16 half2-packed (max M=256)
__device__ unsigned g_b0[(size_t)NMAX * 128];     // feature buffer 0, fp16 k-pair packed
__device__ unsigned g_b1[(size_t)NMAX * 128];     // feature buffer 1
__device__ unsigned g_Wh[106496];                 // weights fp16 k-pair packed, k-major [kp][m]
__device__ float    g_alsA[NMAX * 4];             // logit ping buffer
__device__ float    g_aldA[NMAX * 4];
__device__ float    g_alsB[NMAX * 4];             // logit pong buffer
__device__ float    g_aldB[NMAX * 4];
__device__ float    g_attnAll[4 * 2048];          // folded [Ws@a_src^T | Wd@a_dst^T]
__device__ int      g_cnt[NMAX + 1];
__device__ int      g_cur[NMAX + 1];
__device__ int      g_rowptr[NMAX + 1];
__device__ int      g_bsum[64];
__device__ int      g_ssrc[EMAX];

// ============================================================
// helpers
// ============================================================
__device__ __forceinline__ unsigned f2h2(float a, float b) {
    __half2 t = __floats2half2_rn(a, b);
    return *reinterpret_cast<unsigned*>(&t);
}
__device__ __forceinline__ void mma16h(float* c, const unsigned* a, const unsigned* b) {
    asm volatile(
        "mma.sync.aligned.m16n8k16.row.col.f32.f16.f16.f32 "
        "{%0,%1,%2,%3}, {%4,%5,%6,%7}, {%8,%9}, {%0,%1,%2,%3};\n"
        : "+f"(c[0]), "+f"(c[1]), "+f"(c[2]), "+f"(c[3])
        : "r"(a[0]), "r"(a[1]), "r"(a[2]), "r"(a[3]), "r"(b[0]), "r"(b[1]));
}
__device__ __forceinline__ float2 h2f(unsigned u) {
    return __half22float2(*reinterpret_cast<__half2*>(&u));
}

// ============================================================
// Edge sort: counting sort by dst
// ============================================================
__global__ void hist_kernel(const int* __restrict__ dst, int E) {
    int e = blockIdx.x * blockDim.x + threadIdx.x;
    if (e < E) atomicAdd(&g_cnt[dst[e]], 1);
}
__global__ void scanA_kernel(int n) {
    __shared__ int sh[1024];
    int tid = threadIdx.x;
    int i = blockIdx.x * 1024 + tid;
    int v = (i < n) ? g_cnt[i] : 0;
    sh[tid] = v;
    __syncthreads();
    #pragma unroll
    for (int off = 1; off < 1024; off <<= 1) {
        int t = (tid >= off) ? sh[tid - off] : 0;
        __syncthreads();
        sh[tid] += t;
        __syncthreads();
    }
    if (i < n) g_rowptr[i] = sh[tid] - v;
    if (tid == 1023) g_bsum[blockIdx.x] = sh[1023];
}
__global__ void scanB_kernel(int nb) {
    __shared__ int sh[64];
    int tid = threadIdx.x;
    int v = (tid < nb) ? g_bsum[tid] : 0;
    sh[tid] = v;
    __syncthreads();
    #pragma unroll
    for (int off = 1; off < 64; off <<= 1) {
        int t = (tid >= off) ? sh[tid - off] : 0;
        __syncthreads();
        sh[tid] += t;
        __syncthreads();
    }
    if (tid < nb) g_bsum[tid] = sh[tid] - v;
}
__global__ void scanC_kernel(int n, int E) {
    int i = blockIdx.x * 1024 + threadIdx.x;
    if (i < n) {
        int r = g_rowptr[i] + g_bsum[blockIdx.x];
        g_rowptr[i] = r;
        g_cur[i] = r;
    }
    if (i == n) g_rowptr[n] = E;
}
__global__ void scatter_kernel(const int* __restrict__ src, const int* __restrict__ dst, int E) {
    int e = blockIdx.x * blockDim.x + threadIdx.x;
    if (e < E) {
        int d = dst[e];
        int p = atomicAdd(&g_cur[d], 1);
        g_ssrc[p] = src[e];
    }
}

// ============================================================
// Fold attention vectors (fp32, tiny)
// ============================================================
__global__ void attn_fold_kernel(const float* __restrict__ Ws0, const float* __restrict__ Ws1,
                                 const float* __restrict__ Ws2, const float* __restrict__ Ws3,
                                 const float* __restrict__ Wd0, const float* __restrict__ Wd1,
                                 const float* __restrict__ Wd2, const float* __restrict__ Wd3,
                                 const float* __restrict__ s0, const float* __restrict__ s1,
                                 const float* __restrict__ s2, const float* __restrict__ s3,
                                 const float* __restrict__ d0, const float* __restrict__ d1,
                                 const float* __restrict__ d2, const float* __restrict__ d3) {
    int w = blockIdx.x * (blockDim.x >> 5) + (threadIdx.x >> 5);
    int lane = threadIdx.x & 31;
    if (w >= 8192) return;
    int l = w >> 11;
    int rem = w & 2047;
    int c = rem >> 8;
    int k = rem & 255;
    int H = (l == 3) ? 1 : 4;
    int side = c >> 2;
    int h = c & 3;
    float val = 0.f;
    if (h < H) {
        const float* W;
        const float* a;
        if (side == 0) {
            W = (l == 0) ? Ws0 : (l == 1) ? Ws1 : (l == 2) ? Ws2 : Ws3;
            a = (l == 0) ? s0 : (l == 1) ? s1 : (l == 2) ? s2 : s3;
        } else {
            W = (l == 0) ? Wd0 : (l == 1) ? Wd1 : (l == 2) ? Wd2 : Wd3;
            a = (l == 0) ? d0 : (l == 1) ? d1 : (l == 2) ? d2 : d3;
        }
        int HC = H * 64;
        const float* wr = W + (size_t)k * HC + h * 64;
        const float* ar = a + h * 64;
        float sacc = wr[lane] * ar[lane] + wr[lane + 32] * ar[lane + 32];
        #pragma unroll
        for (int off = 16; off > 0; off >>= 1)
            sacc += __shfl_xor_sync(0xffffffffu, sacc, off);
        val = sacc;
    }
    if (lane == 0) g_attnAll[l * 2048 + c * 256 + k] = val;
}

// ============================================================
// Pack all Ws weights to fp16 k-pairs, k-major: out[kp*M + m].
// ============================================================
__global__ void presplit_W_kernel(const float* __restrict__ W0, const float* __restrict__ W1,
                                  const float* __restrict__ W2, const float* __restrict__ W3) {
    int t = blockIdx.x * blockDim.x + threadIdx.x;
    if (t >= 106496) return;
    const float* W;
    int M, kp, m, base;
    if (t < 98304) {
        int l = t >> 15;
        int within = t & 32767;
        M = 256; kp = within >> 8; m = within & 255;
        base = l << 15;
        W = (l == 0) ? W0 : (l == 1) ? W1 : W2;
    } else {
        int within = t - 98304;
        M = 64; kp = within >> 6; m = within & 63;
        base = 98304;
        W = W3;
    }
    float a = W[(size_t)(2 * kp) * M + m];
    float b = W[(size_t)(2 * kp + 1) * M + m];
    g_Wh[base + kp * M + m] = f2h2(a, b);
}

// ============================================================
// Pack x to fp16 + compute layer-1 attn logits (-> buf A).
// ============================================================
__global__ void presplit_x_attn_kernel(const float* __restrict__ x,
                                       const float* __restrict__ P, int n) {
    __shared__ float sP[2048];
    for (int i = threadIdx.x; i < 2048; i += blockDim.x) sP[i] = P[i];
    __syncthreads();
    int w = (blockIdx.x * blockDim.x + threadIdx.x) >> 5;
    int lane = threadIdx.x & 31;
    if (w >= n) return;
    float4 f0 = *reinterpret_cast<const float4*>(&x[(size_t)w * 256 + lane * 8]);
    float4 f1 = *reinterpret_cast<const float4*>(&x[(size_t)w * 256 + lane * 8 + 4]);
    float f[8] = {f0.x, f0.y, f0.z, f0.w, f1.x, f1.y, f1.z, f1.w};
    uint4 v;
    v.x = f2h2(f[0], f[1]);
    v.y = f2h2(f[2], f[3]);
    v.z = f2h2(f[4], f[5]);
    v.w = f2h2(f[6], f[7]);
    *reinterpret_cast<uint4*>(&g_b0[(size_t)w * 128 + lane * 4]) = v;
    float acc[8] = {};
    #pragma unroll
    for (int u = 0; u < 8; u++)
        #pragma unroll
        for (int c = 0; c < 8; c++)
            acc[c] += f[u] * sP[c * 256 + lane * 8 + u];
    #pragma unroll
    for (int c = 0; c < 8; c++) {
        float v2 = acc[c];
        #pragma unroll
        for (int off = 16; off > 0; off >>= 1)
            v2 += __shfl_xor_sync(0xffffffffu, v2, off);
        acc[c] = v2;
    }
    if (lane == 0) {
        for (int c = 0; c < 4; c++) g_alsA[w * 4 + c] = acc[c];
        for (int c = 0; c < 4; c++) g_aldA[w * 4 + c] = acc[4 + c];
    }
}

// ============================================================
// GEMM: fp16 A x fp16 W, fp16 output.  BM=128, BK=32, 256 threads.
// B col-block (128 kp x 64 cols) resident in smem for the whole CTA;
// A double-buffered.  2 CTAs/SM.
// ============================================================
#define ASTR 20
#define BSTR 72
#define OFF_A  0
#define OFF_B  (2 * 128 * ASTR)
#define SMEM_UINTS (OFF_B + 128 * BSTR)
#define SMEM_BYTES (SMEM_UINTS * 4)

__global__ __launch_bounds__(256, 2)
void gemm_kernel(const unsigned* __restrict__ A, const unsigned* __restrict__ B,
                 unsigned* __restrict__ C2, int N, int M) {
    extern __shared__ unsigned dynsmem[];
    unsigned* sA = dynsmem + OFF_A;    // [2][128][ASTR]
    unsigned* sB = dynsmem + OFF_B;    // [128][BSTR]

    const int tid = threadIdx.x;
    const int lane = tid & 31;
    const int wid = tid >> 5;
    const int rowBase = blockIdx.x * 128;
    const int warpM = wid & 3;
    const int warpN = wid >> 2;
    const int g  = lane >> 2;
    const int tg = lane & 3;
    const int colBase = blockIdx.y * 64;

    const int aRow = tid >> 1;
    const int aH8  = (tid & 1) << 3;
    const bool aOk = (rowBase + aRow) < N;
    const unsigned* Ag = A + (size_t)(rowBase + aRow) * 128 + aH8;

    // ---- load full B col-block: 128 kp x 64 uint32 = 2048 uint4 ----
    #pragma unroll
    for (int i = 0; i < 8; i++) {
        int idx = i * 256 + tid;          // 0..2047
        int kp = idx >> 4;
        int c4 = (idx & 15) << 2;
        uint4 v = *reinterpret_cast<const uint4*>(&B[(size_t)kp * M + colBase + c4]);
        *reinterpret_cast<uint4*>(&sB[kp * BSTR + c4]) = v;
    }

    float c[2][4][4] = {};

    uint4 ra0, ra1;
    const uint4 Z = make_uint4(0, 0, 0, 0);
    if (aOk) {
        ra0 = *reinterpret_cast<const uint4*>(Ag);
        ra1 = *reinterpret_cast<const uint4*>(Ag + 4);
    } else { ra0 = ra1 = Z; }

    const int aIdx = aRow * ASTR + aH8;
    *reinterpret_cast<uint4*>(&sA[aIdx])     = ra0;
    *reinterpret_cast<uint4*>(&sA[aIdx + 4]) = ra1;
    __syncthreads();

    for (int kt = 0; kt < 8; kt++) {
        const int curA = (kt & 1) * 128 * ASTR;
        if (kt + 1 < 8) {
            if (aOk) {
                ra0 = *reinterpret_cast<const uint4*>(Ag + (kt + 1) * 16);
                ra1 = *reinterpret_cast<const uint4*>(Ag + (kt + 1) * 16 + 4);
            }
        }

        #pragma unroll
        for (int k0 = 0; k0 < 2; k0++) {
            const int kpb = kt * 16 + k0 * 8;
            unsigned ah[2][4], bh[4][2];
            #pragma unroll
            for (int mt = 0; mt < 2; mt++) {
                int r = warpM * 32 + mt * 16 + g;
                const unsigned* pA = &sA[curA + r * ASTR + k0 * 8 + tg];
                ah[mt][0] = pA[0];   ah[mt][1] = pA[8 * ASTR];
                ah[mt][2] = pA[4];   ah[mt][3] = pA[8 * ASTR + 4];
            }
            #pragma unroll
            for (int nt = 0; nt < 4; nt++) {
                int col = warpN * 32 + nt * 8 + g;
                bh[nt][0] = sB[(kpb + tg) * BSTR + col];
                bh[nt][1] = sB[(kpb + tg + 4) * BSTR + col];
            }
            #pragma unroll
            for (int mt = 0; mt < 2; mt++)
                #pragma unroll
                for (int nt = 0; nt < 4; nt++)
                    mma16h(c[mt][nt], ah[mt], bh[nt]);
        }

        if (kt + 1 < 8) {
            const int nxtA = ((kt + 1) & 1) * 128 * ASTR;
            *reinterpret_cast<uint4*>(&sA[nxtA + aIdx])     = ra0;
            *reinterpret_cast<uint4*>(&sA[nxtA + aIdx + 4]) = ra1;
            __syncthreads();
        }
    }

    const int M2 = M >> 1;
    #pragma unroll
    for (int mt = 0; mt < 2; mt++) {
        int r0 = rowBase + warpM * 32 + mt * 16 + g;
        #pragma unroll
        for (int nt = 0; nt < 4; nt++) {
            int colH = (colBase + warpN * 32 + nt * 8) / 2 + tg;
            unsigned v0 = f2h2(c[mt][nt][0], c[mt][nt][1]);
            unsigned v1 = f2h2(c[mt][nt][2], c[mt][nt][3]);
            if (r0 < N)
                C2[(size_t)r0 * M2 + colH] = v0;
            if (r0 + 8 < N)
                C2[(size_t)(r0 + 8) * M2 + colH] = v1;
        }
    }
}

// ============================================================
// Aggregation: warp per dst node, no-max softmax, 4-edge unroll,
// fp16 hs gathers.  Reads logits from (alsIn, aldIn); MODE 1 writes
// fp16 features + next-layer logits to separate ping-pong buffers.
// ============================================================
template <int H, int MODE>
__global__ void agg_kernel(const unsigned* __restrict__ hs2, const float* __restrict__ bias,
                           float* __restrict__ out, unsigned* __restrict__ ofeat,
                           const float* __restrict__ Pnext,
                           const float* __restrict__ alsIn, const float* __restrict__ aldIn,
                           float* __restrict__ alsOut, float* __restrict__ aldOut,
                           int Hnext, int n, int doRelu) {
    const int HC = H * 64;
    const int R  = HC / 32;
    const int W2 = HC / 2;
    __shared__ float sP[2048];
    if (MODE == 1) {
        for (int i = threadIdx.x; i < 2048; i += blockDim.x) sP[i] = Pnext[i];
        __syncthreads();
    }
    int w = (blockIdx.x * blockDim.x + threadIdx.x) >> 5;
    int lane = threadIdx.x & 31;
    if (w >= n) return;
    int h = (lane * R) / 64;
    float ald_h = aldIn[w * H + h];

    float acc[R];
    #pragma unroll
    for (int r = 0; r < R; r++) acc[r] = 0.f;
    float den = 0.f;

    int beg = g_rowptr[w], end = g_rowptr[w + 1];
    int e = beg;
    for (; e + 3 < end; e += 4) {
        int s0 = g_ssrc[e];
        int s1 = g_ssrc[e + 1];
        int s2 = g_ssrc[e + 2];
        int s3 = g_ssrc[e + 3];
        float a0 = alsIn[s0 * H + h];
        float a1 = alsIn[s1 * H + h];
        float a2 = alsIn[s2 * H + h];
        float a3 = alsIn[s3 * H + h];
        float ev0 = a0 + ald_h; ev0 = ev0 > 0.f ? ev0 : 0.2f * ev0;
        float ev1 = a1 + ald_h; ev1 = ev1 > 0.f ? ev1 : 0.2f * ev1;
        float ev2 = a2 + ald_h; ev2 = ev2 > 0.f ? ev2 : 0.2f * ev2;
        float ev3 = a3 + ald_h; ev3 = ev3 > 0.f ? ev3 : 0.2f * ev3;
        float w0 = __expf(ev0), w1 = __expf(ev1), w2 = __expf(ev2), w3 = __expf(ev3);
        den += (w0 + w1) + (w2 + w3);
        if (R == 8) {
            uint4 q0 = *reinterpret_cast<const uint4*>(&hs2[(size_t)s0 * W2 + lane * 4]);
            uint4 q1 = *reinterpret_cast<const uint4*>(&hs2[(size_t)s1 * W2 + lane * 4]);
            uint4 q2 = *reinterpret_cast<const uint4*>(&hs2[(size_t)s2 * W2 + lane * 4]);
            uint4 q3 = *reinterpret_cast<const uint4*>(&hs2[(size_t)s3 * W2 + lane * 4]);
            float2 t;
            t = h2f(q0.x); acc[0] += w0 * t.x; acc[1] += w0 * t.y;
            t = h2f(q0.y); acc[2] += w0 * t.x; acc[3] += w0 * t.y;
            t = h2f(q0.z); acc[4] += w0 * t.x; acc[5] += w0 * t.y;
            t = h2f(q0.w); acc[6] += w0 * t.x; acc[7] += w0 * t.y;
            t = h2f(q1.x); acc[0] += w1 * t.x; acc[1] += w1 * t.y;
            t = h2f(q1.y); acc[2] += w1 * t.x; acc[3] += w1 * t.y;
            t = h2f(q1.z); acc[4] += w1 * t.x; acc[5] += w1 * t.y;
            t = h2f(q1.w); acc[6] += w1 * t.x; acc[7] += w1 * t.y;
            t = h2f(q2.x); acc[0] += w2 * t.x; acc[1] += w2 * t.y;
            t = h2f(q2.y); acc[2] += w2 * t.x; acc[3] += w2 * t.y;
            t = h2f(q2.z); acc[4] += w2 * t.x; acc[5] += w2 * t.y;
            t = h2f(q2.w); acc[6] += w2 * t.x; acc[7] += w2 * t.y;
            t = h2f(q3.x); acc[0] += w3 * t.x; acc[1] += w3 * t.y;
            t = h2f(q3.y); acc[2] += w3 * t.x; acc[3] += w3 * t.y;
            t = h2f(q3.z); acc[4] += w3 * t.x; acc[5] += w3 * t.y;
            t = h2f(q3.w); acc[6] += w3 * t.x; acc[7] += w3 * t.y;
        } else {
            float2 t;
            t = h2f(hs2[(size_t)s0 * W2 + lane]); acc[0] += w0 * t.x; acc[1] += w0 * t.y;
            t = h2f(hs2[(size_t)s1 * W2 + lane]); acc[0] += w1 * t.x; acc[1] += w1 * t.y;
            t = h2f(hs2[(size_t)s2 * W2 + lane]); acc[0] += w2 * t.x; acc[1] += w2 * t.y;
            t = h2f(hs2[(size_t)s3 * W2 + lane]); acc[0] += w3 * t.x; acc[1] += w3 * t.y;
        }
    }
    for (; e < end; e++) {
        int s = g_ssrc[e];
        float ev = alsIn[s * H + h] + ald_h;
        ev = ev > 0.f ? ev : 0.2f * ev;
        float wg = __expf(ev);
        den += wg;
        if (R == 8) {
            uint4 q = *reinterpret_cast<const uint4*>(&hs2[(size_t)s * W2 + lane * 4]);
            float2 t;
            t = h2f(q.x); acc[0] += wg * t.x; acc[1] += wg * t.y;
            t = h2f(q.y); acc[2] += wg * t.x; acc[3] += wg * t.y;
            t = h2f(q.z); acc[4] += wg * t.x; acc[5] += wg * t.y;
            t = h2f(q.w); acc[6] += wg * t.x; acc[7] += wg * t.y;
        } else {
            float2 t = h2f(hs2[(size_t)s * W2 + lane]);
            acc[0] += wg * t.x; acc[1] += wg * t.y;
        }
    }
    float invd = (end > beg) ? 1.f / den : 0.f;
    float o[R];
    #pragma unroll
    for (int r = 0; r < R; r++) {
        float v = acc[r] * invd + bias[lane * R + r];
        if (doRelu) v = fmaxf(v, 0.f);
        o[r] = v;
    }
    if (MODE == 1) {
        uint4 v;
        v.x = f2h2(o[0], o[1]);
        v.y = f2h2(o[2], o[3]);
        v.z = f2h2(o[4], o[5]);
        v.w = f2h2(o[6], o[7]);
        *reinterpret_cast<uint4*>(&ofeat[(size_t)w * 128 + lane * 4]) = v;
        float at[8] = {};
        #pragma unroll
        for (int u = 0; u < 8; u++)
            #pragma unroll
            for (int c = 0; c < 8; c++)
                at[c] += o[u] * sP[c * 256 + lane * 8 + u];
        #pragma unroll
        for (int c = 0; c < 8; c++) {
            float vv = at[c];
            #pragma unroll
            for (int off = 16; off > 0; off >>= 1)
                vv += __shfl_xor_sync(0xffffffffu, vv, off);
            at[c] = vv;
        }
        if (lane == 0) {
            for (int c = 0; c < Hnext; c++) alsOut[w * Hnext + c] = at[c];
            for (int c = 0; c < Hnext; c++) aldOut[w * Hnext + c] = at[4 + c];
        }
    } else {
        #pragma unroll
        for (int r = 0; r < R; r++)
            out[(size_t)w * HC + lane * R + r] = o[r];
    }
}

// ============================================================
// Launch
// ============================================================
extern "C" void kernel_launch(void* const* d_in, const int* in_sizes, int n_in,
                              void* d_out, int out_size) {
    const float* x  = (const float*)d_in[0];
    const int*   ei = (const int*)d_in[1];
    int n = in_sizes[0] / 256;
    int E = in_sizes[1] / 2;
    const int* src = ei;
    const int* dst = ei + E;

    const float *Ws[4], *Wd[4], *as_[4], *ad_[4], *bb[4];
    for (int l = 0; l < 4; l++) {
        Ws[l]  = (const float*)d_in[2 + 5 * l + 0];
        Wd[l]  = (const float*)d_in[2 + 5 * l + 1];
        as_[l] = (const float*)d_in[2 + 5 * l + 2];
        ad_[l] = (const float*)d_in[2 + 5 * l + 3];
        bb[l]  = (const float*)d_in[2 + 5 * l + 4];
    }

    void *p_hs2, *p_cnt, *p_at, *p_wh;
    void *p_b0, *p_b1;
    void *p_alsA, *p_aldA, *p_alsB, *p_aldB;
    cudaGetSymbolAddress(&p_hs2, g_hs2);
    cudaGetSymbolAddress(&p_cnt, g_cnt);
    cudaGetSymbolAddress(&p_at, g_attnAll);
    cudaGetSymbolAddress(&p_wh, g_Wh);
    cudaGetSymbolAddress(&p_b0, g_b0);
    cudaGetSymbolAddress(&p_b1, g_b1);
    cudaGetSymbolAddress(&p_alsA, g_alsA);
    cudaGetSymbolAddress(&p_aldA, g_aldA);
    cudaGetSymbolAddress(&p_alsB, g_alsB);
    cudaGetSymbolAddress(&p_aldB, g_aldB);
    unsigned* hs2 = (unsigned*)p_hs2;
    const float* at = (const float*)p_at;
    unsigned* wh = (unsigned*)p_wh;
    unsigned* buf[2] = {(unsigned*)p_b0, (unsigned*)p_b1};
    float* als[2] = {(float*)p_alsA, (float*)p_alsB};
    float* ald[2] = {(float*)p_aldA, (float*)p_aldB};

    cudaFuncSetAttribute(gemm_kernel,
                         cudaFuncAttributeMaxDynamicSharedMemorySize, SMEM_BYTES);

    // ---- sort edges by dst ----
    int nb = (n + 1023) / 1024;
    cudaMemsetAsync(p_cnt, 0, (size_t)(n + 1) * sizeof(int));
    hist_kernel<<<(E + 255) / 256, 256>>>(dst, E);
    scanA_kernel<<<nb, 1024>>>(n);
    scanB_kernel<<<1, 64>>>(nb);
    scanC_kernel<<<nb, 1024>>>(n, E);
    scatter_kernel<<<(E + 255) / 256, 256>>>(src, dst, E);

    // ---- one-shot folds / packs (+ layer-1 attn logits -> buf A) ----
    attn_fold_kernel<<<1024, 256>>>(Ws[0], Ws[1], Ws[2], Ws[3],
                                    Wd[0], Wd[1], Wd[2], Wd[3],
                                    as_[0], as_[1], as_[2], as_[3],
                                    ad_[0], ad_[1], ad_[2], ad_[3]);
    presplit_W_kernel<<<(106496 + 255) / 256, 256>>>(Ws[0], Ws[1], Ws[2], Ws[3]);

    int warpBlocks = (n * 32 + 255) / 256;
    presplit_x_attn_kernel<<<warpBlocks, 256>>>(x, at, n);

    int gx = (n + 127) / 128;
    dim3 gGrid(gx, 4);     // M=256
    dim3 gGrid4(gx, 1);    // M=64

    // layer l: features/logits in buf (l&1), out buf ((l+1)&1)
    for (int l = 0; l < 3; l++) {
        int ia = l & 1, io = (l + 1) & 1;
        gemm_kernel<<<gGrid, 256, SMEM_BYTES>>>(buf[ia], wh + l * 32768, hs2, n, 256);
        agg_kernel<4, 1><<<warpBlocks, 256>>>(hs2, bb[l], nullptr, buf[io],
                                              at + (l + 1) * 2048,
                                              als[ia], ald[ia], als[io], ald[io],
                                              (l == 2) ? 1 : 4, n, 1);
    }
    gemm_kernel<<<gGrid4, 256, SMEM_BYTES>>>(buf[1], wh + 98304, hs2, n, 64);
    agg_kernel<1, 0><<<warpBlocks, 256>>>(hs2, bb[3], (float*)d_out, nullptr,
                                          nullptr, als[1], ald[1], nullptr, nullptr,
                                          0, n, 0);
}